// round 1
// baseline (speedup 1.0000x reference)
#include <cuda_runtime.h>
#include <math.h>

#define B_SZ  8
#define S_LEN 1024
#define NH    16
#define NKV   4
#define HD    128
#define DIM   2048
#define MTOT  (B_SZ * S_LEN)   // 8192

// ---- scratch (static device memory: allocation-free) ----
__device__ float g_q[(size_t)MTOT * DIM];          // [B,S,NH,HD]
__device__ float g_k[(size_t)MTOT * NKV * HD];     // [B,S,NKV,HD]
__device__ float g_v[(size_t)MTOT * NKV * HD];     // [B,S,NKV,HD]
__device__ float g_o[(size_t)MTOT * DIM];          // [B,S,NH,HD]

// =====================================================================
// GEMM: C[M,N] = A[M,K] @ W[N,K]^T   (fp32, f32x2 packed inner loop)
// BM=128, BN=128, BK=32, 256 threads, 8x8 micro-tile (as 8x4 f32x2)
// M,N multiples of 128; K multiple of 32 (true for all our shapes)
// =====================================================================
__global__ __launch_bounds__(256, 2) void sgemm_tn(const float* __restrict__ A,
                                                   const float* __restrict__ W,
                                                   float* __restrict__ C,
                                                   int N, int K) {
    __shared__ float As[32 * 132];   // stored [k][m]
    __shared__ float Bs[32 * 132];   // stored [k][n]

    const int bm  = blockIdx.y * 128;
    const int bn  = blockIdx.x * 128;
    const int tid = threadIdx.x;
    const int ty  = tid >> 4;        // 0..15
    const int tx  = tid & 15;        // 0..15

    unsigned long long acc[8][4];
#pragma unroll
    for (int i = 0; i < 8; i++)
#pragma unroll
        for (int j = 0; j < 4; j++) acc[i][j] = 0ULL;

    for (int k0 = 0; k0 < K; k0 += 32) {
        // load tiles: 128 rows x 32 k each, 1024 float4 per matrix, 4 per thread
#pragma unroll
        for (int t = 0; t < 4; t++) {
            int idx = tid + t * 256;
            int row = idx >> 3;      // 0..127
            int kv  = idx & 7;       // 0..7 (float4 within the 32-wide k slab)
            float4 a = *(const float4*)&A[(size_t)(bm + row) * K + k0 + kv * 4];
            As[(kv * 4 + 0) * 132 + row] = a.x;
            As[(kv * 4 + 1) * 132 + row] = a.y;
            As[(kv * 4 + 2) * 132 + row] = a.z;
            As[(kv * 4 + 3) * 132 + row] = a.w;
            float4 b = *(const float4*)&W[(size_t)(bn + row) * K + k0 + kv * 4];
            Bs[(kv * 4 + 0) * 132 + row] = b.x;
            Bs[(kv * 4 + 1) * 132 + row] = b.y;
            Bs[(kv * 4 + 2) * 132 + row] = b.z;
            Bs[(kv * 4 + 3) * 132 + row] = b.w;
        }
        __syncthreads();

#pragma unroll
        for (int kk = 0; kk < 32; kk++) {
            float4 a0 = *(const float4*)&As[kk * 132 + ty * 8];
            float4 a1 = *(const float4*)&As[kk * 132 + ty * 8 + 4];
            ulonglong2 b0 = *(const ulonglong2*)&Bs[kk * 132 + tx * 8];
            ulonglong2 b1 = *(const ulonglong2*)&Bs[kk * 132 + tx * 8 + 4];
            unsigned long long bb[4] = {b0.x, b0.y, b1.x, b1.y};
            float av[8] = {a0.x, a0.y, a0.z, a0.w, a1.x, a1.y, a1.z, a1.w};
#pragma unroll
            for (int i = 0; i < 8; i++) {
                unsigned long long a2;
                asm("mov.b64 %0, {%1, %1};" : "=l"(a2) : "f"(av[i]));
#pragma unroll
                for (int j = 0; j < 4; j++) {
                    asm("fma.rn.f32x2 %0, %1, %2, %0;"
                        : "+l"(acc[i][j]) : "l"(a2), "l"(bb[j]));
                }
            }
        }
        __syncthreads();
    }

#pragma unroll
    for (int i = 0; i < 8; i++) {
#pragma unroll
        for (int j = 0; j < 4; j++) {
            float lo, hi;
            asm("mov.b64 {%0, %1}, %2;" : "=f"(lo), "=f"(hi) : "l"(acc[i][j]));
            float2 v = make_float2(lo, hi);
            *(float2*)&C[(size_t)(bm + ty * 8 + i) * N + bn + tx * 8 + j * 2] = v;
        }
    }
}

// =====================================================================
// RoPE (in place). t: [B,S,nheads,HD], pairs (even,odd) in last dim.
// =====================================================================
__global__ void rope_kernel(float* __restrict__ t,
                            const float* __restrict__ cosT,
                            const float* __restrict__ sinT,
                            int nheads, int total_pairs) {
    int idx = blockIdx.x * 256 + threadIdx.x;
    if (idx >= total_pairs) return;
    int j   = idx & 63;                  // freq index (HD/2 = 64)
    int grp = idx >> 6;                  // (b*S + s)*nheads + h
    int s   = (grp / nheads) % S_LEN;
    float c  = cosT[s * 64 + j];
    float sn = sinT[s * 64 + j];
    float2 v = *(float2*)&t[(size_t)idx * 2];
    float2 o;
    o.x = v.x * c - v.y * sn;
    o.y = v.x * sn + v.y * c;
    *(float2*)&t[(size_t)idx * 2] = o;
}

// =====================================================================
// Flash attention (causal, GQA). BM=BN=64, D=128, 256 threads.
// grid = (S/64, NH, B). smem: Qs[64][132] Kts[128][68] Vs[64][132]
//                             Ps[64][68] m/l/alpha[64]  = 120,576 B
// =====================================================================
#define FLASH_SMEM_FLOATS (64*132 + 128*68 + 64*132 + 64*68 + 64*3)
#define FLASH_SMEM_BYTES  (FLASH_SMEM_FLOATS * 4)

__global__ __launch_bounds__(256) void flash_kernel(const float* __restrict__ Q,
                                                    const float* __restrict__ K,
                                                    const float* __restrict__ V,
                                                    float* __restrict__ O) {
    const int qt = blockIdx.x;     // q tile (0..15)
    const int h  = blockIdx.y;     // head
    const int b  = blockIdx.z;     // batch
    const int g  = h >> 2;         // kv head (N_REP = 4)

    extern __shared__ float sm[];
    float* Qs   = sm;                    // [64][132]
    float* Kts  = Qs  + 64 * 132;        // [128][68] (transposed K tile)
    float* Vs   = Kts + 128 * 68;        // [64][132]
    float* Ps   = Vs  + 64 * 132;        // [64][68]
    float* mrow = Ps  + 64 * 68;         // [64]
    float* lrow = mrow + 64;             // [64]
    float* arow = lrow + 64;             // [64]

    const int tid = threadIdx.x;
    const int ty  = tid >> 4;            // 0..15
    const int tx  = tid & 15;            // 0..15
    const float scale = 0.08838834764831845f;  // 1/sqrt(128)

    // ---- load Q tile (pre-scaled) ----
#pragma unroll
    for (int t = 0; t < 8; t++) {
        int idx = tid + t * 256;         // float4 index over 64*32
        int row = idx >> 5;
        int dv  = idx & 31;
        float4 v = *(const float4*)&Q[(((size_t)(b * S_LEN + qt * 64 + row)) * NH + h) * HD + dv * 4];
        v.x *= scale; v.y *= scale; v.z *= scale; v.w *= scale;
        *(float4*)&Qs[row * 132 + dv * 4] = v;
    }
    if (tid < 64) { mrow[tid] = -INFINITY; lrow[tid] = 0.0f; }

    float oacc[4][8];
#pragma unroll
    for (int i = 0; i < 4; i++)
#pragma unroll
        for (int j = 0; j < 8; j++) oacc[i][j] = 0.0f;

    for (int jt = 0; jt <= qt; jt++) {
        __syncthreads();   // previous PV / softmax done before overwriting tiles
        // ---- load K (transposed) and V tiles ----
#pragma unroll
        for (int t = 0; t < 8; t++) {
            int idx = tid + t * 256;
            int row = idx >> 5;
            int dv  = idx & 31;
            size_t base = (((size_t)(b * S_LEN + jt * 64 + row)) * NKV + g) * HD + dv * 4;
            float4 kv = *(const float4*)&K[base];
            Kts[(dv * 4 + 0) * 68 + row] = kv.x;
            Kts[(dv * 4 + 1) * 68 + row] = kv.y;
            Kts[(dv * 4 + 2) * 68 + row] = kv.z;
            Kts[(dv * 4 + 3) * 68 + row] = kv.w;
            float4 vv = *(const float4*)&V[base];
            *(float4*)&Vs[row * 132 + dv * 4] = vv;
        }
        __syncthreads();

        // ---- S = Q K^T (64x64, kdim=128) ----
        float sacc[4][4];
#pragma unroll
        for (int i = 0; i < 4; i++)
#pragma unroll
            for (int j = 0; j < 4; j++) sacc[i][j] = 0.0f;

#pragma unroll 8
        for (int kk = 0; kk < HD; kk++) {
            float a0 = Qs[(ty * 4 + 0) * 132 + kk];
            float a1 = Qs[(ty * 4 + 1) * 132 + kk];
            float a2 = Qs[(ty * 4 + 2) * 132 + kk];
            float a3 = Qs[(ty * 4 + 3) * 132 + kk];
            float4 bv = *(const float4*)&Kts[kk * 68 + tx * 4];
            sacc[0][0] += a0 * bv.x; sacc[0][1] += a0 * bv.y; sacc[0][2] += a0 * bv.z; sacc[0][3] += a0 * bv.w;
            sacc[1][0] += a1 * bv.x; sacc[1][1] += a1 * bv.y; sacc[1][2] += a1 * bv.z; sacc[1][3] += a1 * bv.w;
            sacc[2][0] += a2 * bv.x; sacc[2][1] += a2 * bv.y; sacc[2][2] += a2 * bv.z; sacc[2][3] += a2 * bv.w;
            sacc[3][0] += a3 * bv.x; sacc[3][1] += a3 * bv.y; sacc[3][2] += a3 * bv.z; sacc[3][3] += a3 * bv.w;
        }

        // causal mask (diagonal tile only; tiles with jt<qt are fully valid)
        if (jt == qt) {
#pragma unroll
            for (int i = 0; i < 4; i++)
#pragma unroll
                for (int j = 0; j < 4; j++)
                    if (tx * 4 + j > ty * 4 + i) sacc[i][j] = -1e30f;
        }
#pragma unroll
        for (int i = 0; i < 4; i++) {
            float4 pv = make_float4(sacc[i][0], sacc[i][1], sacc[i][2], sacc[i][3]);
            *(float4*)&Ps[(ty * 4 + i) * 68 + tx * 4] = pv;
        }
        __syncthreads();

        // ---- online softmax (one thread per row) ----
        if (tid < 64) {
            const int r = tid;
            float mold = mrow[r];
            float mx = mold;
#pragma unroll 8
            for (int c = 0; c < 64; c++) mx = fmaxf(mx, Ps[r * 68 + c]);
            float al = __expf(mold - mx);
            float sum = 0.0f;
#pragma unroll 8
            for (int c = 0; c < 64; c++) {
                float p = __expf(Ps[r * 68 + c] - mx);
                Ps[r * 68 + c] = p;
                sum += p;
            }
            mrow[r] = mx;
            lrow[r] = lrow[r] * al + sum;
            arow[r] = al;
        }
        __syncthreads();

        // ---- O = O*alpha + P V (64x128, kdim=64) ----
        float al0 = arow[ty * 4 + 0];
        float al1 = arow[ty * 4 + 1];
        float al2 = arow[ty * 4 + 2];
        float al3 = arow[ty * 4 + 3];
#pragma unroll
        for (int j = 0; j < 8; j++) {
            oacc[0][j] *= al0; oacc[1][j] *= al1; oacc[2][j] *= al2; oacc[3][j] *= al3;
        }
#pragma unroll 4
        for (int kk = 0; kk < 64; kk++) {
            float p0 = Ps[(ty * 4 + 0) * 68 + kk];
            float p1 = Ps[(ty * 4 + 1) * 68 + kk];
            float p2 = Ps[(ty * 4 + 2) * 68 + kk];
            float p3 = Ps[(ty * 4 + 3) * 68 + kk];
            float4 v0 = *(const float4*)&Vs[kk * 132 + tx * 8];
            float4 v1 = *(const float4*)&Vs[kk * 132 + tx * 8 + 4];
            float vv[8] = {v0.x, v0.y, v0.z, v0.w, v1.x, v1.y, v1.z, v1.w};
#pragma unroll
            for (int j = 0; j < 8; j++) {
                oacc[0][j] += p0 * vv[j];
                oacc[1][j] += p1 * vv[j];
                oacc[2][j] += p2 * vv[j];
                oacc[3][j] += p3 * vv[j];
            }
        }
    }

    // ---- normalize + write ----
    float li0 = 1.0f / lrow[ty * 4 + 0];
    float li1 = 1.0f / lrow[ty * 4 + 1];
    float li2 = 1.0f / lrow[ty * 4 + 2];
    float li3 = 1.0f / lrow[ty * 4 + 3];
    float li[4] = {li0, li1, li2, li3};
#pragma unroll
    for (int i = 0; i < 4; i++) {
        size_t base = (((size_t)(b * S_LEN + qt * 64 + ty * 4 + i)) * NH + h) * HD + tx * 8;
#pragma unroll
        for (int j = 0; j < 8; j++)
            O[base + j] = oacc[i][j] * li[i];
    }
}

// =====================================================================
// launch
// =====================================================================
extern "C" void kernel_launch(void* const* d_in, const int* in_sizes, int n_in,
                              void* d_out, int out_size) {
    (void)in_sizes; (void)n_in; (void)out_size;
    const float* x    = (const float*)d_in[0];
    const float* cosT = (const float*)d_in[1];
    const float* sinT = (const float*)d_in[2];
    const float* wq   = (const float*)d_in[3];
    const float* wk   = (const float*)d_in[4];
    const float* wv   = (const float*)d_in[5];
    const float* wo   = (const float*)d_in[6];
    float* out = (float*)d_out;

    float *pq, *pk, *pv, *po;
    cudaGetSymbolAddress((void**)&pq, g_q);
    cudaGetSymbolAddress((void**)&pk, g_k);
    cudaGetSymbolAddress((void**)&pv, g_v);
    cudaGetSymbolAddress((void**)&po, g_o);

    cudaFuncSetAttribute(flash_kernel, cudaFuncAttributeMaxDynamicSharedMemorySize,
                         FLASH_SMEM_BYTES);

    // Q/K/V projections
    sgemm_tn<<<dim3(DIM / 128, MTOT / 128), 256>>>(x, wq, pq, DIM, DIM);
    sgemm_tn<<<dim3((NKV * HD) / 128, MTOT / 128), 256>>>(x, wk, pk, NKV * HD, DIM);
    sgemm_tn<<<dim3((NKV * HD) / 128, MTOT / 128), 256>>>(x, wv, pv, NKV * HD, DIM);

    // RoPE (Q: 16 heads, K: 4 heads)
    {
        int qp = MTOT * NH * (HD / 2);
        rope_kernel<<<(qp + 255) / 256, 256>>>(pq, cosT, sinT, NH, qp);
        int kp = MTOT * NKV * (HD / 2);
        rope_kernel<<<(kp + 255) / 256, 256>>>(pk, cosT, sinT, NKV, kp);
    }

    // attention
    flash_kernel<<<dim3(S_LEN / 64, NH, B_SZ), 256, FLASH_SMEM_BYTES>>>(pq, pk, pv, po);

    // output projection
    sgemm_tn<<<dim3(DIM / 128, MTOT / 128), 256>>>(po, wo, out, DIM, DIM);
}

// round 3
// speedup vs baseline: 1.8475x; 1.8475x over previous
#include <cuda_runtime.h>
#include <cuda_bf16.h>
#include <math.h>
#include <stdint.h>

#define B_SZ  8
#define S_LEN 1024
#define NH    16
#define NKV   4
#define HD    128
#define DIM   2048
#define MTOT  (B_SZ * S_LEN)   // 8192
#define KVD   (NKV * HD)       // 512

// ---------------- static scratch (allocation-free) ----------------
__device__ float g_q[(size_t)MTOT * DIM];
__device__ float g_k[(size_t)MTOT * KVD];
__device__ float g_v[(size_t)MTOT * KVD];
__device__ float g_o[(size_t)MTOT * DIM];

__device__ __nv_bfloat16 g_xh[(size_t)MTOT * DIM], g_xl[(size_t)MTOT * DIM];
__device__ __nv_bfloat16 g_oh[(size_t)MTOT * DIM], g_ol[(size_t)MTOT * DIM];
__device__ __nv_bfloat16 g_wqh[(size_t)DIM * DIM], g_wql[(size_t)DIM * DIM];
__device__ __nv_bfloat16 g_wkh[(size_t)KVD * DIM], g_wkl[(size_t)KVD * DIM];
__device__ __nv_bfloat16 g_wvh[(size_t)KVD * DIM], g_wvl[(size_t)KVD * DIM];
__device__ __nv_bfloat16 g_woh[(size_t)DIM * DIM], g_wol[(size_t)DIM * DIM];

// ---------------- helpers ----------------
__device__ __forceinline__ uint32_t smem_u32(const void* p) {
    uint32_t a;
    asm("{ .reg .u64 t; cvta.to.shared.u64 t, %1; cvt.u32.u64 %0, t; }" : "=r"(a) : "l"(p));
    return a;
}

__device__ __forceinline__ void ldsm_x4(uint32_t* r, uint32_t addr) {
    asm volatile("ldmatrix.sync.aligned.m8n8.x4.shared.b16 {%0,%1,%2,%3}, [%4];"
        : "=r"(r[0]), "=r"(r[1]), "=r"(r[2]), "=r"(r[3]) : "r"(addr));
}

__device__ __forceinline__ void mma16816(float* d, const uint32_t* a, const uint32_t* b) {
    asm volatile("mma.sync.aligned.m16n8k16.row.col.f32.bf16.bf16.f32 "
        "{%0,%1,%2,%3}, {%4,%5,%6,%7}, {%8,%9}, {%0,%1,%2,%3};"
        : "+f"(d[0]), "+f"(d[1]), "+f"(d[2]), "+f"(d[3])
        : "r"(a[0]), "r"(a[1]), "r"(a[2]), "r"(a[3]), "r"(b[0]), "r"(b[1]));
}

// f32x2 packed helpers
__device__ __forceinline__ unsigned long long pack2(float x) {
    unsigned long long r; asm("mov.b64 %0, {%1, %1};" : "=l"(r) : "f"(x)); return r;
}
__device__ __forceinline__ void fma2(unsigned long long& d, unsigned long long a, unsigned long long b) {
    asm("fma.rn.f32x2 %0, %1, %2, %0;" : "+l"(d) : "l"(a), "l"(b));
}
__device__ __forceinline__ void mul2(unsigned long long& d, unsigned long long a) {
    asm("mul.rn.f32x2 %0, %0, %1;" : "+l"(d) : "l"(a));
}
__device__ __forceinline__ float2 unpack2(unsigned long long v) {
    float2 r; asm("mov.b64 {%0, %1}, %2;" : "=f"(r.x), "=f"(r.y) : "l"(v)); return r;
}

// =====================================================================
// split fp32 -> bf16 hi + bf16 lo
// =====================================================================
__global__ void split_kernel(const float* __restrict__ in,
                             __nv_bfloat16* __restrict__ hi,
                             __nv_bfloat16* __restrict__ lo, int n4) {
    int i = blockIdx.x * 256 + threadIdx.x;
    if (i >= n4) return;
    float4 v = ((const float4*)in)[i];
    __nv_bfloat16 h0 = __float2bfloat16(v.x);
    __nv_bfloat16 h1 = __float2bfloat16(v.y);
    __nv_bfloat16 h2 = __float2bfloat16(v.z);
    __nv_bfloat16 h3 = __float2bfloat16(v.w);
    __nv_bfloat16 l0 = __float2bfloat16(v.x - __bfloat162float(h0));
    __nv_bfloat16 l1 = __float2bfloat16(v.y - __bfloat162float(h1));
    __nv_bfloat16 l2 = __float2bfloat16(v.z - __bfloat162float(h2));
    __nv_bfloat16 l3 = __float2bfloat16(v.w - __bfloat162float(h3));
    __nv_bfloat162* hp = (__nv_bfloat162*)hi;
    __nv_bfloat162* lp = (__nv_bfloat162*)lo;
    hp[i * 2 + 0] = __nv_bfloat162(h0, h1);
    hp[i * 2 + 1] = __nv_bfloat162(h2, h3);
    lp[i * 2 + 0] = __nv_bfloat162(l0, l1);
    lp[i * 2 + 1] = __nv_bfloat162(l2, l3);
}

// =====================================================================
// GEMM via mma.sync bf16 (3-way split): C[M,N] = (Ah+Al) @ (Bh+Bl)^T
// tile 128x128, BK=32, 256 threads (8 warps, warp tile 32x64).
// smem tiles stride 40 bf16 (80B) -> conflict-free ldmatrix.
// smem: 2 stages x 4 tiles x 128*40*2B = 81920 B
// =====================================================================
#define TILE_B   10240          // one 128x40 bf16 tile
#define STAGE_B  (4 * TILE_B)   // Ah,Al,Bh,Bl
#define GEMM_SMEM_BYTES (2 * STAGE_B)

__device__ __forceinline__ void gemm_load_chunk(
    const __nv_bfloat16* __restrict__ Ah, const __nv_bfloat16* __restrict__ Al,
    const __nv_bfloat16* __restrict__ Bh, const __nv_bfloat16* __restrict__ Bl,
    int bm, int bn, int K, int kc, uint32_t stbase, int tid) {
#pragma unroll
    for (int t = 0; t < 8; t++) {
        const int tile = t >> 1;                  // compile-time
        const int rem  = tid + (t & 1) * 256;     // 0..511
        const int row  = rem >> 2;
        const int c    = rem & 3;
        const __nv_bfloat16* base = (tile == 0) ? Ah : (tile == 1) ? Al : (tile == 2) ? Bh : Bl;
        const int grow = ((tile < 2) ? bm : bn) + row;
        const void* g = base + (size_t)grow * K + kc * 32 + c * 8;
        uint32_t dst = stbase + (uint32_t)tile * TILE_B + (uint32_t)(row * 80 + c * 16);
        asm volatile("cp.async.cg.shared.global [%0], [%1], 16;" :: "r"(dst), "l"(g) : "memory");
    }
    asm volatile("cp.async.commit_group;" ::: "memory");
}

__global__ __launch_bounds__(256, 2)
void gemm_bf16x3(const __nv_bfloat16* __restrict__ Ah, const __nv_bfloat16* __restrict__ Al,
                 const __nv_bfloat16* __restrict__ Bh, const __nv_bfloat16* __restrict__ Bl,
                 float* __restrict__ C, int N, int K) {
    extern __shared__ char smem_raw[];
    const uint32_t sbase = smem_u32(smem_raw);

    const int tid  = threadIdx.x;
    const int wid  = tid >> 5;
    const int lane = tid & 31;
    const int warp_m = wid & 3;        // 4 warps along M (32 rows each)
    const int warp_n = wid >> 2;       // 2 warps along N (64 cols each)
    const int bm = blockIdx.y * 128;
    const int bn = blockIdx.x * 128;

    float acc[2][8][4];
#pragma unroll
    for (int i = 0; i < 2; i++)
#pragma unroll
        for (int j = 0; j < 8; j++)
#pragma unroll
            for (int v = 0; v < 4; v++) acc[i][j][v] = 0.0f;

    // ldmatrix address components (within a tile)
    const uint32_t a_row = (uint32_t)(warp_m * 32 + (lane & 15));
    const uint32_t a_off = a_row * 80u + (uint32_t)((lane >> 4) * 16);
    const uint32_t b_row = (uint32_t)(warp_n * 64 + (lane & 7) + ((lane >> 4) & 1) * 8);
    const uint32_t b_off = b_row * 80u + (uint32_t)(((lane >> 3) & 1) * 16);

    const int NCHUNK = K >> 5;   // BK = 32

    gemm_load_chunk(Ah, Al, Bh, Bl, bm, bn, K, 0, sbase, tid);

    for (int c = 0; c < NCHUNK; c++) {
        const uint32_t stage = (uint32_t)(c & 1) * STAGE_B;
        if (c + 1 < NCHUNK) {
            gemm_load_chunk(Ah, Al, Bh, Bl, bm, bn, K, c + 1,
                            sbase + (uint32_t)((c + 1) & 1) * STAGE_B, tid);
            asm volatile("cp.async.wait_group 1;" ::: "memory");
        } else {
            asm volatile("cp.async.wait_group 0;" ::: "memory");
        }
        __syncthreads();

#pragma unroll
        for (int ks = 0; ks < 2; ks++) {
#pragma unroll
            for (int pass = 0; pass < 3; pass++) {
                const int at = (pass == 2) ? 1 : 0;      // Ah, Ah, Al
                const int bt = (pass == 1) ? 3 : 2;      // Bh, Bl, Bh
                const uint32_t abase = sbase + stage + (uint32_t)at * TILE_B + a_off + ks * 32;
                const uint32_t bbase = sbase + stage + (uint32_t)bt * TILE_B + b_off + ks * 32;
                uint32_t afrag[2][4];
                ldsm_x4(afrag[0], abase);
                ldsm_x4(afrag[1], abase + 16u * 80u);
                uint32_t bfrag[4][4];
#pragma unroll
                for (int nb = 0; nb < 4; nb++)
                    ldsm_x4(bfrag[nb], bbase + (uint32_t)nb * 16u * 80u);
#pragma unroll
                for (int mt = 0; mt < 2; mt++)
#pragma unroll
                    for (int nb = 0; nb < 4; nb++) {
                        mma16816(acc[mt][nb * 2 + 0], afrag[mt], &bfrag[nb][0]);
                        mma16816(acc[mt][nb * 2 + 1], afrag[mt], &bfrag[nb][2]);
                    }
            }
        }
        __syncthreads();
    }

    // epilogue
    const int crow = lane >> 2;
    const int ccol = (lane & 3) * 2;
#pragma unroll
    for (int mt = 0; mt < 2; mt++) {
#pragma unroll
        for (int nt = 0; nt < 8; nt++) {
            const int row = bm + warp_m * 32 + mt * 16 + crow;
            const int col = bn + warp_n * 64 + nt * 8 + ccol;
            *(float2*)&C[(size_t)row * N + col]       = make_float2(acc[mt][nt][0], acc[mt][nt][1]);
            *(float2*)&C[(size_t)(row + 8) * N + col] = make_float2(acc[mt][nt][2], acc[mt][nt][3]);
        }
    }
}

// =====================================================================
// RoPE (in place)
// =====================================================================
__global__ void rope_kernel(float* __restrict__ t,
                            const float* __restrict__ cosT,
                            const float* __restrict__ sinT,
                            int nheads, int total_pairs) {
    int idx = blockIdx.x * 256 + threadIdx.x;
    if (idx >= total_pairs) return;
    int j   = idx & 63;
    int grp = idx >> 6;
    int s   = (grp / nheads) % S_LEN;
    float c  = cosT[s * 64 + j];
    float sn = sinT[s * 64 + j];
    float2 v = *(float2*)&t[(size_t)idx * 2];
    float2 o;
    o.x = v.x * c - v.y * sn;
    o.y = v.x * sn + v.y * c;
    *(float2*)&t[(size_t)idx * 2] = o;
}

// =====================================================================
// Flash attention (causal, GQA). BM=BN=64, D=128, 256 threads, f32x2.
// =====================================================================
#define FLASH_SMEM_FLOATS (64*132 + 128*68 + 64*132 + 64*68 + 64*3)
#define FLASH_SMEM_BYTES  (FLASH_SMEM_FLOATS * 4)

__global__ __launch_bounds__(256) void flash_kernel(const float* __restrict__ Q,
                                                    const float* __restrict__ K,
                                                    const float* __restrict__ V,
                                                    float* __restrict__ O) {
    const int qt = blockIdx.x;
    const int h  = blockIdx.y;
    const int b  = blockIdx.z;
    const int g  = h >> 2;

    extern __shared__ float sm[];
    float* Qs   = sm;                    // [64][132]
    float* Kts  = Qs  + 64 * 132;        // [128][68]
    float* Vs   = Kts + 128 * 68;        // [64][132]
    float* Ps   = Vs  + 64 * 132;        // [64][68]
    float* mrow = Ps  + 64 * 68;
    float* lrow = mrow + 64;
    float* arow = lrow + 64;

    const int tid = threadIdx.x;
    const int ty  = tid >> 4;
    const int tx  = tid & 15;
    const float scale = 0.08838834764831845f;

#pragma unroll
    for (int t = 0; t < 8; t++) {
        int idx = tid + t * 256;
        int row = idx >> 5;
        int dv  = idx & 31;
        float4 v = *(const float4*)&Q[(((size_t)(b * S_LEN + qt * 64 + row)) * NH + h) * HD + dv * 4];
        v.x *= scale; v.y *= scale; v.z *= scale; v.w *= scale;
        *(float4*)&Qs[row * 132 + dv * 4] = v;
    }
    if (tid < 64) { mrow[tid] = -INFINITY; lrow[tid] = 0.0f; }

    unsigned long long oacc2[4][4];
#pragma unroll
    for (int i = 0; i < 4; i++)
#pragma unroll
        for (int j = 0; j < 4; j++) oacc2[i][j] = 0ULL;

    for (int jt = 0; jt <= qt; jt++) {
        __syncthreads();
#pragma unroll
        for (int t = 0; t < 8; t++) {
            int idx = tid + t * 256;
            int row = idx >> 5;
            int dv  = idx & 31;
            size_t base = (((size_t)(b * S_LEN + jt * 64 + row)) * NKV + g) * HD + dv * 4;
            float4 kv = *(const float4*)&K[base];
            Kts[(dv * 4 + 0) * 68 + row] = kv.x;
            Kts[(dv * 4 + 1) * 68 + row] = kv.y;
            Kts[(dv * 4 + 2) * 68 + row] = kv.z;
            Kts[(dv * 4 + 3) * 68 + row] = kv.w;
            float4 vv = *(const float4*)&V[base];
            *(float4*)&Vs[row * 132 + dv * 4] = vv;
        }
        __syncthreads();

        // ---- S = Q K^T (f32x2) ----
        unsigned long long sacc2[4][2];
#pragma unroll
        for (int i = 0; i < 4; i++) { sacc2[i][0] = 0ULL; sacc2[i][1] = 0ULL; }

#pragma unroll 8
        for (int kk = 0; kk < HD; kk++) {
            unsigned long long a0 = pack2(Qs[(ty * 4 + 0) * 132 + kk]);
            unsigned long long a1 = pack2(Qs[(ty * 4 + 1) * 132 + kk]);
            unsigned long long a2 = pack2(Qs[(ty * 4 + 2) * 132 + kk]);
            unsigned long long a3 = pack2(Qs[(ty * 4 + 3) * 132 + kk]);
            ulonglong2 bv = *(const ulonglong2*)&Kts[kk * 68 + tx * 4];
            fma2(sacc2[0][0], a0, bv.x); fma2(sacc2[0][1], a0, bv.y);
            fma2(sacc2[1][0], a1, bv.x); fma2(sacc2[1][1], a1, bv.y);
            fma2(sacc2[2][0], a2, bv.x); fma2(sacc2[2][1], a2, bv.y);
            fma2(sacc2[3][0], a3, bv.x); fma2(sacc2[3][1], a3, bv.y);
        }

        float sacc[4][4];
#pragma unroll
        for (int i = 0; i < 4; i++) {
            float2 v0 = unpack2(sacc2[i][0]);
            float2 v1 = unpack2(sacc2[i][1]);
            sacc[i][0] = v0.x; sacc[i][1] = v0.y; sacc[i][2] = v1.x; sacc[i][3] = v1.y;
        }

        if (jt == qt) {
#pragma unroll
            for (int i = 0; i < 4; i++)
#pragma unroll
                for (int j = 0; j < 4; j++)
                    if (tx * 4 + j > ty * 4 + i) sacc[i][j] = -1e30f;
        }
#pragma unroll
        for (int i = 0; i < 4; i++) {
            float4 pv = make_float4(sacc[i][0], sacc[i][1], sacc[i][2], sacc[i][3]);
            *(float4*)&Ps[(ty * 4 + i) * 68 + tx * 4] = pv;
        }
        __syncthreads();

        // ---- online softmax: 4 threads per row ----
        {
            const int r = tid >> 2;
            const int q = tid & 3;
            float* prow = &Ps[r * 68 + q * 16];
            float mold = mrow[r];
            float4 x0 = *(float4*)&prow[0];
            float4 x1 = *(float4*)&prow[4];
            float4 x2 = *(float4*)&prow[8];
            float4 x3 = *(float4*)&prow[12];
            float mx = fmaxf(fmaxf(fmaxf(x0.x, x0.y), fmaxf(x0.z, x0.w)),
                             fmaxf(fmaxf(x1.x, x1.y), fmaxf(x1.z, x1.w)));
            mx = fmaxf(mx, fmaxf(fmaxf(x2.x, x2.y), fmaxf(x2.z, x2.w)));
            mx = fmaxf(mx, fmaxf(fmaxf(x3.x, x3.y), fmaxf(x3.z, x3.w)));
            mx = fmaxf(mx, mold);
            mx = fmaxf(mx, __shfl_xor_sync(0xffffffffu, mx, 1));
            mx = fmaxf(mx, __shfl_xor_sync(0xffffffffu, mx, 2));
            x0.x = __expf(x0.x - mx); x0.y = __expf(x0.y - mx); x0.z = __expf(x0.z - mx); x0.w = __expf(x0.w - mx);
            x1.x = __expf(x1.x - mx); x1.y = __expf(x1.y - mx); x1.z = __expf(x1.z - mx); x1.w = __expf(x1.w - mx);
            x2.x = __expf(x2.x - mx); x2.y = __expf(x2.y - mx); x2.z = __expf(x2.z - mx); x2.w = __expf(x2.w - mx);
            x3.x = __expf(x3.x - mx); x3.y = __expf(x3.y - mx); x3.z = __expf(x3.z - mx); x3.w = __expf(x3.w - mx);
            *(float4*)&prow[0]  = x0;
            *(float4*)&prow[4]  = x1;
            *(float4*)&prow[8]  = x2;
            *(float4*)&prow[12] = x3;
            float sum = (x0.x + x0.y + x0.z + x0.w) + (x1.x + x1.y + x1.z + x1.w)
                      + (x2.x + x2.y + x2.z + x2.w) + (x3.x + x3.y + x3.z + x3.w);
            sum += __shfl_xor_sync(0xffffffffu, sum, 1);
            sum += __shfl_xor_sync(0xffffffffu, sum, 2);
            if (q == 0) {
                float al = __expf(mold - mx);
                mrow[r] = mx;
                lrow[r] = lrow[r] * al + sum;
                arow[r] = al;
            }
        }
        __syncthreads();

        // ---- O = O*alpha + P V (f32x2) ----
        unsigned long long al2[4];
#pragma unroll
        for (int i = 0; i < 4; i++) al2[i] = pack2(arow[ty * 4 + i]);
#pragma unroll
        for (int i = 0; i < 4; i++)
#pragma unroll
            for (int j = 0; j < 4; j++) mul2(oacc2[i][j], al2[i]);

#pragma unroll 4
        for (int kk = 0; kk < 64; kk++) {
            unsigned long long p0 = pack2(Ps[(ty * 4 + 0) * 68 + kk]);
            unsigned long long p1 = pack2(Ps[(ty * 4 + 1) * 68 + kk]);
            unsigned long long p2 = pack2(Ps[(ty * 4 + 2) * 68 + kk]);
            unsigned long long p3 = pack2(Ps[(ty * 4 + 3) * 68 + kk]);
            ulonglong2 v0 = *(const ulonglong2*)&Vs[kk * 132 + tx * 8];
            ulonglong2 v1 = *(const ulonglong2*)&Vs[kk * 132 + tx * 8 + 4];
            fma2(oacc2[0][0], p0, v0.x); fma2(oacc2[0][1], p0, v0.y); fma2(oacc2[0][2], p0, v1.x); fma2(oacc2[0][3], p0, v1.y);
            fma2(oacc2[1][0], p1, v0.x); fma2(oacc2[1][1], p1, v0.y); fma2(oacc2[1][2], p1, v1.x); fma2(oacc2[1][3], p1, v1.y);
            fma2(oacc2[2][0], p2, v0.x); fma2(oacc2[2][1], p2, v0.y); fma2(oacc2[2][2], p2, v1.x); fma2(oacc2[2][3], p2, v1.y);
            fma2(oacc2[3][0], p3, v0.x); fma2(oacc2[3][1], p3, v0.y); fma2(oacc2[3][2], p3, v1.x); fma2(oacc2[3][3], p3, v1.y);
        }
    }

    // ---- normalize + write ----
#pragma unroll
    for (int i = 0; i < 4; i++) {
        float li = 1.0f / lrow[ty * 4 + i];
        size_t base = (((size_t)(b * S_LEN + qt * 64 + ty * 4 + i)) * NH + h) * HD + tx * 8;
#pragma unroll
        for (int j = 0; j < 4; j++) {
            float2 v = unpack2(oacc2[i][j]);
            O[base + j * 2 + 0] = v.x * li;
            O[base + j * 2 + 1] = v.y * li;
        }
    }
}

// =====================================================================
// launch
// =====================================================================
extern "C" void kernel_launch(void* const* d_in, const int* in_sizes, int n_in,
                              void* d_out, int out_size) {
    (void)in_sizes; (void)n_in; (void)out_size;
    const float* x    = (const float*)d_in[0];
    const float* cosT = (const float*)d_in[1];
    const float* sinT = (const float*)d_in[2];
    const float* wq   = (const float*)d_in[3];
    const float* wk   = (const float*)d_in[4];
    const float* wv   = (const float*)d_in[5];
    const float* wo   = (const float*)d_in[6];
    float* out = (float*)d_out;

    float *pq, *pk, *pv, *po;
    cudaGetSymbolAddress((void**)&pq, g_q);
    cudaGetSymbolAddress((void**)&pk, g_k);
    cudaGetSymbolAddress((void**)&pv, g_v);
    cudaGetSymbolAddress((void**)&po, g_o);
    __nv_bfloat16 *xh, *xl, *oh, *ol, *wqh, *wql, *wkh, *wkl, *wvh, *wvl, *woh, *wol;
    cudaGetSymbolAddress((void**)&xh, g_xh);   cudaGetSymbolAddress((void**)&xl, g_xl);
    cudaGetSymbolAddress((void**)&oh, g_oh);   cudaGetSymbolAddress((void**)&ol, g_ol);
    cudaGetSymbolAddress((void**)&wqh, g_wqh); cudaGetSymbolAddress((void**)&wql, g_wql);
    cudaGetSymbolAddress((void**)&wkh, g_wkh); cudaGetSymbolAddress((void**)&wkl, g_wkl);
    cudaGetSymbolAddress((void**)&wvh, g_wvh); cudaGetSymbolAddress((void**)&wvl, g_wvl);
    cudaGetSymbolAddress((void**)&woh, g_woh); cudaGetSymbolAddress((void**)&wol, g_wol);

    cudaFuncSetAttribute(flash_kernel, cudaFuncAttributeMaxDynamicSharedMemorySize, FLASH_SMEM_BYTES);
    cudaFuncSetAttribute(gemm_bf16x3, cudaFuncAttributeMaxDynamicSharedMemorySize, GEMM_SMEM_BYTES);

    // split inputs to bf16 hi/lo
    {
        int n4 = MTOT * DIM / 4;
        split_kernel<<<(n4 + 255) / 256, 256>>>(x, xh, xl, n4);
        n4 = DIM * DIM / 4;
        split_kernel<<<(n4 + 255) / 256, 256>>>(wq, wqh, wql, n4);
        split_kernel<<<(n4 + 255) / 256, 256>>>(wo, woh, wol, n4);
        n4 = KVD * DIM / 4;
        split_kernel<<<(n4 + 255) / 256, 256>>>(wk, wkh, wkl, n4);
        split_kernel<<<(n4 + 255) / 256, 256>>>(wv, wvh, wvl, n4);
    }

    // projections (tensor core)
    gemm_bf16x3<<<dim3(DIM / 128, MTOT / 128), 256, GEMM_SMEM_BYTES>>>(xh, xl, wqh, wql, pq, DIM, DIM);
    gemm_bf16x3<<<dim3(KVD / 128, MTOT / 128), 256, GEMM_SMEM_BYTES>>>(xh, xl, wkh, wkl, pk, KVD, DIM);
    gemm_bf16x3<<<dim3(KVD / 128, MTOT / 128), 256, GEMM_SMEM_BYTES>>>(xh, xl, wvh, wvl, pv, KVD, DIM);

    // RoPE
    {
        int qp = MTOT * NH * (HD / 2);
        rope_kernel<<<(qp + 255) / 256, 256>>>(pq, cosT, sinT, NH, qp);
        int kp = MTOT * NKV * (HD / 2);
        rope_kernel<<<(kp + 255) / 256, 256>>>(pk, cosT, sinT, NKV, kp);
    }

    // attention
    flash_kernel<<<dim3(S_LEN / 64, NH, B_SZ), 256, FLASH_SMEM_BYTES>>>(pq, pk, pv, po);

    // output projection
    {
        int n4 = MTOT * DIM / 4;
        split_kernel<<<(n4 + 255) / 256, 256>>>(po, oh, ol, n4);
    }
    gemm_bf16x3<<<dim3(DIM / 128, MTOT / 128), 256, GEMM_SMEM_BYTES>>>(oh, ol, woh, wol, out, DIM, DIM);
}

// round 4
// speedup vs baseline: 1.9815x; 1.0725x over previous
#include <cuda_runtime.h>
#include <cuda_fp16.h>
#include <math.h>
#include <stdint.h>

#define B_SZ  8
#define S_LEN 1024
#define NH    16
#define NKV   4
#define HD    128
#define DIM   2048
#define MTOT  (B_SZ * S_LEN)   // 8192
#define KVD   (NKV * HD)       // 512
#define QKVN  (DIM + 2 * KVD)  // 3072

// ---------------- static scratch (allocation-free) ----------------
__device__ float  g_qkv[(size_t)MTOT * QKVN];   // fused Q|K|V fp32
__device__ float  g_o[(size_t)MTOT * DIM];      // attention out fp32
__device__ __half g_xh[(size_t)MTOT * DIM], g_xl[(size_t)MTOT * DIM];
__device__ __half g_oh[(size_t)MTOT * DIM], g_ol[(size_t)MTOT * DIM];
__device__ __half g_wf[(size_t)QKVN * DIM];     // fused wq|wk|wv fp16
__device__ __half g_wo2[(size_t)DIM * DIM];     // wo fp16

// ---------------- helpers ----------------
__device__ __forceinline__ uint32_t smem_u32(const void* p) {
    uint32_t a;
    asm("{ .reg .u64 t; cvta.to.shared.u64 t, %1; cvt.u32.u64 %0, t; }" : "=r"(a) : "l"(p));
    return a;
}

__device__ __forceinline__ void ldsm_x4(uint32_t* r, uint32_t addr) {
    asm volatile("ldmatrix.sync.aligned.m8n8.x4.shared.b16 {%0,%1,%2,%3}, [%4];"
        : "=r"(r[0]), "=r"(r[1]), "=r"(r[2]), "=r"(r[3]) : "r"(addr));
}

__device__ __forceinline__ void mma16816(float* d, const uint32_t* a, const uint32_t* b) {
    asm volatile("mma.sync.aligned.m16n8k16.row.col.f32.f16.f16.f32 "
        "{%0,%1,%2,%3}, {%4,%5,%6,%7}, {%8,%9}, {%0,%1,%2,%3};"
        : "+f"(d[0]), "+f"(d[1]), "+f"(d[2]), "+f"(d[3])
        : "r"(a[0]), "r"(a[1]), "r"(a[2]), "r"(a[3]), "r"(b[0]), "r"(b[1]));
}

// f32x2 packed helpers
__device__ __forceinline__ unsigned long long pack2(float x) {
    unsigned long long r; asm("mov.b64 %0, {%1, %1};" : "=l"(r) : "f"(x)); return r;
}
__device__ __forceinline__ void fma2(unsigned long long& d, unsigned long long a, unsigned long long b) {
    asm("fma.rn.f32x2 %0, %1, %2, %0;" : "+l"(d) : "l"(a), "l"(b));
}
__device__ __forceinline__ void mul2(unsigned long long& d, unsigned long long a) {
    asm("mul.rn.f32x2 %0, %0, %1;" : "+l"(d) : "l"(a));
}
__device__ __forceinline__ float2 unpack2(unsigned long long v) {
    float2 r; asm("mov.b64 {%0, %1}, %2;" : "=f"(r.x), "=f"(r.y) : "l"(v)); return r;
}

// =====================================================================
// convert fp32 -> fp16
// =====================================================================
__global__ void tofp16_kernel(const float* __restrict__ in, __half* __restrict__ out, int n4) {
    int i = blockIdx.x * 256 + threadIdx.x;
    if (i >= n4) return;
    float4 v = ((const float4*)in)[i];
    __half2* op = (__half2*)out;
    op[i * 2 + 0] = __floats2half2_rn(v.x, v.y);
    op[i * 2 + 1] = __floats2half2_rn(v.z, v.w);
}

// =====================================================================
// split fp32 -> fp16 hi + fp16 lo
// =====================================================================
__global__ void split_kernel(const float* __restrict__ in,
                             __half* __restrict__ hi,
                             __half* __restrict__ lo, int n4) {
    int i = blockIdx.x * 256 + threadIdx.x;
    if (i >= n4) return;
    float4 v = ((const float4*)in)[i];
    __half h0 = __float2half_rn(v.x), h1 = __float2half_rn(v.y);
    __half h2 = __float2half_rn(v.z), h3 = __float2half_rn(v.w);
    __half l0 = __float2half_rn(v.x - __half2float(h0));
    __half l1 = __float2half_rn(v.y - __half2float(h1));
    __half l2 = __float2half_rn(v.z - __half2float(h2));
    __half l3 = __float2half_rn(v.w - __half2float(h3));
    __half2* hp = (__half2*)hi;
    __half2* lp = (__half2*)lo;
    hp[i * 2 + 0] = __half2(h0, h1);
    hp[i * 2 + 1] = __half2(h2, h3);
    lp[i * 2 + 0] = __half2(l0, l1);
    lp[i * 2 + 1] = __half2(l2, l3);
}

// =====================================================================
// GEMM via mma.sync fp16 (2-pass A-split): C[M,N] = (Ah+Al) @ B^T
// tile 128x128, BK=32, 256 threads (8 warps, warp tile 32x64).
// smem: 2 stages x 3 tiles (Ah,Al,B) x 128x40 halves = 61440 B
// =====================================================================
#define TILE_B   10240
#define STAGE_B  (3 * TILE_B)
#define GEMM_SMEM_BYTES (2 * STAGE_B)

__device__ __forceinline__ void gemm_load_chunk(
    const __half* __restrict__ Ah, const __half* __restrict__ Al,
    const __half* __restrict__ B,
    int bm, int bn, int K, int kc, uint32_t stbase, int tid) {
#pragma unroll
    for (int t = 0; t < 6; t++) {
        const int tile = t >> 1;                  // 0:Ah 1:Al 2:B (compile-time)
        const int rem  = tid + (t & 1) * 256;     // 0..511
        const int row  = rem >> 2;
        const int c    = rem & 3;
        const __half* base = (tile == 0) ? Ah : (tile == 1) ? Al : B;
        const int grow = ((tile < 2) ? bm : bn) + row;
        const void* g = base + (size_t)grow * K + kc * 32 + c * 8;
        uint32_t dst = stbase + (uint32_t)tile * TILE_B + (uint32_t)(row * 80 + c * 16);
        asm volatile("cp.async.cg.shared.global [%0], [%1], 16;" :: "r"(dst), "l"(g) : "memory");
    }
    asm volatile("cp.async.commit_group;" ::: "memory");
}

__global__ __launch_bounds__(256, 2)
void gemm_f16x2(const __half* __restrict__ Ah, const __half* __restrict__ Al,
                const __half* __restrict__ B,
                float* __restrict__ C, int N, int K) {
    extern __shared__ char smem_raw[];
    const uint32_t sbase = smem_u32(smem_raw);

    const int tid  = threadIdx.x;
    const int wid  = tid >> 5;
    const int lane = tid & 31;
    const int warp_m = wid & 3;        // 4 warps along M (32 rows each)
    const int warp_n = wid >> 2;       // 2 warps along N (64 cols each)
    const int bm = blockIdx.y * 128;
    const int bn = blockIdx.x * 128;

    float acc[2][8][4];
#pragma unroll
    for (int i = 0; i < 2; i++)
#pragma unroll
        for (int j = 0; j < 8; j++)
#pragma unroll
            for (int v = 0; v < 4; v++) acc[i][j][v] = 0.0f;

    const uint32_t a_row = (uint32_t)(warp_m * 32 + (lane & 15));
    const uint32_t a_off = a_row * 80u + (uint32_t)((lane >> 4) * 16);
    const uint32_t b_row = (uint32_t)(warp_n * 64 + (lane & 7) + ((lane >> 4) & 1) * 8);
    const uint32_t b_off = b_row * 80u + (uint32_t)(((lane >> 3) & 1) * 16);

    const int NCHUNK = K >> 5;   // BK = 32

    gemm_load_chunk(Ah, Al, B, bm, bn, K, 0, sbase, tid);

    for (int c = 0; c < NCHUNK; c++) {
        const uint32_t stage = (uint32_t)(c & 1) * STAGE_B;
        if (c + 1 < NCHUNK) {
            gemm_load_chunk(Ah, Al, B, bm, bn, K, c + 1,
                            sbase + (uint32_t)((c + 1) & 1) * STAGE_B, tid);
            asm volatile("cp.async.wait_group 1;" ::: "memory");
        } else {
            asm volatile("cp.async.wait_group 0;" ::: "memory");
        }
        __syncthreads();

#pragma unroll
        for (int ks = 0; ks < 2; ks++) {
            const uint32_t aH = sbase + stage + a_off + (uint32_t)ks * 32u;
            const uint32_t aL = aH + TILE_B;
            const uint32_t bb = sbase + stage + 2u * TILE_B + b_off + (uint32_t)ks * 32u;
            uint32_t bfrag[4][4];
#pragma unroll
            for (int nb = 0; nb < 4; nb++)
                ldsm_x4(bfrag[nb], bb + (uint32_t)nb * 16u * 80u);
            uint32_t ah[2][4], al[2][4];
            ldsm_x4(ah[0], aH);
            ldsm_x4(ah[1], aH + 16u * 80u);
            ldsm_x4(al[0], aL);
            ldsm_x4(al[1], aL + 16u * 80u);
#pragma unroll
            for (int mt = 0; mt < 2; mt++)
#pragma unroll
                for (int nb = 0; nb < 4; nb++) {
                    mma16816(acc[mt][nb * 2 + 0], ah[mt], &bfrag[nb][0]);
                    mma16816(acc[mt][nb * 2 + 1], ah[mt], &bfrag[nb][2]);
                    mma16816(acc[mt][nb * 2 + 0], al[mt], &bfrag[nb][0]);
                    mma16816(acc[mt][nb * 2 + 1], al[mt], &bfrag[nb][2]);
                }
        }
        __syncthreads();
    }

    const int crow = lane >> 2;
    const int ccol = (lane & 3) * 2;
#pragma unroll
    for (int mt = 0; mt < 2; mt++) {
#pragma unroll
        for (int nt = 0; nt < 8; nt++) {
            const int row = bm + warp_m * 32 + mt * 16 + crow;
            const int col = bn + warp_n * 64 + nt * 8 + ccol;
            *(float2*)&C[(size_t)row * N + col]       = make_float2(acc[mt][nt][0], acc[mt][nt][1]);
            *(float2*)&C[(size_t)(row + 8) * N + col] = make_float2(acc[mt][nt][2], acc[mt][nt][3]);
        }
    }
}

// =====================================================================
// RoPE (in place, strided rows)
// =====================================================================
__global__ void rope_kernel(float* __restrict__ t,
                            const float* __restrict__ cosT,
                            const float* __restrict__ sinT,
                            int nheads, int ld, int total_pairs) {
    int idx = blockIdx.x * 256 + threadIdx.x;
    if (idx >= total_pairs) return;
    int j     = idx & 63;
    int grp   = idx >> 6;
    int h     = grp % nheads;
    int token = grp / nheads;
    int s     = token % S_LEN;
    float c  = cosT[s * 64 + j];
    float sn = sinT[s * 64 + j];
    float* p = t + (size_t)token * ld + h * HD + j * 2;
    float2 v = *(float2*)p;
    float2 o;
    o.x = v.x * c - v.y * sn;
    o.y = v.x * sn + v.y * c;
    *(float2*)p = o;
}

// =====================================================================
// Flash attention (causal, GQA). BM=BN=64, D=128, 256 threads, f32x2.
// Q and P stored as duplicated pairs in smem (LDS.64, no pack2).
// QKV is the fused [MTOT][3072] buffer.
// =====================================================================
// smem layout (bytes):
//   Qd : ull[64*128]   65536   @ 0
//   Kts: f32[128*68]   34816   @ 65536
//   Vs : f32[64*132]   33792   @ 100352
//   Ps : f32[64*68]    17408   @ 134144
//   Pd : ull[64*66]    33792   @ 151552
//   mrow/lrow/arow: 3*64*4=768 @ 185344
#define FLASH_SMEM_BYTES 186112

__global__ __launch_bounds__(256) void flash_kernel(const float* __restrict__ QKV,
                                                    float* __restrict__ O) {
    const int qt = blockIdx.x;
    const int h  = blockIdx.y;
    const int b  = blockIdx.z;
    const int g  = h >> 2;

    extern __shared__ char smraw[];
    unsigned long long* Qd = (unsigned long long*)(smraw);
    float* Kts  = (float*)(smraw + 65536);
    float* Vs   = (float*)(smraw + 100352);
    float* Ps   = (float*)(smraw + 134144);
    unsigned long long* Pd = (unsigned long long*)(smraw + 151552);
    float* mrow = (float*)(smraw + 185344);
    float* lrow = mrow + 64;
    float* arow = lrow + 64;

    const int tid = threadIdx.x;
    const int ty  = tid >> 4;
    const int tx  = tid & 15;
    const float scale = 0.08838834764831845f;  // 1/sqrt(128)

    // ---- load Q tile (pre-scaled, duplicated pairs) ----
#pragma unroll
    for (int t = 0; t < 8; t++) {
        int idx = tid + t * 256;       // over 64 rows x 32 float4
        int row = idx >> 5;
        int dv  = idx & 31;
        float4 v = *(const float4*)&QKV[(size_t)(b * S_LEN + qt * 64 + row) * QKVN + h * HD + dv * 4];
        Qd[row * 128 + dv * 4 + 0] = pack2(v.x * scale);
        Qd[row * 128 + dv * 4 + 1] = pack2(v.y * scale);
        Qd[row * 128 + dv * 4 + 2] = pack2(v.z * scale);
        Qd[row * 128 + dv * 4 + 3] = pack2(v.w * scale);
    }
    if (tid < 64) { mrow[tid] = -INFINITY; lrow[tid] = 0.0f; }

    unsigned long long oacc2[4][4];
#pragma unroll
    for (int i = 0; i < 4; i++)
#pragma unroll
        for (int j = 0; j < 4; j++) oacc2[i][j] = 0ULL;

    for (int jt = 0; jt <= qt; jt++) {
        __syncthreads();
        // ---- load K (transposed) and V tiles ----
#pragma unroll
        for (int t = 0; t < 8; t++) {
            int idx = tid + t * 256;
            int row = idx >> 5;
            int dv  = idx & 31;
            size_t base = (size_t)(b * S_LEN + jt * 64 + row) * QKVN + DIM + g * HD + dv * 4;
            float4 kv = *(const float4*)&QKV[base];
            Kts[(dv * 4 + 0) * 68 + row] = kv.x;
            Kts[(dv * 4 + 1) * 68 + row] = kv.y;
            Kts[(dv * 4 + 2) * 68 + row] = kv.z;
            Kts[(dv * 4 + 3) * 68 + row] = kv.w;
            float4 vv = *(const float4*)&QKV[base + KVD];
            *(float4*)&Vs[row * 132 + dv * 4] = vv;
        }
        __syncthreads();

        // ---- S = Q K^T (f32x2, Q from duplicated pairs) ----
        unsigned long long sacc2[4][2];
#pragma unroll
        for (int i = 0; i < 4; i++) { sacc2[i][0] = 0ULL; sacc2[i][1] = 0ULL; }

#pragma unroll 8
        for (int kk = 0; kk < HD; kk++) {
            unsigned long long a0 = Qd[(ty * 4 + 0) * 128 + kk];
            unsigned long long a1 = Qd[(ty * 4 + 1) * 128 + kk];
            unsigned long long a2 = Qd[(ty * 4 + 2) * 128 + kk];
            unsigned long long a3 = Qd[(ty * 4 + 3) * 128 + kk];
            ulonglong2 bv = *(const ulonglong2*)&Kts[kk * 68 + tx * 4];
            fma2(sacc2[0][0], a0, bv.x); fma2(sacc2[0][1], a0, bv.y);
            fma2(sacc2[1][0], a1, bv.x); fma2(sacc2[1][1], a1, bv.y);
            fma2(sacc2[2][0], a2, bv.x); fma2(sacc2[2][1], a2, bv.y);
            fma2(sacc2[3][0], a3, bv.x); fma2(sacc2[3][1], a3, bv.y);
        }

        float sacc[4][4];
#pragma unroll
        for (int i = 0; i < 4; i++) {
            float2 v0 = unpack2(sacc2[i][0]);
            float2 v1 = unpack2(sacc2[i][1]);
            sacc[i][0] = v0.x; sacc[i][1] = v0.y; sacc[i][2] = v1.x; sacc[i][3] = v1.y;
        }

        if (jt == qt) {
#pragma unroll
            for (int i = 0; i < 4; i++)
#pragma unroll
                for (int j = 0; j < 4; j++)
                    if (tx * 4 + j > ty * 4 + i) sacc[i][j] = -1e30f;
        }
#pragma unroll
        for (int i = 0; i < 4; i++) {
            float4 pv = make_float4(sacc[i][0], sacc[i][1], sacc[i][2], sacc[i][3]);
            *(float4*)&Ps[(ty * 4 + i) * 68 + tx * 4] = pv;
        }
        __syncthreads();

        // ---- online softmax: 4 threads per row, exp -> Pd pairs ----
        {
            const int r = tid >> 2;
            const int q = tid & 3;
            float* prow = &Ps[r * 68 + q * 16];
            float mold = mrow[r];
            float4 x0 = *(float4*)&prow[0];
            float4 x1 = *(float4*)&prow[4];
            float4 x2 = *(float4*)&prow[8];
            float4 x3 = *(float4*)&prow[12];
            float mx = fmaxf(fmaxf(fmaxf(x0.x, x0.y), fmaxf(x0.z, x0.w)),
                             fmaxf(fmaxf(x1.x, x1.y), fmaxf(x1.z, x1.w)));
            mx = fmaxf(mx, fmaxf(fmaxf(x2.x, x2.y), fmaxf(x2.z, x2.w)));
            mx = fmaxf(mx, fmaxf(fmaxf(x3.x, x3.y), fmaxf(x3.z, x3.w)));
            mx = fmaxf(mx, mold);
            mx = fmaxf(mx, __shfl_xor_sync(0xffffffffu, mx, 1));
            mx = fmaxf(mx, __shfl_xor_sync(0xffffffffu, mx, 2));
            x0.x = __expf(x0.x - mx); x0.y = __expf(x0.y - mx); x0.z = __expf(x0.z - mx); x0.w = __expf(x0.w - mx);
            x1.x = __expf(x1.x - mx); x1.y = __expf(x1.y - mx); x1.z = __expf(x1.z - mx); x1.w = __expf(x1.w - mx);
            x2.x = __expf(x2.x - mx); x2.y = __expf(x2.y - mx); x2.z = __expf(x2.z - mx); x2.w = __expf(x2.w - mx);
            x3.x = __expf(x3.x - mx); x3.y = __expf(x3.y - mx); x3.z = __expf(x3.z - mx); x3.w = __expf(x3.w - mx);
            unsigned long long* pd = &Pd[r * 66 + q * 16];
            pd[0]  = pack2(x0.x); pd[1]  = pack2(x0.y); pd[2]  = pack2(x0.z); pd[3]  = pack2(x0.w);
            pd[4]  = pack2(x1.x); pd[5]  = pack2(x1.y); pd[6]  = pack2(x1.z); pd[7]  = pack2(x1.w);
            pd[8]  = pack2(x2.x); pd[9]  = pack2(x2.y); pd[10] = pack2(x2.z); pd[11] = pack2(x2.w);
            pd[12] = pack2(x3.x); pd[13] = pack2(x3.y); pd[14] = pack2(x3.z); pd[15] = pack2(x3.w);
            float sum = (x0.x + x0.y + x0.z + x0.w) + (x1.x + x1.y + x1.z + x1.w)
                      + (x2.x + x2.y + x2.z + x2.w) + (x3.x + x3.y + x3.z + x3.w);
            sum += __shfl_xor_sync(0xffffffffu, sum, 1);
            sum += __shfl_xor_sync(0xffffffffu, sum, 2);
            if (q == 0) {
                float al = __expf(mold - mx);
                mrow[r] = mx;
                lrow[r] = lrow[r] * al + sum;
                arow[r] = al;
            }
        }
        __syncthreads();

        // ---- O = O*alpha + P V (f32x2, P from duplicated pairs) ----
        unsigned long long al2[4];
#pragma unroll
        for (int i = 0; i < 4; i++) al2[i] = pack2(arow[ty * 4 + i]);
#pragma unroll
        for (int i = 0; i < 4; i++)
#pragma unroll
            for (int j = 0; j < 4; j++) mul2(oacc2[i][j], al2[i]);

#pragma unroll 4
        for (int kk = 0; kk < 64; kk++) {
            unsigned long long p0 = Pd[(ty * 4 + 0) * 66 + kk];
            unsigned long long p1 = Pd[(ty * 4 + 1) * 66 + kk];
            unsigned long long p2 = Pd[(ty * 4 + 2) * 66 + kk];
            unsigned long long p3 = Pd[(ty * 4 + 3) * 66 + kk];
            ulonglong2 v0 = *(const ulonglong2*)&Vs[kk * 132 + tx * 8];
            ulonglong2 v1 = *(const ulonglong2*)&Vs[kk * 132 + tx * 8 + 4];
            fma2(oacc2[0][0], p0, v0.x); fma2(oacc2[0][1], p0, v0.y); fma2(oacc2[0][2], p0, v1.x); fma2(oacc2[0][3], p0, v1.y);
            fma2(oacc2[1][0], p1, v0.x); fma2(oacc2[1][1], p1, v0.y); fma2(oacc2[1][2], p1, v1.x); fma2(oacc2[1][3], p1, v1.y);
            fma2(oacc2[2][0], p2, v0.x); fma2(oacc2[2][1], p2, v0.y); fma2(oacc2[2][2], p2, v1.x); fma2(oacc2[2][3], p2, v1.y);
            fma2(oacc2[3][0], p3, v0.x); fma2(oacc2[3][1], p3, v0.y); fma2(oacc2[3][2], p3, v1.x); fma2(oacc2[3][3], p3, v1.y);
        }
    }

    // ---- normalize + write ----
#pragma unroll
    for (int i = 0; i < 4; i++) {
        float li = 1.0f / lrow[ty * 4 + i];
        size_t base = (size_t)(b * S_LEN + qt * 64 + ty * 4 + i) * DIM + h * HD + tx * 8;
#pragma unroll
        for (int j = 0; j < 4; j++) {
            float2 v = unpack2(oacc2[i][j]);
            O[base + j * 2 + 0] = v.x * li;
            O[base + j * 2 + 1] = v.y * li;
        }
    }
}

// =====================================================================
// launch
// =====================================================================
extern "C" void kernel_launch(void* const* d_in, const int* in_sizes, int n_in,
                              void* d_out, int out_size) {
    (void)in_sizes; (void)n_in; (void)out_size;
    const float* x    = (const float*)d_in[0];
    const float* cosT = (const float*)d_in[1];
    const float* sinT = (const float*)d_in[2];
    const float* wq   = (const float*)d_in[3];
    const float* wk   = (const float*)d_in[4];
    const float* wv   = (const float*)d_in[5];
    const float* wo   = (const float*)d_in[6];
    float* out = (float*)d_out;

    float *pqkv, *po;
    cudaGetSymbolAddress((void**)&pqkv, g_qkv);
    cudaGetSymbolAddress((void**)&po, g_o);
    __half *xh, *xl, *oh, *ol, *wf, *wo2;
    cudaGetSymbolAddress((void**)&xh, g_xh);
    cudaGetSymbolAddress((void**)&xl, g_xl);
    cudaGetSymbolAddress((void**)&oh, g_oh);
    cudaGetSymbolAddress((void**)&ol, g_ol);
    cudaGetSymbolAddress((void**)&wf, g_wf);
    cudaGetSymbolAddress((void**)&wo2, g_wo2);

    cudaFuncSetAttribute(flash_kernel, cudaFuncAttributeMaxDynamicSharedMemorySize, FLASH_SMEM_BYTES);
    cudaFuncSetAttribute(gemm_f16x2, cudaFuncAttributeMaxDynamicSharedMemorySize, GEMM_SMEM_BYTES);

    // weights -> fused fp16 buffer [wq | wk | wv], wo -> fp16
    {
        int n4 = DIM * DIM / 4;
        tofp16_kernel<<<(n4 + 255) / 256, 256>>>(wq, wf, n4);
        tofp16_kernel<<<(n4 + 255) / 256, 256>>>(wo, wo2, n4);
        int m4 = KVD * DIM / 4;
        tofp16_kernel<<<(m4 + 255) / 256, 256>>>(wk, wf + (size_t)DIM * DIM, m4);
        tofp16_kernel<<<(m4 + 255) / 256, 256>>>(wv, wf + (size_t)(DIM + KVD) * DIM, m4);
    }

    // x -> fp16 hi/lo
    {
        int n4 = MTOT * DIM / 4;
        split_kernel<<<(n4 + 255) / 256, 256>>>(x, xh, xl, n4);
    }

    // fused QKV projection
    gemm_f16x2<<<dim3(QKVN / 128, MTOT / 128), 256, GEMM_SMEM_BYTES>>>(xh, xl, wf, pqkv, QKVN, DIM);

    // RoPE on Q and K regions of fused buffer
    {
        int qp = MTOT * NH * (HD / 2);
        rope_kernel<<<(qp + 255) / 256, 256>>>(pqkv, cosT, sinT, NH, QKVN, qp);
        int kp = MTOT * NKV * (HD / 2);
        rope_kernel<<<(kp + 255) / 256, 256>>>(pqkv + DIM, cosT, sinT, NKV, QKVN, kp);
    }

    // attention
    flash_kernel<<<dim3(S_LEN / 64, NH, B_SZ), 256, FLASH_SMEM_BYTES>>>(pqkv, po);

    // output projection
    {
        int n4 = MTOT * DIM / 4;
        split_kernel<<<(n4 + 255) / 256, 256>>>(po, oh, ol, n4);
    }
    gemm_f16x2<<<dim3(DIM / 128, MTOT / 128), 256, GEMM_SMEM_BYTES>>>(oh, ol, wo2, out, DIM, DIM);
}

// round 5
// speedup vs baseline: 2.3000x; 1.1608x over previous
#include <cuda_runtime.h>
#include <cuda_fp16.h>
#include <math.h>
#include <stdint.h>

#define B_SZ  8
#define S_LEN 1024
#define NH    16
#define NKV   4
#define HD    128
#define DIM   2048
#define MTOT  (B_SZ * S_LEN)   // 8192
#define KVD   (NKV * HD)       // 512
#define QKVN  (DIM + 2 * KVD)  // 3072

// ---------------- static scratch (allocation-free) ----------------
__device__ float  g_qkv[(size_t)MTOT * QKVN];   // fused Q|K|V fp32
__device__ float  g_o[(size_t)MTOT * DIM];      // attention out fp32
__device__ __half g_xh[(size_t)MTOT * DIM];     // x fp16
__device__ __half g_oh[(size_t)MTOT * DIM];     // attn out fp16
__device__ __half g_wf[(size_t)QKVN * DIM];     // fused wq|wk|wv fp16
__device__ __half g_wo2[(size_t)DIM * DIM];     // wo fp16

// ---------------- helpers ----------------
__device__ __forceinline__ uint32_t smem_u32(const void* p) {
    uint32_t a;
    asm("{ .reg .u64 t; cvta.to.shared.u64 t, %1; cvt.u32.u64 %0, t; }" : "=r"(a) : "l"(p));
    return a;
}

__device__ __forceinline__ void ldsm_x4(uint32_t* r, uint32_t addr) {
    asm volatile("ldmatrix.sync.aligned.m8n8.x4.shared.b16 {%0,%1,%2,%3}, [%4];"
        : "=r"(r[0]), "=r"(r[1]), "=r"(r[2]), "=r"(r[3]) : "r"(addr));
}

__device__ __forceinline__ void mma16816(float* d, const uint32_t* a, const uint32_t* b) {
    asm volatile("mma.sync.aligned.m16n8k16.row.col.f32.f16.f16.f32 "
        "{%0,%1,%2,%3}, {%4,%5,%6,%7}, {%8,%9}, {%0,%1,%2,%3};"
        : "+f"(d[0]), "+f"(d[1]), "+f"(d[2]), "+f"(d[3])
        : "r"(a[0]), "r"(a[1]), "r"(a[2]), "r"(a[3]), "r"(b[0]), "r"(b[1]));
}

// f32x2 packed helpers
__device__ __forceinline__ unsigned long long pack2(float x) {
    unsigned long long r; asm("mov.b64 %0, {%1, %1};" : "=l"(r) : "f"(x)); return r;
}
__device__ __forceinline__ void fma2(unsigned long long& d, unsigned long long a, unsigned long long b) {
    asm("fma.rn.f32x2 %0, %1, %2, %0;" : "+l"(d) : "l"(a), "l"(b));
}
__device__ __forceinline__ void mul2(unsigned long long& d, unsigned long long a) {
    asm("mul.rn.f32x2 %0, %0, %1;" : "+l"(d) : "l"(a));
}
__device__ __forceinline__ float2 unpack2(unsigned long long v) {
    float2 r; asm("mov.b64 {%0, %1}, %2;" : "=f"(r.x), "=f"(r.y) : "l"(v)); return r;
}

// =====================================================================
// convert fp32 -> fp16
// =====================================================================
__global__ void tofp16_kernel(const float* __restrict__ in, __half* __restrict__ out, int n4) {
    int i = blockIdx.x * 256 + threadIdx.x;
    if (i >= n4) return;
    float4 v = ((const float4*)in)[i];
    __half2* op = (__half2*)out;
    op[i * 2 + 0] = __floats2half2_rn(v.x, v.y);
    op[i * 2 + 1] = __floats2half2_rn(v.z, v.w);
}

// =====================================================================
// GEMM via mma.sync fp16 single-pass: C[M,N] = A @ B^T, fp32 accum
// tile 128x128, BK=32, 256 threads (8 warps, warp tile 32x64).
// smem: 4 stages x 2 tiles (A,B) x 128x40 halves = 81920 B
// =====================================================================
#define TILE_B   10240
#define STAGE_B  (2 * TILE_B)
#define GEMM_SMEM_BYTES (4 * STAGE_B)

__device__ __forceinline__ void gemm_load_chunk(
    const __half* __restrict__ A, const __half* __restrict__ B,
    int bm, int bn, int K, int kc, uint32_t stbase, int tid) {
#pragma unroll
    for (int t = 0; t < 4; t++) {
        const int tile = t >> 1;                  // 0:A 1:B (compile-time)
        const int rem  = tid + (t & 1) * 256;     // 0..511
        const int row  = rem >> 2;
        const int c    = rem & 3;
        const __half* base = (tile == 0) ? A : B;
        const int grow = ((tile == 0) ? bm : bn) + row;
        const void* g = base + (size_t)grow * K + kc * 32 + c * 8;
        uint32_t dst = stbase + (uint32_t)tile * TILE_B + (uint32_t)(row * 80 + c * 16);
        asm volatile("cp.async.cg.shared.global [%0], [%1], 16;" :: "r"(dst), "l"(g) : "memory");
    }
    asm volatile("cp.async.commit_group;" ::: "memory");
}

__global__ __launch_bounds__(256, 2)
void gemm_f16(const __half* __restrict__ A, const __half* __restrict__ B,
              float* __restrict__ C, int N, int K) {
    extern __shared__ char smem_raw[];
    const uint32_t sbase = smem_u32(smem_raw);

    const int tid  = threadIdx.x;
    const int wid  = tid >> 5;
    const int lane = tid & 31;
    const int warp_m = wid & 3;        // 4 warps along M (32 rows each)
    const int warp_n = wid >> 2;       // 2 warps along N (64 cols each)
    const int bm = blockIdx.y * 128;
    const int bn = blockIdx.x * 128;

    float acc[2][8][4];
#pragma unroll
    for (int i = 0; i < 2; i++)
#pragma unroll
        for (int j = 0; j < 8; j++)
#pragma unroll
            for (int v = 0; v < 4; v++) acc[i][j][v] = 0.0f;

    const uint32_t a_row = (uint32_t)(warp_m * 32 + (lane & 15));
    const uint32_t a_off = a_row * 80u + (uint32_t)((lane >> 4) * 16);
    const uint32_t b_row = (uint32_t)(warp_n * 64 + (lane & 7) + ((lane >> 4) & 1) * 8);
    const uint32_t b_off = b_row * 80u + (uint32_t)(((lane >> 3) & 1) * 16);

    const int NCHUNK = K >> 5;   // BK = 32

    // prologue: fill 3 of 4 stages
    gemm_load_chunk(A, B, bm, bn, K, 0, sbase + 0u * STAGE_B, tid);
    gemm_load_chunk(A, B, bm, bn, K, 1, sbase + 1u * STAGE_B, tid);
    gemm_load_chunk(A, B, bm, bn, K, 2, sbase + 2u * STAGE_B, tid);

    for (int c = 0; c < NCHUNK; c++) {
        if (c + 2 < NCHUNK)      asm volatile("cp.async.wait_group 2;" ::: "memory");
        else if (c + 1 < NCHUNK) asm volatile("cp.async.wait_group 1;" ::: "memory");
        else                     asm volatile("cp.async.wait_group 0;" ::: "memory");
        __syncthreads();

        if (c + 3 < NCHUNK)
            gemm_load_chunk(A, B, bm, bn, K, c + 3,
                            sbase + (uint32_t)((c + 3) & 3) * STAGE_B, tid);

        const uint32_t stage = (uint32_t)(c & 3) * STAGE_B;
#pragma unroll
        for (int ks = 0; ks < 2; ks++) {
            const uint32_t aa = sbase + stage + a_off + (uint32_t)ks * 32u;
            const uint32_t bb = sbase + stage + TILE_B + b_off + (uint32_t)ks * 32u;
            uint32_t bfrag[4][4];
#pragma unroll
            for (int nb = 0; nb < 4; nb++)
                ldsm_x4(bfrag[nb], bb + (uint32_t)nb * 16u * 80u);
            uint32_t af[2][4];
            ldsm_x4(af[0], aa);
            ldsm_x4(af[1], aa + 16u * 80u);
#pragma unroll
            for (int mt = 0; mt < 2; mt++)
#pragma unroll
                for (int nb = 0; nb < 4; nb++) {
                    mma16816(acc[mt][nb * 2 + 0], af[mt], &bfrag[nb][0]);
                    mma16816(acc[mt][nb * 2 + 1], af[mt], &bfrag[nb][2]);
                }
        }
    }

    const int crow = lane >> 2;
    const int ccol = (lane & 3) * 2;
#pragma unroll
    for (int mt = 0; mt < 2; mt++) {
#pragma unroll
        for (int nt = 0; nt < 8; nt++) {
            const int row = bm + warp_m * 32 + mt * 16 + crow;
            const int col = bn + warp_n * 64 + nt * 8 + ccol;
            *(float2*)&C[(size_t)row * N + col]       = make_float2(acc[mt][nt][0], acc[mt][nt][1]);
            *(float2*)&C[(size_t)(row + 8) * N + col] = make_float2(acc[mt][nt][2], acc[mt][nt][3]);
        }
    }
}

// =====================================================================
// RoPE (in place, strided rows)
// =====================================================================
__global__ void rope_kernel(float* __restrict__ t,
                            const float* __restrict__ cosT,
                            const float* __restrict__ sinT,
                            int nheads, int ld, int total_pairs) {
    int idx = blockIdx.x * 256 + threadIdx.x;
    if (idx >= total_pairs) return;
    int j     = idx & 63;
    int grp   = idx >> 6;
    int h     = grp % nheads;
    int token = grp / nheads;
    int s     = token % S_LEN;
    float c  = cosT[s * 64 + j];
    float sn = sinT[s * 64 + j];
    float* p = t + (size_t)token * ld + h * HD + j * 2;
    float2 v = *(float2*)p;
    float2 o;
    o.x = v.x * c - v.y * sn;
    o.y = v.x * sn + v.y * c;
    *(float2*)p = o;
}

// =====================================================================
// Flash attention (causal, GQA). BM=BN=64, D=128, 256 threads, f32x2.
// Q and P stored as duplicated pairs in smem (LDS.64, no pack2).
// QKV is the fused [MTOT][3072] fp32 buffer.
// =====================================================================
#define FLASH_SMEM_BYTES 186112

__global__ __launch_bounds__(256) void flash_kernel(const float* __restrict__ QKV,
                                                    float* __restrict__ O) {
    const int qt = blockIdx.x;
    const int h  = blockIdx.y;
    const int b  = blockIdx.z;
    const int g  = h >> 2;

    extern __shared__ char smraw[];
    unsigned long long* Qd = (unsigned long long*)(smraw);
    float* Kts  = (float*)(smraw + 65536);
    float* Vs   = (float*)(smraw + 100352);
    float* Ps   = (float*)(smraw + 134144);
    unsigned long long* Pd = (unsigned long long*)(smraw + 151552);
    float* mrow = (float*)(smraw + 185344);
    float* lrow = mrow + 64;
    float* arow = lrow + 64;

    const int tid = threadIdx.x;
    const int ty  = tid >> 4;
    const int tx  = tid & 15;
    const float scale = 0.08838834764831845f;  // 1/sqrt(128)

#pragma unroll
    for (int t = 0; t < 8; t++) {
        int idx = tid + t * 256;
        int row = idx >> 5;
        int dv  = idx & 31;
        float4 v = *(const float4*)&QKV[(size_t)(b * S_LEN + qt * 64 + row) * QKVN + h * HD + dv * 4];
        Qd[row * 128 + dv * 4 + 0] = pack2(v.x * scale);
        Qd[row * 128 + dv * 4 + 1] = pack2(v.y * scale);
        Qd[row * 128 + dv * 4 + 2] = pack2(v.z * scale);
        Qd[row * 128 + dv * 4 + 3] = pack2(v.w * scale);
    }
    if (tid < 64) { mrow[tid] = -INFINITY; lrow[tid] = 0.0f; }

    unsigned long long oacc2[4][4];
#pragma unroll
    for (int i = 0; i < 4; i++)
#pragma unroll
        for (int j = 0; j < 4; j++) oacc2[i][j] = 0ULL;

    for (int jt = 0; jt <= qt; jt++) {
        __syncthreads();
#pragma unroll
        for (int t = 0; t < 8; t++) {
            int idx = tid + t * 256;
            int row = idx >> 5;
            int dv  = idx & 31;
            size_t base = (size_t)(b * S_LEN + jt * 64 + row) * QKVN + DIM + g * HD + dv * 4;
            float4 kv = *(const float4*)&QKV[base];
            Kts[(dv * 4 + 0) * 68 + row] = kv.x;
            Kts[(dv * 4 + 1) * 68 + row] = kv.y;
            Kts[(dv * 4 + 2) * 68 + row] = kv.z;
            Kts[(dv * 4 + 3) * 68 + row] = kv.w;
            float4 vv = *(const float4*)&QKV[base + KVD];
            *(float4*)&Vs[row * 132 + dv * 4] = vv;
        }
        __syncthreads();

        // ---- S = Q K^T (f32x2, Q from duplicated pairs) ----
        unsigned long long sacc2[4][2];
#pragma unroll
        for (int i = 0; i < 4; i++) { sacc2[i][0] = 0ULL; sacc2[i][1] = 0ULL; }

#pragma unroll 8
        for (int kk = 0; kk < HD; kk++) {
            unsigned long long a0 = Qd[(ty * 4 + 0) * 128 + kk];
            unsigned long long a1 = Qd[(ty * 4 + 1) * 128 + kk];
            unsigned long long a2 = Qd[(ty * 4 + 2) * 128 + kk];
            unsigned long long a3 = Qd[(ty * 4 + 3) * 128 + kk];
            ulonglong2 bv = *(const ulonglong2*)&Kts[kk * 68 + tx * 4];
            fma2(sacc2[0][0], a0, bv.x); fma2(sacc2[0][1], a0, bv.y);
            fma2(sacc2[1][0], a1, bv.x); fma2(sacc2[1][1], a1, bv.y);
            fma2(sacc2[2][0], a2, bv.x); fma2(sacc2[2][1], a2, bv.y);
            fma2(sacc2[3][0], a3, bv.x); fma2(sacc2[3][1], a3, bv.y);
        }

        float sacc[4][4];
#pragma unroll
        for (int i = 0; i < 4; i++) {
            float2 v0 = unpack2(sacc2[i][0]);
            float2 v1 = unpack2(sacc2[i][1]);
            sacc[i][0] = v0.x; sacc[i][1] = v0.y; sacc[i][2] = v1.x; sacc[i][3] = v1.y;
        }

        if (jt == qt) {
#pragma unroll
            for (int i = 0; i < 4; i++)
#pragma unroll
                for (int j = 0; j < 4; j++)
                    if (tx * 4 + j > ty * 4 + i) sacc[i][j] = -1e30f;
        }
#pragma unroll
        for (int i = 0; i < 4; i++) {
            float4 pv = make_float4(sacc[i][0], sacc[i][1], sacc[i][2], sacc[i][3]);
            *(float4*)&Ps[(ty * 4 + i) * 68 + tx * 4] = pv;
        }
        __syncthreads();

        // ---- online softmax: 4 threads per row, exp -> Pd pairs ----
        {
            const int r = tid >> 2;
            const int q = tid & 3;
            float* prow = &Ps[r * 68 + q * 16];
            float mold = mrow[r];
            float4 x0 = *(float4*)&prow[0];
            float4 x1 = *(float4*)&prow[4];
            float4 x2 = *(float4*)&prow[8];
            float4 x3 = *(float4*)&prow[12];
            float mx = fmaxf(fmaxf(fmaxf(x0.x, x0.y), fmaxf(x0.z, x0.w)),
                             fmaxf(fmaxf(x1.x, x1.y), fmaxf(x1.z, x1.w)));
            mx = fmaxf(mx, fmaxf(fmaxf(x2.x, x2.y), fmaxf(x2.z, x2.w)));
            mx = fmaxf(mx, fmaxf(fmaxf(x3.x, x3.y), fmaxf(x3.z, x3.w)));
            mx = fmaxf(mx, mold);
            mx = fmaxf(mx, __shfl_xor_sync(0xffffffffu, mx, 1));
            mx = fmaxf(mx, __shfl_xor_sync(0xffffffffu, mx, 2));
            x0.x = __expf(x0.x - mx); x0.y = __expf(x0.y - mx); x0.z = __expf(x0.z - mx); x0.w = __expf(x0.w - mx);
            x1.x = __expf(x1.x - mx); x1.y = __expf(x1.y - mx); x1.z = __expf(x1.z - mx); x1.w = __expf(x1.w - mx);
            x2.x = __expf(x2.x - mx); x2.y = __expf(x2.y - mx); x2.z = __expf(x2.z - mx); x2.w = __expf(x2.w - mx);
            x3.x = __expf(x3.x - mx); x3.y = __expf(x3.y - mx); x3.z = __expf(x3.z - mx); x3.w = __expf(x3.w - mx);
            unsigned long long* pd = &Pd[r * 66 + q * 16];
            pd[0]  = pack2(x0.x); pd[1]  = pack2(x0.y); pd[2]  = pack2(x0.z); pd[3]  = pack2(x0.w);
            pd[4]  = pack2(x1.x); pd[5]  = pack2(x1.y); pd[6]  = pack2(x1.z); pd[7]  = pack2(x1.w);
            pd[8]  = pack2(x2.x); pd[9]  = pack2(x2.y); pd[10] = pack2(x2.z); pd[11] = pack2(x2.w);
            pd[12] = pack2(x3.x); pd[13] = pack2(x3.y); pd[14] = pack2(x3.z); pd[15] = pack2(x3.w);
            float sum = (x0.x + x0.y + x0.z + x0.w) + (x1.x + x1.y + x1.z + x1.w)
                      + (x2.x + x2.y + x2.z + x2.w) + (x3.x + x3.y + x3.z + x3.w);
            sum += __shfl_xor_sync(0xffffffffu, sum, 1);
            sum += __shfl_xor_sync(0xffffffffu, sum, 2);
            if (q == 0) {
                float al = __expf(mold - mx);
                mrow[r] = mx;
                lrow[r] = lrow[r] * al + sum;
                arow[r] = al;
            }
        }
        __syncthreads();

        // ---- O = O*alpha + P V (f32x2, P from duplicated pairs) ----
        unsigned long long al2[4];
#pragma unroll
        for (int i = 0; i < 4; i++) al2[i] = pack2(arow[ty * 4 + i]);
#pragma unroll
        for (int i = 0; i < 4; i++)
#pragma unroll
            for (int j = 0; j < 4; j++) mul2(oacc2[i][j], al2[i]);

#pragma unroll 4
        for (int kk = 0; kk < 64; kk++) {
            unsigned long long p0 = Pd[(ty * 4 + 0) * 66 + kk];
            unsigned long long p1 = Pd[(ty * 4 + 1) * 66 + kk];
            unsigned long long p2 = Pd[(ty * 4 + 2) * 66 + kk];
            unsigned long long p3 = Pd[(ty * 4 + 3) * 66 + kk];
            ulonglong2 v0 = *(const ulonglong2*)&Vs[kk * 132 + tx * 8];
            ulonglong2 v1 = *(const ulonglong2*)&Vs[kk * 132 + tx * 8 + 4];
            fma2(oacc2[0][0], p0, v0.x); fma2(oacc2[0][1], p0, v0.y); fma2(oacc2[0][2], p0, v1.x); fma2(oacc2[0][3], p0, v1.y);
            fma2(oacc2[1][0], p1, v0.x); fma2(oacc2[1][1], p1, v0.y); fma2(oacc2[1][2], p1, v1.x); fma2(oacc2[1][3], p1, v1.y);
            fma2(oacc2[2][0], p2, v0.x); fma2(oacc2[2][1], p2, v0.y); fma2(oacc2[2][2], p2, v1.x); fma2(oacc2[2][3], p2, v1.y);
            fma2(oacc2[3][0], p3, v0.x); fma2(oacc2[3][1], p3, v0.y); fma2(oacc2[3][2], p3, v1.x); fma2(oacc2[3][3], p3, v1.y);
        }
    }

    // ---- normalize + write ----
#pragma unroll
    for (int i = 0; i < 4; i++) {
        float li = 1.0f / lrow[ty * 4 + i];
        size_t base = (size_t)(b * S_LEN + qt * 64 + ty * 4 + i) * DIM + h * HD + tx * 8;
#pragma unroll
        for (int j = 0; j < 4; j++) {
            float2 v = unpack2(oacc2[i][j]);
            O[base + j * 2 + 0] = v.x * li;
            O[base + j * 2 + 1] = v.y * li;
        }
    }
}

// =====================================================================
// launch
// =====================================================================
extern "C" void kernel_launch(void* const* d_in, const int* in_sizes, int n_in,
                              void* d_out, int out_size) {
    (void)in_sizes; (void)n_in; (void)out_size;
    const float* x    = (const float*)d_in[0];
    const float* cosT = (const float*)d_in[1];
    const float* sinT = (const float*)d_in[2];
    const float* wq   = (const float*)d_in[3];
    const float* wk   = (const float*)d_in[4];
    const float* wv   = (const float*)d_in[5];
    const float* wo   = (const float*)d_in[6];
    float* out = (float*)d_out;

    float *pqkv, *po;
    cudaGetSymbolAddress((void**)&pqkv, g_qkv);
    cudaGetSymbolAddress((void**)&po, g_o);
    __half *xh, *oh, *wf, *wo2;
    cudaGetSymbolAddress((void**)&xh, g_xh);
    cudaGetSymbolAddress((void**)&oh, g_oh);
    cudaGetSymbolAddress((void**)&wf, g_wf);
    cudaGetSymbolAddress((void**)&wo2, g_wo2);

    cudaFuncSetAttribute(flash_kernel, cudaFuncAttributeMaxDynamicSharedMemorySize, FLASH_SMEM_BYTES);
    cudaFuncSetAttribute(gemm_f16, cudaFuncAttributeMaxDynamicSharedMemorySize, GEMM_SMEM_BYTES);

    // weights -> fused fp16 buffer [wq | wk | wv], wo -> fp16, x -> fp16
    {
        int n4 = DIM * DIM / 4;
        tofp16_kernel<<<(n4 + 255) / 256, 256>>>(wq, wf, n4);
        tofp16_kernel<<<(n4 + 255) / 256, 256>>>(wo, wo2, n4);
        int m4 = KVD * DIM / 4;
        tofp16_kernel<<<(m4 + 255) / 256, 256>>>(wk, wf + (size_t)DIM * DIM, m4);
        tofp16_kernel<<<(m4 + 255) / 256, 256>>>(wv, wf + (size_t)(DIM + KVD) * DIM, m4);
        int x4 = MTOT * DIM / 4;
        tofp16_kernel<<<(x4 + 255) / 256, 256>>>(x, xh, x4);
    }

    // fused QKV projection
    gemm_f16<<<dim3(QKVN / 128, MTOT / 128), 256, GEMM_SMEM_BYTES>>>(xh, wf, pqkv, QKVN, DIM);

    // RoPE on Q and K regions of fused buffer
    {
        int qp = MTOT * NH * (HD / 2);
        rope_kernel<<<(qp + 255) / 256, 256>>>(pqkv, cosT, sinT, NH, QKVN, qp);
        int kp = MTOT * NKV * (HD / 2);
        rope_kernel<<<(kp + 255) / 256, 256>>>(pqkv + DIM, cosT, sinT, NKV, QKVN, kp);
    }

    // attention
    flash_kernel<<<dim3(S_LEN / 64, NH, B_SZ), 256, FLASH_SMEM_BYTES>>>(pqkv, po);

    // output projection
    {
        int n4 = MTOT * DIM / 4;
        tofp16_kernel<<<(n4 + 255) / 256, 256>>>(po, oh, n4);
    }
    gemm_f16<<<dim3(DIM / 128, MTOT / 128), 256, GEMM_SMEM_BYTES>>>(oh, wo2, out, DIM, DIM);
}

// round 6
// speedup vs baseline: 6.7711x; 2.9439x over previous
#include <cuda_runtime.h>
#include <cuda_fp16.h>
#include <math.h>
#include <stdint.h>

#define B_SZ  8
#define S_LEN 1024
#define NH    16
#define NKV   4
#define HD    128
#define DIM   2048
#define MTOT  (B_SZ * S_LEN)   // 8192
#define KVD   (NKV * HD)       // 512
#define QKVN  (DIM + 2 * KVD)  // 3072

// ---------------- static scratch (allocation-free) ----------------
__device__ float  g_qkv[(size_t)MTOT * QKVN];    // fused Q|K|V fp32 (rope target)
__device__ __half g_qkvh[(size_t)MTOT * QKVN];   // fused Q|K|V fp16 (flash input)
__device__ __half g_xh[(size_t)MTOT * DIM];      // x fp16
__device__ __half g_oh[(size_t)MTOT * DIM];      // attn out fp16
__device__ __half g_wf[(size_t)QKVN * DIM];      // fused wq|wk|wv fp16
__device__ __half g_wo2[(size_t)DIM * DIM];      // wo fp16

// ---------------- helpers ----------------
__device__ __forceinline__ uint32_t smem_u32(const void* p) {
    uint32_t a;
    asm("{ .reg .u64 t; cvta.to.shared.u64 t, %1; cvt.u32.u64 %0, t; }" : "=r"(a) : "l"(p));
    return a;
}

__device__ __forceinline__ void ldsm_x4(uint32_t* r, uint32_t addr) {
    asm volatile("ldmatrix.sync.aligned.m8n8.x4.shared.b16 {%0,%1,%2,%3}, [%4];"
        : "=r"(r[0]), "=r"(r[1]), "=r"(r[2]), "=r"(r[3]) : "r"(addr));
}
__device__ __forceinline__ void ldsm_x4_trans(uint32_t* r, uint32_t addr) {
    asm volatile("ldmatrix.sync.aligned.m8n8.x4.trans.shared.b16 {%0,%1,%2,%3}, [%4];"
        : "=r"(r[0]), "=r"(r[1]), "=r"(r[2]), "=r"(r[3]) : "r"(addr));
}

__device__ __forceinline__ void mma16816(float* d, const uint32_t* a, const uint32_t* b) {
    asm volatile("mma.sync.aligned.m16n8k16.row.col.f32.f16.f16.f32 "
        "{%0,%1,%2,%3}, {%4,%5,%6,%7}, {%8,%9}, {%0,%1,%2,%3};"
        : "+f"(d[0]), "+f"(d[1]), "+f"(d[2]), "+f"(d[3])
        : "r"(a[0]), "r"(a[1]), "r"(a[2]), "r"(a[3]), "r"(b[0]), "r"(b[1]));
}

__device__ __forceinline__ uint32_t packh2(float lo, float hi) {
    __half2 h = __floats2half2_rn(lo, hi);
    return *(uint32_t*)&h;
}

// =====================================================================
// convert fp32 -> fp16
// =====================================================================
__global__ void tofp16_kernel(const float* __restrict__ in, __half* __restrict__ out, int n4) {
    int i = blockIdx.x * 256 + threadIdx.x;
    if (i >= n4) return;
    float4 v = ((const float4*)in)[i];
    __half2* op = (__half2*)out;
    op[i * 2 + 0] = __floats2half2_rn(v.x, v.y);
    op[i * 2 + 1] = __floats2half2_rn(v.z, v.w);
}

// =====================================================================
// GEMM via mma.sync fp16 single-pass: C[M,N] = A @ B^T, fp32 accum
// tile 128x128, BK=32, 256 threads (8 warps, warp tile 32x64).
// smem: 4 stages x 2 tiles (A,B) x 128x40 halves = 81920 B
// =====================================================================
#define TILE_B   10240
#define STAGE_B  (2 * TILE_B)
#define GEMM_SMEM_BYTES (4 * STAGE_B)

__device__ __forceinline__ void gemm_load_chunk(
    const __half* __restrict__ A, const __half* __restrict__ B,
    int bm, int bn, int K, int kc, uint32_t stbase, int tid) {
#pragma unroll
    for (int t = 0; t < 4; t++) {
        const int tile = t >> 1;                  // 0:A 1:B (compile-time)
        const int rem  = tid + (t & 1) * 256;     // 0..511
        const int row  = rem >> 2;
        const int c    = rem & 3;
        const __half* base = (tile == 0) ? A : B;
        const int grow = ((tile == 0) ? bm : bn) + row;
        const void* g = base + (size_t)grow * K + kc * 32 + c * 8;
        uint32_t dst = stbase + (uint32_t)tile * TILE_B + (uint32_t)(row * 80 + c * 16);
        asm volatile("cp.async.cg.shared.global [%0], [%1], 16;" :: "r"(dst), "l"(g) : "memory");
    }
    asm volatile("cp.async.commit_group;" ::: "memory");
}

__global__ __launch_bounds__(256, 2)
void gemm_f16(const __half* __restrict__ A, const __half* __restrict__ B,
              float* __restrict__ C, int N, int K) {
    extern __shared__ char smem_raw[];
    const uint32_t sbase = smem_u32(smem_raw);

    const int tid  = threadIdx.x;
    const int wid  = tid >> 5;
    const int lane = tid & 31;
    const int warp_m = wid & 3;
    const int warp_n = wid >> 2;
    const int bm = blockIdx.y * 128;
    const int bn = blockIdx.x * 128;

    float acc[2][8][4];
#pragma unroll
    for (int i = 0; i < 2; i++)
#pragma unroll
        for (int j = 0; j < 8; j++)
#pragma unroll
            for (int v = 0; v < 4; v++) acc[i][j][v] = 0.0f;

    const uint32_t a_row = (uint32_t)(warp_m * 32 + (lane & 15));
    const uint32_t a_off = a_row * 80u + (uint32_t)((lane >> 4) * 16);
    const uint32_t b_row = (uint32_t)(warp_n * 64 + (lane & 7) + ((lane >> 4) & 1) * 8);
    const uint32_t b_off = b_row * 80u + (uint32_t)(((lane >> 3) & 1) * 16);

    const int NCHUNK = K >> 5;

    gemm_load_chunk(A, B, bm, bn, K, 0, sbase + 0u * STAGE_B, tid);
    gemm_load_chunk(A, B, bm, bn, K, 1, sbase + 1u * STAGE_B, tid);
    gemm_load_chunk(A, B, bm, bn, K, 2, sbase + 2u * STAGE_B, tid);

    for (int c = 0; c < NCHUNK; c++) {
        if (c + 2 < NCHUNK)      asm volatile("cp.async.wait_group 2;" ::: "memory");
        else if (c + 1 < NCHUNK) asm volatile("cp.async.wait_group 1;" ::: "memory");
        else                     asm volatile("cp.async.wait_group 0;" ::: "memory");
        __syncthreads();

        if (c + 3 < NCHUNK)
            gemm_load_chunk(A, B, bm, bn, K, c + 3,
                            sbase + (uint32_t)((c + 3) & 3) * STAGE_B, tid);

        const uint32_t stage = (uint32_t)(c & 3) * STAGE_B;
#pragma unroll
        for (int ks = 0; ks < 2; ks++) {
            const uint32_t aa = sbase + stage + a_off + (uint32_t)ks * 32u;
            const uint32_t bb = sbase + stage + TILE_B + b_off + (uint32_t)ks * 32u;
            uint32_t bfrag[4][4];
#pragma unroll
            for (int nb = 0; nb < 4; nb++)
                ldsm_x4(bfrag[nb], bb + (uint32_t)nb * 16u * 80u);
            uint32_t af[2][4];
            ldsm_x4(af[0], aa);
            ldsm_x4(af[1], aa + 16u * 80u);
#pragma unroll
            for (int mt = 0; mt < 2; mt++)
#pragma unroll
                for (int nb = 0; nb < 4; nb++) {
                    mma16816(acc[mt][nb * 2 + 0], af[mt], &bfrag[nb][0]);
                    mma16816(acc[mt][nb * 2 + 1], af[mt], &bfrag[nb][2]);
                }
        }
    }

    const int crow = lane >> 2;
    const int ccol = (lane & 3) * 2;
#pragma unroll
    for (int mt = 0; mt < 2; mt++) {
#pragma unroll
        for (int nt = 0; nt < 8; nt++) {
            const int row = bm + warp_m * 32 + mt * 16 + crow;
            const int col = bn + warp_n * 64 + nt * 8 + ccol;
            *(float2*)&C[(size_t)row * N + col]       = make_float2(acc[mt][nt][0], acc[mt][nt][1]);
            *(float2*)&C[(size_t)(row + 8) * N + col] = make_float2(acc[mt][nt][2], acc[mt][nt][3]);
        }
    }
}

// =====================================================================
// RoPE (in place, strided rows)
// =====================================================================
__global__ void rope_kernel(float* __restrict__ t,
                            const float* __restrict__ cosT,
                            const float* __restrict__ sinT,
                            int nheads, int ld, int total_pairs) {
    int idx = blockIdx.x * 256 + threadIdx.x;
    if (idx >= total_pairs) return;
    int j     = idx & 63;
    int grp   = idx >> 6;
    int h     = grp % nheads;
    int token = grp / nheads;
    int s     = token % S_LEN;
    float c  = cosT[s * 64 + j];
    float sn = sinT[s * 64 + j];
    float* p = t + (size_t)token * ld + h * HD + j * 2;
    float2 v = *(float2*)p;
    float2 o;
    o.x = v.x * c - v.y * sn;
    o.y = v.x * sn + v.y * c;
    *(float2*)p = o;
}

// =====================================================================
// Tensor-core flash attention (causal, GQA).
// BM=BN=64, D=128, 128 threads (4 warps, each owns 16 q-rows).
// Q/K/V fp16 in smem stride 136 halves; K/V double-buffered cp.async.
// =====================================================================
#define FLA_TILE_B  (64 * 136 * 2)                 // 17408 B
#define FLASH_SMEM_BYTES (5 * FLA_TILE_B)          // Q + 2*K + 2*V = 87040

__device__ __forceinline__ void fla_load_tile(const __half* src, uint32_t dst, int tid) {
#pragma unroll
    for (int i = 0; i < 8; i++) {
        int s = tid + i * 128;
        int row = s >> 4, seg = s & 15;
        const void* g = src + (size_t)row * QKVN + seg * 8;
        asm volatile("cp.async.cg.shared.global [%0], [%1], 16;"
            :: "r"(dst + (uint32_t)(row * 272 + seg * 16)), "l"(g) : "memory");
    }
}

__global__ __launch_bounds__(128)
void flash_mma(const __half* __restrict__ QKVh, __half* __restrict__ Oh) {
    const int qt = blockIdx.x;
    const int h  = blockIdx.y;
    const int b  = blockIdx.z;
    const int g  = h >> 2;

    extern __shared__ char smraw[];
    const uint32_t sQ = smem_u32(smraw);
    const uint32_t sK = sQ + FLA_TILE_B;
    const uint32_t sV = sK + 2 * FLA_TILE_B;

    const int tid  = threadIdx.x;
    const int wid  = tid >> 5;
    const int lane = tid & 31;

    // initial loads: Q + K0 + V0 (one commit group)
    {
        const __half* qsrc = QKVh + (size_t)(b * S_LEN + qt * 64) * QKVN + h * HD;
        fla_load_tile(qsrc, sQ, tid);
        const __half* ksrc = QKVh + (size_t)(b * S_LEN) * QKVN + DIM + g * HD;
        fla_load_tile(ksrc, sK, tid);
        fla_load_tile(ksrc + KVD, sV, tid);
        asm volatile("cp.async.commit_group;" ::: "memory");
    }

    // per-warp fragment addressing
    const uint32_t a_base = sQ + (uint32_t)((wid * 16 + (lane & 15)) * 272 + (lane >> 4) * 16);
    const uint32_t kb_off = (uint32_t)(((lane & 7) + ((lane >> 4) & 1) * 8) * 272 + ((lane >> 3) & 1) * 16);
    const uint32_t vb_off = (uint32_t)(((lane & 7) + ((lane >> 3) & 1) * 8) * 272 + ((lane >> 4) & 1) * 16);

    float o[16][4];
#pragma unroll
    for (int j = 0; j < 16; j++)
#pragma unroll
        for (int v = 0; v < 4; v++) o[j][v] = 0.0f;
    float m0 = -INFINITY, m1 = -INFINITY, l0 = 0.0f, l1 = 0.0f;

    asm volatile("cp.async.wait_group 0;" ::: "memory");
    __syncthreads();

    // hoist Q fragments (8 k16-steps)
    uint32_t qa[8][4];
#pragma unroll
    for (int ks = 0; ks < 8; ks++) ldsm_x4(qa[ks], a_base + (uint32_t)ks * 32u);

    const float scale = 0.08838834764831845f;  // 1/sqrt(128)
    const int rb0 = wid * 16 + (lane >> 2);
    const int rb1 = rb0 + 8;
    const int cb  = (lane & 3) * 2;

    for (int jt = 0; jt <= qt; jt++) {
        const uint32_t buf = (uint32_t)(jt & 1) * FLA_TILE_B;
        if (jt > 0) {
            asm volatile("cp.async.wait_group 0;" ::: "memory");
            __syncthreads();
        }
        if (jt < qt) {
            const __half* ksrc = QKVh + (size_t)(b * S_LEN + (jt + 1) * 64) * QKVN + DIM + g * HD;
            const uint32_t nbuf = (uint32_t)((jt + 1) & 1) * FLA_TILE_B;
            fla_load_tile(ksrc, sK + nbuf, tid);
            fla_load_tile(ksrc + KVD, sV + nbuf, tid);
            asm volatile("cp.async.commit_group;" ::: "memory");
        }

        // ---- S = Q K^T : m16 x n64 x k128 per warp ----
        float s[8][4];
#pragma unroll
        for (int j = 0; j < 8; j++)
#pragma unroll
            for (int v = 0; v < 4; v++) s[j][v] = 0.0f;

#pragma unroll
        for (int ks = 0; ks < 8; ks++) {
            const uint32_t bb = sK + buf + kb_off + (uint32_t)ks * 32u;
#pragma unroll
            for (int nb = 0; nb < 4; nb++) {
                uint32_t bf[4];
                ldsm_x4(bf, bb + (uint32_t)nb * (16u * 272u));
                mma16816(s[nb * 2 + 0], qa[ks], &bf[0]);
                mma16816(s[nb * 2 + 1], qa[ks], &bf[2]);
            }
        }

        // scale + causal mask
#pragma unroll
        for (int j = 0; j < 8; j++) {
            s[j][0] *= scale; s[j][1] *= scale; s[j][2] *= scale; s[j][3] *= scale;
        }
        if (jt == qt) {
#pragma unroll
            for (int j = 0; j < 8; j++) {
                const int c0 = j * 8 + cb;
                if (c0 > rb0)     s[j][0] = -1e30f;
                if (c0 + 1 > rb0) s[j][1] = -1e30f;
                if (c0 > rb1)     s[j][2] = -1e30f;
                if (c0 + 1 > rb1) s[j][3] = -1e30f;
            }
        }

        // ---- online softmax (2 rows per lane, quad reduce) ----
        float mx0 = -INFINITY, mx1 = -INFINITY;
#pragma unroll
        for (int j = 0; j < 8; j++) {
            mx0 = fmaxf(mx0, fmaxf(s[j][0], s[j][1]));
            mx1 = fmaxf(mx1, fmaxf(s[j][2], s[j][3]));
        }
        mx0 = fmaxf(mx0, __shfl_xor_sync(0xffffffffu, mx0, 1));
        mx0 = fmaxf(mx0, __shfl_xor_sync(0xffffffffu, mx0, 2));
        mx1 = fmaxf(mx1, __shfl_xor_sync(0xffffffffu, mx1, 1));
        mx1 = fmaxf(mx1, __shfl_xor_sync(0xffffffffu, mx1, 2));
        const float mn0 = fmaxf(m0, mx0);
        const float mn1 = fmaxf(m1, mx1);
        const float al0 = __expf(m0 - mn0);
        const float al1 = __expf(m1 - mn1);
        m0 = mn0; m1 = mn1;

        float sum0 = 0.0f, sum1 = 0.0f;
#pragma unroll
        for (int j = 0; j < 8; j++) {
            s[j][0] = __expf(s[j][0] - mn0);
            s[j][1] = __expf(s[j][1] - mn0);
            s[j][2] = __expf(s[j][2] - mn1);
            s[j][3] = __expf(s[j][3] - mn1);
            sum0 += s[j][0] + s[j][1];
            sum1 += s[j][2] + s[j][3];
        }
        sum0 += __shfl_xor_sync(0xffffffffu, sum0, 1);
        sum0 += __shfl_xor_sync(0xffffffffu, sum0, 2);
        sum1 += __shfl_xor_sync(0xffffffffu, sum1, 1);
        sum1 += __shfl_xor_sync(0xffffffffu, sum1, 2);
        l0 = l0 * al0 + sum0;
        l1 = l1 * al1 + sum1;

#pragma unroll
        for (int j = 0; j < 16; j++) {
            o[j][0] *= al0; o[j][1] *= al0; o[j][2] *= al1; o[j][3] *= al1;
        }

        // ---- O += P V : m16 x n128 x k64 ----
#pragma unroll
        for (int ksp = 0; ksp < 4; ksp++) {
            uint32_t pa[4];
            pa[0] = packh2(s[2 * ksp][0],     s[2 * ksp][1]);
            pa[1] = packh2(s[2 * ksp][2],     s[2 * ksp][3]);
            pa[2] = packh2(s[2 * ksp + 1][0], s[2 * ksp + 1][1]);
            pa[3] = packh2(s[2 * ksp + 1][2], s[2 * ksp + 1][3]);
            const uint32_t vb = sV + buf + vb_off + (uint32_t)ksp * (16u * 272u);
#pragma unroll
            for (int nb = 0; nb < 8; nb++) {
                uint32_t bf[4];
                ldsm_x4_trans(bf, vb + (uint32_t)nb * 32u);
                mma16816(o[nb * 2 + 0], pa, &bf[0]);
                mma16816(o[nb * 2 + 1], pa, &bf[2]);
            }
        }
    }

    // ---- normalize + write fp16 ----
    const float inv0 = 1.0f / l0;
    const float inv1 = 1.0f / l1;
    const size_t row0 = (size_t)(b * S_LEN + qt * 64 + rb0);
    const size_t row1 = row0 + 8;
#pragma unroll
    for (int j = 0; j < 16; j++) {
        const int col = h * HD + j * 8 + cb;
        uint32_t p0 = packh2(o[j][0] * inv0, o[j][1] * inv0);
        uint32_t p1 = packh2(o[j][2] * inv1, o[j][3] * inv1);
        *(uint32_t*)&Oh[row0 * DIM + col] = p0;
        *(uint32_t*)&Oh[row1 * DIM + col] = p1;
    }
}

// =====================================================================
// launch
// =====================================================================
extern "C" void kernel_launch(void* const* d_in, const int* in_sizes, int n_in,
                              void* d_out, int out_size) {
    (void)in_sizes; (void)n_in; (void)out_size;
    const float* x    = (const float*)d_in[0];
    const float* cosT = (const float*)d_in[1];
    const float* sinT = (const float*)d_in[2];
    const float* wq   = (const float*)d_in[3];
    const float* wk   = (const float*)d_in[4];
    const float* wv   = (const float*)d_in[5];
    const float* wo   = (const float*)d_in[6];
    float* out = (float*)d_out;

    float* pqkv;
    cudaGetSymbolAddress((void**)&pqkv, g_qkv);
    __half *pqkvh, *xh, *oh, *wf, *wo2;
    cudaGetSymbolAddress((void**)&pqkvh, g_qkvh);
    cudaGetSymbolAddress((void**)&xh, g_xh);
    cudaGetSymbolAddress((void**)&oh, g_oh);
    cudaGetSymbolAddress((void**)&wf, g_wf);
    cudaGetSymbolAddress((void**)&wo2, g_wo2);

    cudaFuncSetAttribute(flash_mma, cudaFuncAttributeMaxDynamicSharedMemorySize, FLASH_SMEM_BYTES);
    cudaFuncSetAttribute(gemm_f16, cudaFuncAttributeMaxDynamicSharedMemorySize, GEMM_SMEM_BYTES);

    // converts: weights -> fused fp16 [wq|wk|wv], wo -> fp16, x -> fp16
    {
        int n4 = DIM * DIM / 4;
        tofp16_kernel<<<(n4 + 255) / 256, 256>>>(wq, wf, n4);
        tofp16_kernel<<<(n4 + 255) / 256, 256>>>(wo, wo2, n4);
        int m4 = KVD * DIM / 4;
        tofp16_kernel<<<(m4 + 255) / 256, 256>>>(wk, wf + (size_t)DIM * DIM, m4);
        tofp16_kernel<<<(m4 + 255) / 256, 256>>>(wv, wf + (size_t)(DIM + KVD) * DIM, m4);
        int x4 = MTOT * DIM / 4;
        tofp16_kernel<<<(x4 + 255) / 256, 256>>>(x, xh, x4);
    }

    // fused QKV projection (fp32 out)
    gemm_f16<<<dim3(QKVN / 128, MTOT / 128), 256, GEMM_SMEM_BYTES>>>(xh, wf, pqkv, QKVN, DIM);

    // RoPE on Q and K regions
    {
        int qp = MTOT * NH * (HD / 2);
        rope_kernel<<<(qp + 255) / 256, 256>>>(pqkv, cosT, sinT, NH, QKVN, qp);
        int kp = MTOT * NKV * (HD / 2);
        rope_kernel<<<(kp + 255) / 256, 256>>>(pqkv + DIM, cosT, sinT, NKV, QKVN, kp);
    }

    // QKV -> fp16 for tensor-core flash
    {
        int n4 = MTOT * QKVN / 4;
        tofp16_kernel<<<(n4 + 255) / 256, 256>>>(pqkv, (__half*)pqkvh, n4);
    }

    // tensor-core flash attention (writes fp16 O directly)
    flash_mma<<<dim3(S_LEN / 64, NH, B_SZ), 128, FLASH_SMEM_BYTES>>>(pqkvh, oh);

    // output projection
    gemm_f16<<<dim3(DIM / 128, MTOT / 128), 256, GEMM_SMEM_BYTES>>>(oh, wo2, out, DIM, DIM);
}

// round 7
// speedup vs baseline: 7.1902x; 1.0619x over previous
#include <cuda_runtime.h>
#include <cuda_fp16.h>
#include <math.h>
#include <stdint.h>

#define B_SZ  8
#define S_LEN 1024
#define NH    16
#define NKV   4
#define HD    128
#define DIM   2048
#define MTOT  (B_SZ * S_LEN)   // 8192
#define KVD   (NKV * HD)       // 512
#define QKVN  (DIM + 2 * KVD)  // 3072
#define QKEND (DIM + KVD)      // 2560: cols < this get RoPE

// ---------------- static scratch (allocation-free) ----------------
__device__ __half g_qkvh[(size_t)MTOT * QKVN];   // fused Q|K|V fp16 (rope applied)
__device__ __half g_xh[(size_t)MTOT * DIM];      // x fp16
__device__ __half g_oh[(size_t)MTOT * DIM];      // attn out fp16
__device__ __half g_wf[(size_t)QKVN * DIM];      // fused wq|wk|wv fp16
__device__ __half g_wo2[(size_t)DIM * DIM];      // wo fp16

// ---------------- helpers ----------------
__device__ __forceinline__ uint32_t smem_u32(const void* p) {
    uint32_t a;
    asm("{ .reg .u64 t; cvta.to.shared.u64 t, %1; cvt.u32.u64 %0, t; }" : "=r"(a) : "l"(p));
    return a;
}

__device__ __forceinline__ void ldsm_x4(uint32_t* r, uint32_t addr) {
    asm volatile("ldmatrix.sync.aligned.m8n8.x4.shared.b16 {%0,%1,%2,%3}, [%4];"
        : "=r"(r[0]), "=r"(r[1]), "=r"(r[2]), "=r"(r[3]) : "r"(addr));
}
__device__ __forceinline__ void ldsm_x4_trans(uint32_t* r, uint32_t addr) {
    asm volatile("ldmatrix.sync.aligned.m8n8.x4.trans.shared.b16 {%0,%1,%2,%3}, [%4];"
        : "=r"(r[0]), "=r"(r[1]), "=r"(r[2]), "=r"(r[3]) : "r"(addr));
}

__device__ __forceinline__ void mma16816(float* d, const uint32_t* a, const uint32_t* b) {
    asm volatile("mma.sync.aligned.m16n8k16.row.col.f32.f16.f16.f32 "
        "{%0,%1,%2,%3}, {%4,%5,%6,%7}, {%8,%9}, {%0,%1,%2,%3};"
        : "+f"(d[0]), "+f"(d[1]), "+f"(d[2]), "+f"(d[3])
        : "r"(a[0]), "r"(a[1]), "r"(a[2]), "r"(a[3]), "r"(b[0]), "r"(b[1]));
}

__device__ __forceinline__ uint32_t packh2(float lo, float hi) {
    __half2 h = __floats2half2_rn(lo, hi);
    return *(uint32_t*)&h;
}

// =====================================================================
// convert fp32 -> fp16
// =====================================================================
__global__ void tofp16_kernel(const float* __restrict__ in, __half* __restrict__ out, int n4) {
    int i = blockIdx.x * 256 + threadIdx.x;
    if (i >= n4) return;
    float4 v = ((const float4*)in)[i];
    __half2* op = (__half2*)out;
    op[i * 2 + 0] = __floats2half2_rn(v.x, v.y);
    op[i * 2 + 1] = __floats2half2_rn(v.z, v.w);
}

// =====================================================================
// GEMM via mma.sync fp16: C[M,N] = A @ B^T, fp32 accum.
// tile 128x128, BK=32, 256 threads (8 warps, warp tile 32x64),
// 4-stage cp.async pipeline.
// Epilogue variants:
//   ROPE_F16=false: write fp32 C
//   ROPE_F16=true : apply RoPE to cols < QKEND, write fp16 C
// =====================================================================
#define TILE_B   10240
#define STAGE_B  (2 * TILE_B)
#define GEMM_SMEM_BYTES (4 * STAGE_B)

__device__ __forceinline__ void gemm_load_chunk(
    const __half* __restrict__ A, const __half* __restrict__ B,
    int bm, int bn, int K, int kc, uint32_t stbase, int tid) {
#pragma unroll
    for (int t = 0; t < 4; t++) {
        const int tile = t >> 1;                  // 0:A 1:B (compile-time)
        const int rem  = tid + (t & 1) * 256;     // 0..511
        const int row  = rem >> 2;
        const int c    = rem & 3;
        const __half* base = (tile == 0) ? A : B;
        const int grow = ((tile == 0) ? bm : bn) + row;
        const void* g = base + (size_t)grow * K + kc * 32 + c * 8;
        uint32_t dst = stbase + (uint32_t)tile * TILE_B + (uint32_t)(row * 80 + c * 16);
        asm volatile("cp.async.cg.shared.global [%0], [%1], 16;" :: "r"(dst), "l"(g) : "memory");
    }
    asm volatile("cp.async.commit_group;" ::: "memory");
}

template <bool ROPE_F16>
__global__ __launch_bounds__(256, 2)
void gemm_f16(const __half* __restrict__ A, const __half* __restrict__ B,
              void* __restrict__ Cout, int N, int K,
              const float* __restrict__ cosT, const float* __restrict__ sinT) {
    extern __shared__ char smem_raw[];
    const uint32_t sbase = smem_u32(smem_raw);

    const int tid  = threadIdx.x;
    const int wid  = tid >> 5;
    const int lane = tid & 31;
    const int warp_m = wid & 3;
    const int warp_n = wid >> 2;
    const int bm = blockIdx.y * 128;
    const int bn = blockIdx.x * 128;

    float acc[2][8][4];
#pragma unroll
    for (int i = 0; i < 2; i++)
#pragma unroll
        for (int j = 0; j < 8; j++)
#pragma unroll
            for (int v = 0; v < 4; v++) acc[i][j][v] = 0.0f;

    const uint32_t a_row = (uint32_t)(warp_m * 32 + (lane & 15));
    const uint32_t a_off = a_row * 80u + (uint32_t)((lane >> 4) * 16);
    const uint32_t b_row = (uint32_t)(warp_n * 64 + (lane & 7) + ((lane >> 4) & 1) * 8);
    const uint32_t b_off = b_row * 80u + (uint32_t)(((lane >> 3) & 1) * 16);

    const int NCHUNK = K >> 5;

    gemm_load_chunk(A, B, bm, bn, K, 0, sbase + 0u * STAGE_B, tid);
    gemm_load_chunk(A, B, bm, bn, K, 1, sbase + 1u * STAGE_B, tid);
    gemm_load_chunk(A, B, bm, bn, K, 2, sbase + 2u * STAGE_B, tid);

    for (int c = 0; c < NCHUNK; c++) {
        if (c + 2 < NCHUNK)      asm volatile("cp.async.wait_group 2;" ::: "memory");
        else if (c + 1 < NCHUNK) asm volatile("cp.async.wait_group 1;" ::: "memory");
        else                     asm volatile("cp.async.wait_group 0;" ::: "memory");
        __syncthreads();

        if (c + 3 < NCHUNK)
            gemm_load_chunk(A, B, bm, bn, K, c + 3,
                            sbase + (uint32_t)((c + 3) & 3) * STAGE_B, tid);

        const uint32_t stage = (uint32_t)(c & 3) * STAGE_B;
#pragma unroll
        for (int ks = 0; ks < 2; ks++) {
            const uint32_t aa = sbase + stage + a_off + (uint32_t)ks * 32u;
            const uint32_t bb = sbase + stage + TILE_B + b_off + (uint32_t)ks * 32u;
            uint32_t bfrag[4][4];
#pragma unroll
            for (int nb = 0; nb < 4; nb++)
                ldsm_x4(bfrag[nb], bb + (uint32_t)nb * 16u * 80u);
            uint32_t af[2][4];
            ldsm_x4(af[0], aa);
            ldsm_x4(af[1], aa + 16u * 80u);
#pragma unroll
            for (int mt = 0; mt < 2; mt++)
#pragma unroll
                for (int nb = 0; nb < 4; nb++) {
                    mma16816(acc[mt][nb * 2 + 0], af[mt], &bfrag[nb][0]);
                    mma16816(acc[mt][nb * 2 + 1], af[mt], &bfrag[nb][2]);
                }
        }
    }

    const int crow = lane >> 2;
    const int ccol = (lane & 3) * 2;
#pragma unroll
    for (int mt = 0; mt < 2; mt++) {
#pragma unroll
        for (int nt = 0; nt < 8; nt++) {
            const int row = bm + warp_m * 32 + mt * 16 + crow;
            const int col = bn + warp_n * 64 + nt * 8 + ccol;
            if (ROPE_F16) {
                float2 v0 = make_float2(acc[mt][nt][0], acc[mt][nt][1]);
                float2 v1 = make_float2(acc[mt][nt][2], acc[mt][nt][3]);
                if (col < QKEND) {
                    const int j  = (col & (HD - 1)) >> 1;
                    const int s0 = row & (S_LEN - 1);
                    const int s1 = (row + 8) & (S_LEN - 1);
                    float c0 = cosT[s0 * 64 + j], n0 = sinT[s0 * 64 + j];
                    float c1 = cosT[s1 * 64 + j], n1 = sinT[s1 * 64 + j];
                    v0 = make_float2(v0.x * c0 - v0.y * n0, v0.x * n0 + v0.y * c0);
                    v1 = make_float2(v1.x * c1 - v1.y * n1, v1.x * n1 + v1.y * c1);
                }
                __half* Ch = (__half*)Cout;
                *(uint32_t*)&Ch[(size_t)row * N + col]       = packh2(v0.x, v0.y);
                *(uint32_t*)&Ch[(size_t)(row + 8) * N + col] = packh2(v1.x, v1.y);
            } else {
                float* Cf = (float*)Cout;
                *(float2*)&Cf[(size_t)row * N + col]       = make_float2(acc[mt][nt][0], acc[mt][nt][1]);
                *(float2*)&Cf[(size_t)(row + 8) * N + col] = make_float2(acc[mt][nt][2], acc[mt][nt][3]);
            }
        }
    }
}

// =====================================================================
// Tensor-core flash attention (causal, GQA).
// BM=BN=64, D=128, 128 threads (4 warps, each owns 16 q-rows).
// Q/K/V fp16 in smem stride 136 halves; K/V double-buffered cp.async.
// =====================================================================
#define FLA_TILE_B  (64 * 136 * 2)                 // 17408 B
#define FLASH_SMEM_BYTES (5 * FLA_TILE_B)          // Q + 2*K + 2*V = 87040

__device__ __forceinline__ void fla_load_tile(const __half* src, uint32_t dst, int tid) {
#pragma unroll
    for (int i = 0; i < 8; i++) {
        int s = tid + i * 128;
        int row = s >> 4, seg = s & 15;
        const void* g = src + (size_t)row * QKVN + seg * 8;
        asm volatile("cp.async.cg.shared.global [%0], [%1], 16;"
            :: "r"(dst + (uint32_t)(row * 272 + seg * 16)), "l"(g) : "memory");
    }
}

__global__ __launch_bounds__(128)
void flash_mma(const __half* __restrict__ QKVh, __half* __restrict__ Oh) {
    const int qt = blockIdx.x;
    const int h  = blockIdx.y;
    const int b  = blockIdx.z;
    const int g  = h >> 2;

    extern __shared__ char smraw[];
    const uint32_t sQ = smem_u32(smraw);
    const uint32_t sK = sQ + FLA_TILE_B;
    const uint32_t sV = sK + 2 * FLA_TILE_B;

    const int tid  = threadIdx.x;
    const int wid  = tid >> 5;
    const int lane = tid & 31;

    {
        const __half* qsrc = QKVh + (size_t)(b * S_LEN + qt * 64) * QKVN + h * HD;
        fla_load_tile(qsrc, sQ, tid);
        const __half* ksrc = QKVh + (size_t)(b * S_LEN) * QKVN + DIM + g * HD;
        fla_load_tile(ksrc, sK, tid);
        fla_load_tile(ksrc + KVD, sV, tid);
        asm volatile("cp.async.commit_group;" ::: "memory");
    }

    const uint32_t a_base = sQ + (uint32_t)((wid * 16 + (lane & 15)) * 272 + (lane >> 4) * 16);
    const uint32_t kb_off = (uint32_t)(((lane & 7) + ((lane >> 4) & 1) * 8) * 272 + ((lane >> 3) & 1) * 16);
    const uint32_t vb_off = (uint32_t)(((lane & 7) + ((lane >> 3) & 1) * 8) * 272 + ((lane >> 4) & 1) * 16);

    float o[16][4];
#pragma unroll
    for (int j = 0; j < 16; j++)
#pragma unroll
        for (int v = 0; v < 4; v++) o[j][v] = 0.0f;
    float m0 = -INFINITY, m1 = -INFINITY, l0 = 0.0f, l1 = 0.0f;

    asm volatile("cp.async.wait_group 0;" ::: "memory");
    __syncthreads();

    uint32_t qa[8][4];
#pragma unroll
    for (int ks = 0; ks < 8; ks++) ldsm_x4(qa[ks], a_base + (uint32_t)ks * 32u);

    const float scale = 0.08838834764831845f;  // 1/sqrt(128)
    const int rb0 = wid * 16 + (lane >> 2);
    const int rb1 = rb0 + 8;
    const int cb  = (lane & 3) * 2;

    for (int jt = 0; jt <= qt; jt++) {
        const uint32_t buf = (uint32_t)(jt & 1) * FLA_TILE_B;
        if (jt > 0) {
            asm volatile("cp.async.wait_group 0;" ::: "memory");
            __syncthreads();
        }
        if (jt < qt) {
            const __half* ksrc = QKVh + (size_t)(b * S_LEN + (jt + 1) * 64) * QKVN + DIM + g * HD;
            const uint32_t nbuf = (uint32_t)((jt + 1) & 1) * FLA_TILE_B;
            fla_load_tile(ksrc, sK + nbuf, tid);
            fla_load_tile(ksrc + KVD, sV + nbuf, tid);
            asm volatile("cp.async.commit_group;" ::: "memory");
        }

        // ---- S = Q K^T ----
        float s[8][4];
#pragma unroll
        for (int j = 0; j < 8; j++)
#pragma unroll
            for (int v = 0; v < 4; v++) s[j][v] = 0.0f;

#pragma unroll
        for (int ks = 0; ks < 8; ks++) {
            const uint32_t bb = sK + buf + kb_off + (uint32_t)ks * 32u;
#pragma unroll
            for (int nb = 0; nb < 4; nb++) {
                uint32_t bf[4];
                ldsm_x4(bf, bb + (uint32_t)nb * (16u * 272u));
                mma16816(s[nb * 2 + 0], qa[ks], &bf[0]);
                mma16816(s[nb * 2 + 1], qa[ks], &bf[2]);
            }
        }

#pragma unroll
        for (int j = 0; j < 8; j++) {
            s[j][0] *= scale; s[j][1] *= scale; s[j][2] *= scale; s[j][3] *= scale;
        }
        if (jt == qt) {
#pragma unroll
            for (int j = 0; j < 8; j++) {
                const int c0 = j * 8 + cb;
                if (c0 > rb0)     s[j][0] = -1e30f;
                if (c0 + 1 > rb0) s[j][1] = -1e30f;
                if (c0 > rb1)     s[j][2] = -1e30f;
                if (c0 + 1 > rb1) s[j][3] = -1e30f;
            }
        }

        // ---- online softmax ----
        float mx0 = -INFINITY, mx1 = -INFINITY;
#pragma unroll
        for (int j = 0; j < 8; j++) {
            mx0 = fmaxf(mx0, fmaxf(s[j][0], s[j][1]));
            mx1 = fmaxf(mx1, fmaxf(s[j][2], s[j][3]));
        }
        mx0 = fmaxf(mx0, __shfl_xor_sync(0xffffffffu, mx0, 1));
        mx0 = fmaxf(mx0, __shfl_xor_sync(0xffffffffu, mx0, 2));
        mx1 = fmaxf(mx1, __shfl_xor_sync(0xffffffffu, mx1, 1));
        mx1 = fmaxf(mx1, __shfl_xor_sync(0xffffffffu, mx1, 2));
        const float mn0 = fmaxf(m0, mx0);
        const float mn1 = fmaxf(m1, mx1);
        const float al0 = __expf(m0 - mn0);
        const float al1 = __expf(m1 - mn1);
        m0 = mn0; m1 = mn1;

        float sum0 = 0.0f, sum1 = 0.0f;
#pragma unroll
        for (int j = 0; j < 8; j++) {
            s[j][0] = __expf(s[j][0] - mn0);
            s[j][1] = __expf(s[j][1] - mn0);
            s[j][2] = __expf(s[j][2] - mn1);
            s[j][3] = __expf(s[j][3] - mn1);
            sum0 += s[j][0] + s[j][1];
            sum1 += s[j][2] + s[j][3];
        }
        sum0 += __shfl_xor_sync(0xffffffffu, sum0, 1);
        sum0 += __shfl_xor_sync(0xffffffffu, sum0, 2);
        sum1 += __shfl_xor_sync(0xffffffffu, sum1, 1);
        sum1 += __shfl_xor_sync(0xffffffffu, sum1, 2);
        l0 = l0 * al0 + sum0;
        l1 = l1 * al1 + sum1;

#pragma unroll
        for (int j = 0; j < 16; j++) {
            o[j][0] *= al0; o[j][1] *= al0; o[j][2] *= al1; o[j][3] *= al1;
        }

        // ---- O += P V ----
#pragma unroll
        for (int ksp = 0; ksp < 4; ksp++) {
            uint32_t pa[4];
            pa[0] = packh2(s[2 * ksp][0],     s[2 * ksp][1]);
            pa[1] = packh2(s[2 * ksp][2],     s[2 * ksp][3]);
            pa[2] = packh2(s[2 * ksp + 1][0], s[2 * ksp + 1][1]);
            pa[3] = packh2(s[2 * ksp + 1][2], s[2 * ksp + 1][3]);
            const uint32_t vb = sV + buf + vb_off + (uint32_t)ksp * (16u * 272u);
#pragma unroll
            for (int nb = 0; nb < 8; nb++) {
                uint32_t bf[4];
                ldsm_x4_trans(bf, vb + (uint32_t)nb * 32u);
                mma16816(o[nb * 2 + 0], pa, &bf[0]);
                mma16816(o[nb * 2 + 1], pa, &bf[2]);
            }
        }
    }

    const float inv0 = 1.0f / l0;
    const float inv1 = 1.0f / l1;
    const size_t row0 = (size_t)(b * S_LEN + qt * 64 + rb0);
    const size_t row1 = row0 + 8;
#pragma unroll
    for (int j = 0; j < 16; j++) {
        const int col = h * HD + j * 8 + cb;
        uint32_t p0 = packh2(o[j][0] * inv0, o[j][1] * inv0);
        uint32_t p1 = packh2(o[j][2] * inv1, o[j][3] * inv1);
        *(uint32_t*)&Oh[row0 * DIM + col] = p0;
        *(uint32_t*)&Oh[row1 * DIM + col] = p1;
    }
}

// =====================================================================
// launch
// =====================================================================
extern "C" void kernel_launch(void* const* d_in, const int* in_sizes, int n_in,
                              void* d_out, int out_size) {
    (void)in_sizes; (void)n_in; (void)out_size;
    const float* x    = (const float*)d_in[0];
    const float* cosT = (const float*)d_in[1];
    const float* sinT = (const float*)d_in[2];
    const float* wq   = (const float*)d_in[3];
    const float* wk   = (const float*)d_in[4];
    const float* wv   = (const float*)d_in[5];
    const float* wo   = (const float*)d_in[6];
    float* out = (float*)d_out;

    __half *pqkvh, *xh, *oh, *wf, *wo2;
    cudaGetSymbolAddress((void**)&pqkvh, g_qkvh);
    cudaGetSymbolAddress((void**)&xh, g_xh);
    cudaGetSymbolAddress((void**)&oh, g_oh);
    cudaGetSymbolAddress((void**)&wf, g_wf);
    cudaGetSymbolAddress((void**)&wo2, g_wo2);

    cudaFuncSetAttribute(flash_mma, cudaFuncAttributeMaxDynamicSharedMemorySize, FLASH_SMEM_BYTES);
    cudaFuncSetAttribute(gemm_f16<true>,  cudaFuncAttributeMaxDynamicSharedMemorySize, GEMM_SMEM_BYTES);
    cudaFuncSetAttribute(gemm_f16<false>, cudaFuncAttributeMaxDynamicSharedMemorySize, GEMM_SMEM_BYTES);

    // converts: weights -> fused fp16 [wq|wk|wv], wo -> fp16, x -> fp16
    {
        int n4 = DIM * DIM / 4;
        tofp16_kernel<<<(n4 + 255) / 256, 256>>>(wq, wf, n4);
        tofp16_kernel<<<(n4 + 255) / 256, 256>>>(wo, wo2, n4);
        int m4 = KVD * DIM / 4;
        tofp16_kernel<<<(m4 + 255) / 256, 256>>>(wk, wf + (size_t)DIM * DIM, m4);
        tofp16_kernel<<<(m4 + 255) / 256, 256>>>(wv, wf + (size_t)(DIM + KVD) * DIM, m4);
        int x4 = MTOT * DIM / 4;
        tofp16_kernel<<<(x4 + 255) / 256, 256>>>(x, xh, x4);
    }

    // fused QKV projection with RoPE epilogue, fp16 out
    gemm_f16<true><<<dim3(QKVN / 128, MTOT / 128), 256, GEMM_SMEM_BYTES>>>(
        xh, wf, pqkvh, QKVN, DIM, cosT, sinT);

    // tensor-core flash attention (writes fp16 O directly)
    flash_mma<<<dim3(S_LEN / 64, NH, B_SZ), 128, FLASH_SMEM_BYTES>>>(pqkvh, oh);

    // output projection (fp32 out)
    gemm_f16<false><<<dim3(DIM / 128, MTOT / 128), 256, GEMM_SMEM_BYTES>>>(
        oh, wo2, out, DIM, DIM, nullptr, nullptr);
}

// round 8
// speedup vs baseline: 7.3302x; 1.0195x over previous
#include <cuda_runtime.h>
#include <cuda_fp16.h>
#include <math.h>
#include <stdint.h>

#define B_SZ  8
#define S_LEN 1024
#define NH    16
#define NKV   4
#define HD    128
#define DIM   2048
#define MTOT  (B_SZ * S_LEN)   // 8192
#define KVD   (NKV * HD)       // 512
#define QKVN  (DIM + 2 * KVD)  // 3072
#define QKEND (DIM + KVD)      // 2560: cols < this get RoPE

// ---------------- static scratch (allocation-free) ----------------
__device__ __half g_qkvh[(size_t)MTOT * QKVN];   // fused Q|K|V fp16 (rope applied)
__device__ __half g_xh[(size_t)MTOT * DIM];      // x fp16
__device__ __half g_oh[(size_t)MTOT * DIM];      // attn out fp16
__device__ __half g_wf[(size_t)QKVN * DIM];      // fused wq|wk|wv fp16
__device__ __half g_wo2[(size_t)DIM * DIM];      // wo fp16

// ---------------- helpers ----------------
__device__ __forceinline__ uint32_t smem_u32(const void* p) {
    uint32_t a;
    asm("{ .reg .u64 t; cvta.to.shared.u64 t, %1; cvt.u32.u64 %0, t; }" : "=r"(a) : "l"(p));
    return a;
}

__device__ __forceinline__ void ldsm_x4(uint32_t* r, uint32_t addr) {
    asm volatile("ldmatrix.sync.aligned.m8n8.x4.shared.b16 {%0,%1,%2,%3}, [%4];"
        : "=r"(r[0]), "=r"(r[1]), "=r"(r[2]), "=r"(r[3]) : "r"(addr));
}
__device__ __forceinline__ void ldsm_x4_trans(uint32_t* r, uint32_t addr) {
    asm volatile("ldmatrix.sync.aligned.m8n8.x4.trans.shared.b16 {%0,%1,%2,%3}, [%4];"
        : "=r"(r[0]), "=r"(r[1]), "=r"(r[2]), "=r"(r[3]) : "r"(addr));
}

__device__ __forceinline__ void mma16816(float* d, const uint32_t* a, const uint32_t* b) {
    asm volatile("mma.sync.aligned.m16n8k16.row.col.f32.f16.f16.f32 "
        "{%0,%1,%2,%3}, {%4,%5,%6,%7}, {%8,%9}, {%0,%1,%2,%3};"
        : "+f"(d[0]), "+f"(d[1]), "+f"(d[2]), "+f"(d[3])
        : "r"(a[0]), "r"(a[1]), "r"(a[2]), "r"(a[3]), "r"(b[0]), "r"(b[1]));
}

__device__ __forceinline__ uint32_t packh2(float lo, float hi) {
    __half2 h = __floats2half2_rn(lo, hi);
    return *(uint32_t*)&h;
}

// =====================================================================
// fused convert: all fp32 weights/activations -> fp16 in one launch
// regions (in float4 units):
//   [0, 1048576)            wq -> wf
//   [1048576, 1310720)      wk -> wf + DIM*DIM
//   [1310720, 1572864)      wv -> wf + (DIM+KVD)*DIM
//   [1572864, 2621440)      wo -> wo2
//   [2621440, 6815744)      x  -> xh
// =====================================================================
#define CVT_TOTAL4 6815744

__global__ void convert_all(const float* __restrict__ wq, const float* __restrict__ wk,
                            const float* __restrict__ wv, const float* __restrict__ wo,
                            const float* __restrict__ x,
                            __half* __restrict__ wf, __half* __restrict__ wo2,
                            __half* __restrict__ xh) {
    int i = blockIdx.x * 256 + threadIdx.x;
    if (i >= CVT_TOTAL4) return;
    const float* src;
    __half* dst;
    int off;
    if (i < 1048576)       { src = wq; dst = wf;                             off = i; }
    else if (i < 1310720)  { src = wk; dst = wf + (size_t)DIM * DIM;         off = i - 1048576; }
    else if (i < 1572864)  { src = wv; dst = wf + (size_t)(DIM + KVD) * DIM; off = i - 1310720; }
    else if (i < 2621440)  { src = wo; dst = wo2;                            off = i - 1572864; }
    else                   { src = x;  dst = xh;                             off = i - 2621440; }
    float4 v = ((const float4*)src)[off];
    __half2* op = (__half2*)dst;
    op[off * 2 + 0] = __floats2half2_rn(v.x, v.y);
    op[off * 2 + 1] = __floats2half2_rn(v.z, v.w);
}

// =====================================================================
// GEMM via mma.sync fp16: C[M,N] = A @ B^T, fp32 accum.
// tile 128x128, BK=32, 256 threads (8 warps, warp tile 32x64),
// 4-stage cp.async pipeline.
// =====================================================================
#define TILE_B   10240
#define STAGE_B  (2 * TILE_B)
#define GEMM_SMEM_BYTES (4 * STAGE_B)

__device__ __forceinline__ void gemm_load_chunk(
    const __half* __restrict__ A, const __half* __restrict__ B,
    int bm, int bn, int K, int kc, uint32_t stbase, int tid) {
#pragma unroll
    for (int t = 0; t < 4; t++) {
        const int tile = t >> 1;
        const int rem  = tid + (t & 1) * 256;
        const int row  = rem >> 2;
        const int c    = rem & 3;
        const __half* base = (tile == 0) ? A : B;
        const int grow = ((tile == 0) ? bm : bn) + row;
        const void* g = base + (size_t)grow * K + kc * 32 + c * 8;
        uint32_t dst = stbase + (uint32_t)tile * TILE_B + (uint32_t)(row * 80 + c * 16);
        asm volatile("cp.async.cg.shared.global [%0], [%1], 16;" :: "r"(dst), "l"(g) : "memory");
    }
    asm volatile("cp.async.commit_group;" ::: "memory");
}

template <bool ROPE_F16>
__global__ __launch_bounds__(256, 2)
void gemm_f16(const __half* __restrict__ A, const __half* __restrict__ B,
              void* __restrict__ Cout, int N, int K,
              const float* __restrict__ cosT, const float* __restrict__ sinT) {
    extern __shared__ char smem_raw[];
    const uint32_t sbase = smem_u32(smem_raw);

    const int tid  = threadIdx.x;
    const int wid  = tid >> 5;
    const int lane = tid & 31;
    const int warp_m = wid & 3;
    const int warp_n = wid >> 2;
    const int bm = blockIdx.y * 128;
    const int bn = blockIdx.x * 128;

    float acc[2][8][4];
#pragma unroll
    for (int i = 0; i < 2; i++)
#pragma unroll
        for (int j = 0; j < 8; j++)
#pragma unroll
            for (int v = 0; v < 4; v++) acc[i][j][v] = 0.0f;

    const uint32_t a_row = (uint32_t)(warp_m * 32 + (lane & 15));
    const uint32_t a_off = a_row * 80u + (uint32_t)((lane >> 4) * 16);
    const uint32_t b_row = (uint32_t)(warp_n * 64 + (lane & 7) + ((lane >> 4) & 1) * 8);
    const uint32_t b_off = b_row * 80u + (uint32_t)(((lane >> 3) & 1) * 16);

    const int NCHUNK = K >> 5;

    gemm_load_chunk(A, B, bm, bn, K, 0, sbase + 0u * STAGE_B, tid);
    gemm_load_chunk(A, B, bm, bn, K, 1, sbase + 1u * STAGE_B, tid);
    gemm_load_chunk(A, B, bm, bn, K, 2, sbase + 2u * STAGE_B, tid);

    for (int c = 0; c < NCHUNK; c++) {
        if (c + 2 < NCHUNK)      asm volatile("cp.async.wait_group 2;" ::: "memory");
        else if (c + 1 < NCHUNK) asm volatile("cp.async.wait_group 1;" ::: "memory");
        else                     asm volatile("cp.async.wait_group 0;" ::: "memory");
        __syncthreads();

        if (c + 3 < NCHUNK)
            gemm_load_chunk(A, B, bm, bn, K, c + 3,
                            sbase + (uint32_t)((c + 3) & 3) * STAGE_B, tid);

        const uint32_t stage = (uint32_t)(c & 3) * STAGE_B;
#pragma unroll
        for (int ks = 0; ks < 2; ks++) {
            const uint32_t aa = sbase + stage + a_off + (uint32_t)ks * 32u;
            const uint32_t bb = sbase + stage + TILE_B + b_off + (uint32_t)ks * 32u;
            uint32_t bfrag[4][4];
#pragma unroll
            for (int nb = 0; nb < 4; nb++)
                ldsm_x4(bfrag[nb], bb + (uint32_t)nb * 16u * 80u);
            uint32_t af[2][4];
            ldsm_x4(af[0], aa);
            ldsm_x4(af[1], aa + 16u * 80u);
#pragma unroll
            for (int mt = 0; mt < 2; mt++)
#pragma unroll
                for (int nb = 0; nb < 4; nb++) {
                    mma16816(acc[mt][nb * 2 + 0], af[mt], &bfrag[nb][0]);
                    mma16816(acc[mt][nb * 2 + 1], af[mt], &bfrag[nb][2]);
                }
        }
    }

    const int crow = lane >> 2;
    const int ccol = (lane & 3) * 2;
#pragma unroll
    for (int mt = 0; mt < 2; mt++) {
#pragma unroll
        for (int nt = 0; nt < 8; nt++) {
            const int row = bm + warp_m * 32 + mt * 16 + crow;
            const int col = bn + warp_n * 64 + nt * 8 + ccol;
            if (ROPE_F16) {
                float2 v0 = make_float2(acc[mt][nt][0], acc[mt][nt][1]);
                float2 v1 = make_float2(acc[mt][nt][2], acc[mt][nt][3]);
                if (col < QKEND) {
                    const int j  = (col & (HD - 1)) >> 1;
                    const int s0 = row & (S_LEN - 1);
                    const int s1 = (row + 8) & (S_LEN - 1);
                    float c0 = cosT[s0 * 64 + j], n0 = sinT[s0 * 64 + j];
                    float c1 = cosT[s1 * 64 + j], n1 = sinT[s1 * 64 + j];
                    v0 = make_float2(v0.x * c0 - v0.y * n0, v0.x * n0 + v0.y * c0);
                    v1 = make_float2(v1.x * c1 - v1.y * n1, v1.x * n1 + v1.y * c1);
                }
                __half* Ch = (__half*)Cout;
                *(uint32_t*)&Ch[(size_t)row * N + col]       = packh2(v0.x, v0.y);
                *(uint32_t*)&Ch[(size_t)(row + 8) * N + col] = packh2(v1.x, v1.y);
            } else {
                float* Cf = (float*)Cout;
                *(float2*)&Cf[(size_t)row * N + col]       = make_float2(acc[mt][nt][0], acc[mt][nt][1]);
                *(float2*)&Cf[(size_t)(row + 8) * N + col] = make_float2(acc[mt][nt][2], acc[mt][nt][3]);
            }
        }
    }
}

// =====================================================================
// Tensor-core flash attention (causal, GQA).
// BM=128, BN=64, D=128, 256 threads (8 warps, each owns 16 q-rows).
// Q/K/V fp16 in smem stride 136 halves; K/V double-buffered cp.async.
// smem: Q 34816 + 2*K 17408 + 2*V 17408 = 104448 B (2 CTAs/SM)
// =====================================================================
#define FLA_KV_B    (64 * 136 * 2)                 // 17408 B
#define FLA_Q_B     (128 * 136 * 2)                // 34816 B
#define FLASH_SMEM_BYTES (FLA_Q_B + 4 * FLA_KV_B)  // 104448

__device__ __forceinline__ void fla_load_kv(const __half* src, uint32_t dst, int tid) {
#pragma unroll
    for (int i = 0; i < 4; i++) {
        int s = tid + i * 256;
        int row = s >> 4, seg = s & 15;
        const void* g = src + (size_t)row * QKVN + seg * 8;
        asm volatile("cp.async.cg.shared.global [%0], [%1], 16;"
            :: "r"(dst + (uint32_t)(row * 272 + seg * 16)), "l"(g) : "memory");
    }
}

__global__ __launch_bounds__(256)
void flash_mma(const __half* __restrict__ QKVh, __half* __restrict__ Oh) {
    const int qt = blockIdx.x;          // 0..7 (128-row q tiles)
    const int h  = blockIdx.y;
    const int b  = blockIdx.z;
    const int g  = h >> 2;

    extern __shared__ char smraw[];
    const uint32_t sQ = smem_u32(smraw);
    const uint32_t sK = sQ + FLA_Q_B;
    const uint32_t sV = sK + 2 * FLA_KV_B;

    const int tid  = threadIdx.x;
    const int wid  = tid >> 5;
    const int lane = tid & 31;

    // initial loads: Q (128 rows) + K0 + V0
    {
        const __half* qsrc = QKVh + (size_t)(b * S_LEN + qt * 128) * QKVN + h * HD;
#pragma unroll
        for (int i = 0; i < 8; i++) {
            int s = tid + i * 256;
            int row = s >> 4, seg = s & 15;
            const void* gp = qsrc + (size_t)row * QKVN + seg * 8;
            asm volatile("cp.async.cg.shared.global [%0], [%1], 16;"
                :: "r"(sQ + (uint32_t)(row * 272 + seg * 16)), "l"(gp) : "memory");
        }
        const __half* ksrc = QKVh + (size_t)(b * S_LEN) * QKVN + DIM + g * HD;
        fla_load_kv(ksrc, sK, tid);
        fla_load_kv(ksrc + KVD, sV, tid);
        asm volatile("cp.async.commit_group;" ::: "memory");
    }

    const uint32_t a_base = sQ + (uint32_t)((wid * 16 + (lane & 15)) * 272 + (lane >> 4) * 16);
    const uint32_t kb_off = (uint32_t)(((lane & 7) + ((lane >> 4) & 1) * 8) * 272 + ((lane >> 3) & 1) * 16);
    const uint32_t vb_off = (uint32_t)(((lane & 7) + ((lane >> 3) & 1) * 8) * 272 + ((lane >> 4) & 1) * 16);

    float o[16][4];
#pragma unroll
    for (int j = 0; j < 16; j++)
#pragma unroll
        for (int v = 0; v < 4; v++) o[j][v] = 0.0f;
    float m0 = -INFINITY, m1 = -INFINITY, l0 = 0.0f, l1 = 0.0f;

    asm volatile("cp.async.wait_group 0;" ::: "memory");
    __syncthreads();

    uint32_t qa[8][4];
#pragma unroll
    for (int ks = 0; ks < 8; ks++) ldsm_x4(qa[ks], a_base + (uint32_t)ks * 32u);

    const float scale = 0.08838834764831845f;  // 1/sqrt(128)
    const int rb0 = wid * 16 + (lane >> 2);    // warp-local row 0
    const int rb1 = rb0 + 8;
    const int cb  = (lane & 3) * 2;
    const int qrow0 = qt * 128 + rb0;          // absolute q row
    const int qrow1 = qrow0 + 8;

    const int njt = 2 * qt + 2;
    for (int jt = 0; jt < njt; jt++) {
        const uint32_t buf = (uint32_t)(jt & 1) * FLA_KV_B;
        if (jt > 0) {
            asm volatile("cp.async.wait_group 0;" ::: "memory");
            __syncthreads();
        }
        if (jt + 1 < njt) {
            const __half* ksrc = QKVh + (size_t)(b * S_LEN + (jt + 1) * 64) * QKVN + DIM + g * HD;
            const uint32_t nbuf = (uint32_t)((jt + 1) & 1) * FLA_KV_B;
            fla_load_kv(ksrc, sK + nbuf, tid);
            fla_load_kv(ksrc + KVD, sV + nbuf, tid);
            asm volatile("cp.async.commit_group;" ::: "memory");
        }

        // ---- S = Q K^T ----
        float s[8][4];
#pragma unroll
        for (int j = 0; j < 8; j++)
#pragma unroll
            for (int v = 0; v < 4; v++) s[j][v] = 0.0f;

#pragma unroll
        for (int ks = 0; ks < 8; ks++) {
            const uint32_t bb = sK + buf + kb_off + (uint32_t)ks * 32u;
#pragma unroll
            for (int nb = 0; nb < 4; nb++) {
                uint32_t bf[4];
                ldsm_x4(bf, bb + (uint32_t)nb * (16u * 272u));
                mma16816(s[nb * 2 + 0], qa[ks], &bf[0]);
                mma16816(s[nb * 2 + 1], qa[ks], &bf[2]);
            }
        }

#pragma unroll
        for (int j = 0; j < 8; j++) {
            s[j][0] *= scale; s[j][1] *= scale; s[j][2] *= scale; s[j][3] *= scale;
        }
        if (jt >= 2 * qt) {   // diagonal region (last two k-tiles)
#pragma unroll
            for (int j = 0; j < 8; j++) {
                const int c0 = jt * 64 + j * 8 + cb;
                if (c0 > qrow0)     s[j][0] = -1e30f;
                if (c0 + 1 > qrow0) s[j][1] = -1e30f;
                if (c0 > qrow1)     s[j][2] = -1e30f;
                if (c0 + 1 > qrow1) s[j][3] = -1e30f;
            }
        }

        // ---- online softmax ----
        float mx0 = -INFINITY, mx1 = -INFINITY;
#pragma unroll
        for (int j = 0; j < 8; j++) {
            mx0 = fmaxf(mx0, fmaxf(s[j][0], s[j][1]));
            mx1 = fmaxf(mx1, fmaxf(s[j][2], s[j][3]));
        }
        mx0 = fmaxf(mx0, __shfl_xor_sync(0xffffffffu, mx0, 1));
        mx0 = fmaxf(mx0, __shfl_xor_sync(0xffffffffu, mx0, 2));
        mx1 = fmaxf(mx1, __shfl_xor_sync(0xffffffffu, mx1, 1));
        mx1 = fmaxf(mx1, __shfl_xor_sync(0xffffffffu, mx1, 2));
        const float mn0 = fmaxf(m0, mx0);
        const float mn1 = fmaxf(m1, mx1);
        const float al0 = __expf(m0 - mn0);
        const float al1 = __expf(m1 - mn1);
        m0 = mn0; m1 = mn1;

        float sum0 = 0.0f, sum1 = 0.0f;
#pragma unroll
        for (int j = 0; j < 8; j++) {
            s[j][0] = __expf(s[j][0] - mn0);
            s[j][1] = __expf(s[j][1] - mn0);
            s[j][2] = __expf(s[j][2] - mn1);
            s[j][3] = __expf(s[j][3] - mn1);
            sum0 += s[j][0] + s[j][1];
            sum1 += s[j][2] + s[j][3];
        }
        sum0 += __shfl_xor_sync(0xffffffffu, sum0, 1);
        sum0 += __shfl_xor_sync(0xffffffffu, sum0, 2);
        sum1 += __shfl_xor_sync(0xffffffffu, sum1, 1);
        sum1 += __shfl_xor_sync(0xffffffffu, sum1, 2);
        l0 = l0 * al0 + sum0;
        l1 = l1 * al1 + sum1;

#pragma unroll
        for (int j = 0; j < 16; j++) {
            o[j][0] *= al0; o[j][1] *= al0; o[j][2] *= al1; o[j][3] *= al1;
        }

        // ---- O += P V ----
#pragma unroll
        for (int ksp = 0; ksp < 4; ksp++) {
            uint32_t pa[4];
            pa[0] = packh2(s[2 * ksp][0],     s[2 * ksp][1]);
            pa[1] = packh2(s[2 * ksp][2],     s[2 * ksp][3]);
            pa[2] = packh2(s[2 * ksp + 1][0], s[2 * ksp + 1][1]);
            pa[3] = packh2(s[2 * ksp + 1][2], s[2 * ksp + 1][3]);
            const uint32_t vb = sV + buf + vb_off + (uint32_t)ksp * (16u * 272u);
#pragma unroll
            for (int nb = 0; nb < 8; nb++) {
                uint32_t bf[4];
                ldsm_x4_trans(bf, vb + (uint32_t)nb * 32u);
                mma16816(o[nb * 2 + 0], pa, &bf[0]);
                mma16816(o[nb * 2 + 1], pa, &bf[2]);
            }
        }
    }

    const float inv0 = 1.0f / l0;
    const float inv1 = 1.0f / l1;
    const size_t row0 = (size_t)(b * S_LEN + qt * 128 + rb0);
    const size_t row1 = row0 + 8;
#pragma unroll
    for (int j = 0; j < 16; j++) {
        const int col = h * HD + j * 8 + cb;
        uint32_t p0 = packh2(o[j][0] * inv0, o[j][1] * inv0);
        uint32_t p1 = packh2(o[j][2] * inv1, o[j][3] * inv1);
        *(uint32_t*)&Oh[row0 * DIM + col] = p0;
        *(uint32_t*)&Oh[row1 * DIM + col] = p1;
    }
}

// =====================================================================
// launch
// =====================================================================
extern "C" void kernel_launch(void* const* d_in, const int* in_sizes, int n_in,
                              void* d_out, int out_size) {
    (void)in_sizes; (void)n_in; (void)out_size;
    const float* x    = (const float*)d_in[0];
    const float* cosT = (const float*)d_in[1];
    const float* sinT = (const float*)d_in[2];
    const float* wq   = (const float*)d_in[3];
    const float* wk   = (const float*)d_in[4];
    const float* wv   = (const float*)d_in[5];
    const float* wo   = (const float*)d_in[6];
    float* out = (float*)d_out;

    __half *pqkvh, *xh, *oh, *wf, *wo2;
    cudaGetSymbolAddress((void**)&pqkvh, g_qkvh);
    cudaGetSymbolAddress((void**)&xh, g_xh);
    cudaGetSymbolAddress((void**)&oh, g_oh);
    cudaGetSymbolAddress((void**)&wf, g_wf);
    cudaGetSymbolAddress((void**)&wo2, g_wo2);

    cudaFuncSetAttribute(flash_mma, cudaFuncAttributeMaxDynamicSharedMemorySize, FLASH_SMEM_BYTES);
    cudaFuncSetAttribute(gemm_f16<true>,  cudaFuncAttributeMaxDynamicSharedMemorySize, GEMM_SMEM_BYTES);
    cudaFuncSetAttribute(gemm_f16<false>, cudaFuncAttributeMaxDynamicSharedMemorySize, GEMM_SMEM_BYTES);

    // one fused convert launch
    convert_all<<<(CVT_TOTAL4 + 255) / 256, 256>>>(wq, wk, wv, wo, x, wf, wo2, xh);

    // fused QKV projection with RoPE epilogue, fp16 out
    gemm_f16<true><<<dim3(QKVN / 128, MTOT / 128), 256, GEMM_SMEM_BYTES>>>(
        xh, wf, pqkvh, QKVN, DIM, cosT, sinT);

    // tensor-core flash attention (writes fp16 O directly)
    flash_mma<<<dim3(S_LEN / 128, NH, B_SZ), 256, FLASH_SMEM_BYTES>>>(pqkvh, oh);

    // output projection (fp32 out)
    gemm_f16<false><<<dim3(DIM / 128, MTOT / 128), 256, GEMM_SMEM_BYTES>>>(
        oh, wo2, out, DIM, DIM, nullptr, nullptr);
}

// round 9
// speedup vs baseline: 7.4948x; 1.0225x over previous
#include <cuda_runtime.h>
#include <cuda_fp16.h>
#include <math.h>
#include <stdint.h>

#define B_SZ  8
#define S_LEN 1024
#define NH    16
#define NKV   4
#define HD    128
#define DIM   2048
#define MTOT  (B_SZ * S_LEN)   // 8192
#define KVD   (NKV * HD)       // 512
#define QKVN  (DIM + 2 * KVD)  // 3072
#define QKEND (DIM + KVD)      // 2560: cols < this get RoPE

// ---------------- static scratch (allocation-free) ----------------
__device__ __half g_qkvh[(size_t)MTOT * QKVN];   // fused Q|K|V fp16 (rope applied)
__device__ __half g_xh[(size_t)MTOT * DIM];      // x fp16
__device__ __half g_oh[(size_t)MTOT * DIM];      // attn out fp16
__device__ __half g_wf[(size_t)QKVN * DIM];      // fused wq|wk|wv fp16
__device__ __half g_wo2[(size_t)DIM * DIM];      // wo fp16

// ---------------- helpers ----------------
__device__ __forceinline__ uint32_t smem_u32(const void* p) {
    uint32_t a;
    asm("{ .reg .u64 t; cvta.to.shared.u64 t, %1; cvt.u32.u64 %0, t; }" : "=r"(a) : "l"(p));
    return a;
}

__device__ __forceinline__ void ldsm_x4(uint32_t* r, uint32_t addr) {
    asm volatile("ldmatrix.sync.aligned.m8n8.x4.shared.b16 {%0,%1,%2,%3}, [%4];"
        : "=r"(r[0]), "=r"(r[1]), "=r"(r[2]), "=r"(r[3]) : "r"(addr));
}
__device__ __forceinline__ void ldsm_x4_trans(uint32_t* r, uint32_t addr) {
    asm volatile("ldmatrix.sync.aligned.m8n8.x4.trans.shared.b16 {%0,%1,%2,%3}, [%4];"
        : "=r"(r[0]), "=r"(r[1]), "=r"(r[2]), "=r"(r[3]) : "r"(addr));
}

__device__ __forceinline__ void mma16816(float* d, const uint32_t* a, const uint32_t* b) {
    asm volatile("mma.sync.aligned.m16n8k16.row.col.f32.f16.f16.f32 "
        "{%0,%1,%2,%3}, {%4,%5,%6,%7}, {%8,%9}, {%0,%1,%2,%3};"
        : "+f"(d[0]), "+f"(d[1]), "+f"(d[2]), "+f"(d[3])
        : "r"(a[0]), "r"(a[1]), "r"(a[2]), "r"(a[3]), "r"(b[0]), "r"(b[1]));
}

__device__ __forceinline__ uint32_t packh2(float lo, float hi) {
    __half2 h = __floats2half2_rn(lo, hi);
    return *(uint32_t*)&h;
}

// =====================================================================
// fused convert: all fp32 weights/activations -> fp16 in one launch
// =====================================================================
#define CVT_TOTAL4 6815744

__global__ void convert_all(const float* __restrict__ wq, const float* __restrict__ wk,
                            const float* __restrict__ wv, const float* __restrict__ wo,
                            const float* __restrict__ x,
                            __half* __restrict__ wf, __half* __restrict__ wo2,
                            __half* __restrict__ xh) {
    int i = blockIdx.x * 256 + threadIdx.x;
    if (i >= CVT_TOTAL4) return;
    const float* src;
    __half* dst;
    int off;
    if (i < 1048576)       { src = wq; dst = wf;                             off = i; }
    else if (i < 1310720)  { src = wk; dst = wf + (size_t)DIM * DIM;         off = i - 1048576; }
    else if (i < 1572864)  { src = wv; dst = wf + (size_t)(DIM + KVD) * DIM; off = i - 1310720; }
    else if (i < 2621440)  { src = wo; dst = wo2;                            off = i - 1572864; }
    else                   { src = x;  dst = xh;                             off = i - 2621440; }
    float4 v = ((const float4*)src)[off];
    __half2* op = (__half2*)dst;
    op[off * 2 + 0] = __floats2half2_rn(v.x, v.y);
    op[off * 2 + 1] = __floats2half2_rn(v.z, v.w);
}

// =====================================================================
// GEMM via mma.sync fp16: C[M,N] = A @ B^T, fp32 accum.
// tile 128x128, BK=64, 256 threads (8 warps, warp tile 32x64),
// 3-stage cp.async pipeline. smem row stride 144B (ldmatrix conflict-free).
// =====================================================================
#define TILE_B   18432          // 128 rows * 144 B
#define STAGE_B  (2 * TILE_B)   // 36864
#define GEMM_SMEM_BYTES (3 * STAGE_B)  // 110592

__device__ __forceinline__ void gemm_load_chunk(
    const __half* __restrict__ A, const __half* __restrict__ B,
    int bm, int bn, int K, int kc, uint32_t stbase, int tid) {
#pragma unroll
    for (int t = 0; t < 8; t++) {
        const int tile = t >> 2;                  // 0:A 1:B (compile-time)
        const int rem  = tid + (t & 3) * 256;     // 0..1023
        const int row  = rem >> 3;
        const int seg  = rem & 7;
        const __half* base = (tile == 0) ? A : B;
        const int grow = ((tile == 0) ? bm : bn) + row;
        const void* g = base + (size_t)grow * K + kc * 64 + seg * 8;
        uint32_t dst = stbase + (uint32_t)tile * TILE_B + (uint32_t)(row * 144 + seg * 16);
        asm volatile("cp.async.cg.shared.global [%0], [%1], 16;" :: "r"(dst), "l"(g) : "memory");
    }
    asm volatile("cp.async.commit_group;" ::: "memory");
}

template <bool ROPE_F16>
__global__ __launch_bounds__(256, 2)
void gemm_f16(const __half* __restrict__ A, const __half* __restrict__ B,
              void* __restrict__ Cout, int N, int K,
              const float* __restrict__ cosT, const float* __restrict__ sinT) {
    extern __shared__ char smem_raw[];
    const uint32_t sbase = smem_u32(smem_raw);

    const int tid  = threadIdx.x;
    const int wid  = tid >> 5;
    const int lane = tid & 31;
    const int warp_m = wid & 3;
    const int warp_n = wid >> 2;
    const int bm = blockIdx.y * 128;
    const int bn = blockIdx.x * 128;

    float acc[2][8][4];
#pragma unroll
    for (int i = 0; i < 2; i++)
#pragma unroll
        for (int j = 0; j < 8; j++)
#pragma unroll
            for (int v = 0; v < 4; v++) acc[i][j][v] = 0.0f;

    const uint32_t a_row = (uint32_t)(warp_m * 32 + (lane & 15));
    const uint32_t a_off = a_row * 144u + (uint32_t)((lane >> 4) * 16);
    const uint32_t b_row = (uint32_t)(warp_n * 64 + (lane & 7) + ((lane >> 4) & 1) * 8);
    const uint32_t b_off = b_row * 144u + (uint32_t)(((lane >> 3) & 1) * 16);

    const int NCHUNK = K >> 6;   // BK = 64

    gemm_load_chunk(A, B, bm, bn, K, 0, sbase + 0u * STAGE_B, tid);
    gemm_load_chunk(A, B, bm, bn, K, 1, sbase + 1u * STAGE_B, tid);

    uint32_t stage_of[3] = {0u, STAGE_B, 2u * STAGE_B};

    for (int c = 0; c < NCHUNK; c++) {
        if (c + 1 < NCHUNK) asm volatile("cp.async.wait_group 1;" ::: "memory");
        else                asm volatile("cp.async.wait_group 0;" ::: "memory");
        __syncthreads();

        if (c + 2 < NCHUNK) {
            int bsel = (c + 2) % 3;
            gemm_load_chunk(A, B, bm, bn, K, c + 2, sbase + stage_of[bsel], tid);
        }

        const uint32_t stage = stage_of[c % 3];
#pragma unroll
        for (int ks = 0; ks < 4; ks++) {
            const uint32_t aa = sbase + stage + a_off + (uint32_t)ks * 32u;
            const uint32_t bb = sbase + stage + TILE_B + b_off + (uint32_t)ks * 32u;
            uint32_t bfrag[4][4];
#pragma unroll
            for (int nb = 0; nb < 4; nb++)
                ldsm_x4(bfrag[nb], bb + (uint32_t)nb * 16u * 144u);
            uint32_t af[2][4];
            ldsm_x4(af[0], aa);
            ldsm_x4(af[1], aa + 16u * 144u);
#pragma unroll
            for (int mt = 0; mt < 2; mt++)
#pragma unroll
                for (int nb = 0; nb < 4; nb++) {
                    mma16816(acc[mt][nb * 2 + 0], af[mt], &bfrag[nb][0]);
                    mma16816(acc[mt][nb * 2 + 1], af[mt], &bfrag[nb][2]);
                }
        }
    }

    const int crow = lane >> 2;
    const int ccol = (lane & 3) * 2;
#pragma unroll
    for (int mt = 0; mt < 2; mt++) {
#pragma unroll
        for (int nt = 0; nt < 8; nt++) {
            const int row = bm + warp_m * 32 + mt * 16 + crow;
            const int col = bn + warp_n * 64 + nt * 8 + ccol;
            if (ROPE_F16) {
                float2 v0 = make_float2(acc[mt][nt][0], acc[mt][nt][1]);
                float2 v1 = make_float2(acc[mt][nt][2], acc[mt][nt][3]);
                if (col < QKEND) {
                    const int j  = (col & (HD - 1)) >> 1;
                    const int s0 = row & (S_LEN - 1);
                    const int s1 = (row + 8) & (S_LEN - 1);
                    float c0 = cosT[s0 * 64 + j], n0 = sinT[s0 * 64 + j];
                    float c1 = cosT[s1 * 64 + j], n1 = sinT[s1 * 64 + j];
                    v0 = make_float2(v0.x * c0 - v0.y * n0, v0.x * n0 + v0.y * c0);
                    v1 = make_float2(v1.x * c1 - v1.y * n1, v1.x * n1 + v1.y * c1);
                }
                __half* Ch = (__half*)Cout;
                *(uint32_t*)&Ch[(size_t)row * N + col]       = packh2(v0.x, v0.y);
                *(uint32_t*)&Ch[(size_t)(row + 8) * N + col] = packh2(v1.x, v1.y);
            } else {
                float* Cf = (float*)Cout;
                *(float2*)&Cf[(size_t)row * N + col]       = make_float2(acc[mt][nt][0], acc[mt][nt][1]);
                *(float2*)&Cf[(size_t)(row + 8) * N + col] = make_float2(acc[mt][nt][2], acc[mt][nt][3]);
            }
        }
    }
}

// =====================================================================
// Tensor-core flash attention (causal, GQA).
// BM=128, BN=64, D=128, 256 threads (8 warps, each owns 16 q-rows).
// Q/K/V fp16 in smem stride 136 halves; K/V double-buffered cp.async.
// Fully-masked warp-tiles on the diagonal are skipped.
// =====================================================================
#define FLA_KV_B    (64 * 136 * 2)                 // 17408 B
#define FLA_Q_B     (128 * 136 * 2)                // 34816 B
#define FLASH_SMEM_BYTES (FLA_Q_B + 4 * FLA_KV_B)  // 104448

__device__ __forceinline__ void fla_load_kv(const __half* src, uint32_t dst, int tid) {
#pragma unroll
    for (int i = 0; i < 4; i++) {
        int s = tid + i * 256;
        int row = s >> 4, seg = s & 15;
        const void* g = src + (size_t)row * QKVN + seg * 8;
        asm volatile("cp.async.cg.shared.global [%0], [%1], 16;"
            :: "r"(dst + (uint32_t)(row * 272 + seg * 16)), "l"(g) : "memory");
    }
}

__global__ __launch_bounds__(256)
void flash_mma(const __half* __restrict__ QKVh, __half* __restrict__ Oh) {
    const int qt = blockIdx.x;          // 0..7 (128-row q tiles)
    const int h  = blockIdx.y;
    const int b  = blockIdx.z;
    const int g  = h >> 2;

    extern __shared__ char smraw[];
    const uint32_t sQ = smem_u32(smraw);
    const uint32_t sK = sQ + FLA_Q_B;
    const uint32_t sV = sK + 2 * FLA_KV_B;

    const int tid  = threadIdx.x;
    const int wid  = tid >> 5;
    const int lane = tid & 31;

    {
        const __half* qsrc = QKVh + (size_t)(b * S_LEN + qt * 128) * QKVN + h * HD;
#pragma unroll
        for (int i = 0; i < 8; i++) {
            int s = tid + i * 256;
            int row = s >> 4, seg = s & 15;
            const void* gp = qsrc + (size_t)row * QKVN + seg * 8;
            asm volatile("cp.async.cg.shared.global [%0], [%1], 16;"
                :: "r"(sQ + (uint32_t)(row * 272 + seg * 16)), "l"(gp) : "memory");
        }
        const __half* ksrc = QKVh + (size_t)(b * S_LEN) * QKVN + DIM + g * HD;
        fla_load_kv(ksrc, sK, tid);
        fla_load_kv(ksrc + KVD, sV, tid);
        asm volatile("cp.async.commit_group;" ::: "memory");
    }

    const uint32_t a_base = sQ + (uint32_t)((wid * 16 + (lane & 15)) * 272 + (lane >> 4) * 16);
    const uint32_t kb_off = (uint32_t)(((lane & 7) + ((lane >> 4) & 1) * 8) * 272 + ((lane >> 3) & 1) * 16);
    const uint32_t vb_off = (uint32_t)(((lane & 7) + ((lane >> 3) & 1) * 8) * 272 + ((lane >> 4) & 1) * 16);

    float o[16][4];
#pragma unroll
    for (int j = 0; j < 16; j++)
#pragma unroll
        for (int v = 0; v < 4; v++) o[j][v] = 0.0f;
    float m0 = -INFINITY, m1 = -INFINITY, l0 = 0.0f, l1 = 0.0f;

    asm volatile("cp.async.wait_group 0;" ::: "memory");
    __syncthreads();

    uint32_t qa[8][4];
#pragma unroll
    for (int ks = 0; ks < 8; ks++) ldsm_x4(qa[ks], a_base + (uint32_t)ks * 32u);

    const float scale = 0.08838834764831845f;  // 1/sqrt(128)
    const int rb0 = wid * 16 + (lane >> 2);
    const int rb1 = rb0 + 8;
    const int cb  = (lane & 3) * 2;
    const int qrow0 = qt * 128 + rb0;
    const int qrow1 = qrow0 + 8;
    const int warp_row_max = qt * 128 + wid * 16 + 15;

    const int njt = 2 * qt + 2;
    for (int jt = 0; jt < njt; jt++) {
        const uint32_t buf = (uint32_t)(jt & 1) * FLA_KV_B;
        if (jt > 0) {
            asm volatile("cp.async.wait_group 0;" ::: "memory");
            __syncthreads();
        }
        if (jt + 1 < njt) {
            const __half* ksrc = QKVh + (size_t)(b * S_LEN + (jt + 1) * 64) * QKVN + DIM + g * HD;
            const uint32_t nbuf = (uint32_t)((jt + 1) & 1) * FLA_KV_B;
            fla_load_kv(ksrc, sK + nbuf, tid);
            fla_load_kv(ksrc + KVD, sV + nbuf, tid);
            asm volatile("cp.async.commit_group;" ::: "memory");
        }

        // fully-masked warp-tile: nothing to do
        if (jt * 64 > warp_row_max) continue;

        // ---- S = Q K^T ----
        float s[8][4];
#pragma unroll
        for (int j = 0; j < 8; j++)
#pragma unroll
            for (int v = 0; v < 4; v++) s[j][v] = 0.0f;

#pragma unroll
        for (int ks = 0; ks < 8; ks++) {
            const uint32_t bb = sK + buf + kb_off + (uint32_t)ks * 32u;
#pragma unroll
            for (int nb = 0; nb < 4; nb++) {
                uint32_t bf[4];
                ldsm_x4(bf, bb + (uint32_t)nb * (16u * 272u));
                mma16816(s[nb * 2 + 0], qa[ks], &bf[0]);
                mma16816(s[nb * 2 + 1], qa[ks], &bf[2]);
            }
        }

#pragma unroll
        for (int j = 0; j < 8; j++) {
            s[j][0] *= scale; s[j][1] *= scale; s[j][2] *= scale; s[j][3] *= scale;
        }
        if (jt >= 2 * qt) {
#pragma unroll
            for (int j = 0; j < 8; j++) {
                const int c0 = jt * 64 + j * 8 + cb;
                if (c0 > qrow0)     s[j][0] = -1e30f;
                if (c0 + 1 > qrow0) s[j][1] = -1e30f;
                if (c0 > qrow1)     s[j][2] = -1e30f;
                if (c0 + 1 > qrow1) s[j][3] = -1e30f;
            }
        }

        // ---- online softmax ----
        float mx0 = -INFINITY, mx1 = -INFINITY;
#pragma unroll
        for (int j = 0; j < 8; j++) {
            mx0 = fmaxf(mx0, fmaxf(s[j][0], s[j][1]));
            mx1 = fmaxf(mx1, fmaxf(s[j][2], s[j][3]));
        }
        mx0 = fmaxf(mx0, __shfl_xor_sync(0xffffffffu, mx0, 1));
        mx0 = fmaxf(mx0, __shfl_xor_sync(0xffffffffu, mx0, 2));
        mx1 = fmaxf(mx1, __shfl_xor_sync(0xffffffffu, mx1, 1));
        mx1 = fmaxf(mx1, __shfl_xor_sync(0xffffffffu, mx1, 2));
        const float mn0 = fmaxf(m0, mx0);
        const float mn1 = fmaxf(m1, mx1);
        const float al0 = __expf(m0 - mn0);
        const float al1 = __expf(m1 - mn1);
        m0 = mn0; m1 = mn1;

        float sum0 = 0.0f, sum1 = 0.0f;
#pragma unroll
        for (int j = 0; j < 8; j++) {
            s[j][0] = __expf(s[j][0] - mn0);
            s[j][1] = __expf(s[j][1] - mn0);
            s[j][2] = __expf(s[j][2] - mn1);
            s[j][3] = __expf(s[j][3] - mn1);
            sum0 += s[j][0] + s[j][1];
            sum1 += s[j][2] + s[j][3];
        }
        sum0 += __shfl_xor_sync(0xffffffffu, sum0, 1);
        sum0 += __shfl_xor_sync(0xffffffffu, sum0, 2);
        sum1 += __shfl_xor_sync(0xffffffffu, sum1, 1);
        sum1 += __shfl_xor_sync(0xffffffffu, sum1, 2);
        l0 = l0 * al0 + sum0;
        l1 = l1 * al1 + sum1;

#pragma unroll
        for (int j = 0; j < 16; j++) {
            o[j][0] *= al0; o[j][1] *= al0; o[j][2] *= al1; o[j][3] *= al1;
        }

        // ---- O += P V ----
#pragma unroll
        for (int ksp = 0; ksp < 4; ksp++) {
            uint32_t pa[4];
            pa[0] = packh2(s[2 * ksp][0],     s[2 * ksp][1]);
            pa[1] = packh2(s[2 * ksp][2],     s[2 * ksp][3]);
            pa[2] = packh2(s[2 * ksp + 1][0], s[2 * ksp + 1][1]);
            pa[3] = packh2(s[2 * ksp + 1][2], s[2 * ksp + 1][3]);
            const uint32_t vb = sV + buf + vb_off + (uint32_t)ksp * (16u * 272u);
#pragma unroll
            for (int nb = 0; nb < 8; nb++) {
                uint32_t bf[4];
                ldsm_x4_trans(bf, vb + (uint32_t)nb * 32u);
                mma16816(o[nb * 2 + 0], pa, &bf[0]);
                mma16816(o[nb * 2 + 1], pa, &bf[2]);
            }
        }
    }

    const float inv0 = 1.0f / l0;
    const float inv1 = 1.0f / l1;
    const size_t row0 = (size_t)(b * S_LEN + qt * 128 + rb0);
    const size_t row1 = row0 + 8;
#pragma unroll
    for (int j = 0; j < 16; j++) {
        const int col = h * HD + j * 8 + cb;
        uint32_t p0 = packh2(o[j][0] * inv0, o[j][1] * inv0);
        uint32_t p1 = packh2(o[j][2] * inv1, o[j][3] * inv1);
        *(uint32_t*)&Oh[row0 * DIM + col] = p0;
        *(uint32_t*)&Oh[row1 * DIM + col] = p1;
    }
}

// =====================================================================
// launch
// =====================================================================
extern "C" void kernel_launch(void* const* d_in, const int* in_sizes, int n_in,
                              void* d_out, int out_size) {
    (void)in_sizes; (void)n_in; (void)out_size;
    const float* x    = (const float*)d_in[0];
    const float* cosT = (const float*)d_in[1];
    const float* sinT = (const float*)d_in[2];
    const float* wq   = (const float*)d_in[3];
    const float* wk   = (const float*)d_in[4];
    const float* wv   = (const float*)d_in[5];
    const float* wo   = (const float*)d_in[6];
    float* out = (float*)d_out;

    __half *pqkvh, *xh, *oh, *wf, *wo2;
    cudaGetSymbolAddress((void**)&pqkvh, g_qkvh);
    cudaGetSymbolAddress((void**)&xh, g_xh);
    cudaGetSymbolAddress((void**)&oh, g_oh);
    cudaGetSymbolAddress((void**)&wf, g_wf);
    cudaGetSymbolAddress((void**)&wo2, g_wo2);

    cudaFuncSetAttribute(flash_mma, cudaFuncAttributeMaxDynamicSharedMemorySize, FLASH_SMEM_BYTES);
    cudaFuncSetAttribute(gemm_f16<true>,  cudaFuncAttributeMaxDynamicSharedMemorySize, GEMM_SMEM_BYTES);
    cudaFuncSetAttribute(gemm_f16<false>, cudaFuncAttributeMaxDynamicSharedMemorySize, GEMM_SMEM_BYTES);

    // one fused convert launch
    convert_all<<<(CVT_TOTAL4 + 255) / 256, 256>>>(wq, wk, wv, wo, x, wf, wo2, xh);

    // fused QKV projection with RoPE epilogue, fp16 out
    gemm_f16<true><<<dim3(QKVN / 128, MTOT / 128), 256, GEMM_SMEM_BYTES>>>(
        xh, wf, pqkvh, QKVN, DIM, cosT, sinT);

    // tensor-core flash attention (writes fp16 O directly)
    flash_mma<<<dim3(S_LEN / 128, NH, B_SZ), 256, FLASH_SMEM_BYTES>>>(pqkvh, oh);

    // output projection (fp32 out)
    gemm_f16<false><<<dim3(DIM / 128, MTOT / 128), 256, GEMM_SMEM_BYTES>>>(
        oh, wo2, out, DIM, DIM, nullptr, nullptr);
}

// round 10
// speedup vs baseline: 8.1643x; 1.0893x over previous
#include <cuda_runtime.h>
#include <cuda_fp16.h>
#include <math.h>
#include <stdint.h>

#define B_SZ  8
#define S_LEN 1024
#define NH    16
#define NKV   4
#define HD    128
#define DIM   2048
#define MTOT  (B_SZ * S_LEN)   // 8192
#define KVD   (NKV * HD)       // 512
#define QKVN  (DIM + 2 * KVD)  // 3072
#define QKEND (DIM + KVD)      // 2560: cols < this get RoPE

// ---------------- static scratch (allocation-free) ----------------
__device__ __half g_qkvh[(size_t)MTOT * QKVN];   // fused Q|K|V fp16 (rope applied)
__device__ __half g_xh[(size_t)MTOT * DIM];      // x fp16
__device__ __half g_oh[(size_t)MTOT * DIM];      // attn out fp16
__device__ __half g_wf[(size_t)QKVN * DIM];      // fused wq|wk|wv fp16
__device__ __half g_wo2[(size_t)DIM * DIM];      // wo fp16

// ---------------- helpers ----------------
__device__ __forceinline__ uint32_t smem_u32(const void* p) {
    uint32_t a;
    asm("{ .reg .u64 t; cvta.to.shared.u64 t, %1; cvt.u32.u64 %0, t; }" : "=r"(a) : "l"(p));
    return a;
}

__device__ __forceinline__ void ldsm_x4(uint32_t* r, uint32_t addr) {
    asm volatile("ldmatrix.sync.aligned.m8n8.x4.shared.b16 {%0,%1,%2,%3}, [%4];"
        : "=r"(r[0]), "=r"(r[1]), "=r"(r[2]), "=r"(r[3]) : "r"(addr));
}
__device__ __forceinline__ void ldsm_x4_trans(uint32_t* r, uint32_t addr) {
    asm volatile("ldmatrix.sync.aligned.m8n8.x4.trans.shared.b16 {%0,%1,%2,%3}, [%4];"
        : "=r"(r[0]), "=r"(r[1]), "=r"(r[2]), "=r"(r[3]) : "r"(addr));
}

__device__ __forceinline__ void mma16816(float* d, const uint32_t* a, const uint32_t* b) {
    asm volatile("mma.sync.aligned.m16n8k16.row.col.f32.f16.f16.f32 "
        "{%0,%1,%2,%3}, {%4,%5,%6,%7}, {%8,%9}, {%0,%1,%2,%3};"
        : "+f"(d[0]), "+f"(d[1]), "+f"(d[2]), "+f"(d[3])
        : "r"(a[0]), "r"(a[1]), "r"(a[2]), "r"(a[3]), "r"(b[0]), "r"(b[1]));
}

__device__ __forceinline__ uint32_t packh2(float lo, float hi) {
    __half2 h = __floats2half2_rn(lo, hi);
    return *(uint32_t*)&h;
}

// =====================================================================
// fused convert: all fp32 weights/activations -> fp16 in one launch
// =====================================================================
#define CVT_TOTAL4 6815744

__global__ void convert_all(const float* __restrict__ wq, const float* __restrict__ wk,
                            const float* __restrict__ wv, const float* __restrict__ wo,
                            const float* __restrict__ x,
                            __half* __restrict__ wf, __half* __restrict__ wo2,
                            __half* __restrict__ xh) {
    int i = blockIdx.x * 256 + threadIdx.x;
    if (i >= CVT_TOTAL4) return;
    const float* src;
    __half* dst;
    int off;
    if (i < 1048576)       { src = wq; dst = wf;                             off = i; }
    else if (i < 1310720)  { src = wk; dst = wf + (size_t)DIM * DIM;         off = i - 1048576; }
    else if (i < 1572864)  { src = wv; dst = wf + (size_t)(DIM + KVD) * DIM; off = i - 1310720; }
    else if (i < 2621440)  { src = wo; dst = wo2;                            off = i - 1572864; }
    else                   { src = x;  dst = xh;                             off = i - 2621440; }
    float4 v = ((const float4*)src)[off];
    __half2* op = (__half2*)dst;
    op[off * 2 + 0] = __floats2half2_rn(v.x, v.y);
    op[off * 2 + 1] = __floats2half2_rn(v.z, v.w);
}

// =====================================================================
// GEMM via mma.sync fp16: C[M,N] = A @ B^T, fp32 accum.
// CTA tile 128x128, BK=64, 128 threads (4 warps, warp tile 64x64),
// double-buffered cp.async. smem row stride 144B (ldmatrix conflict-free).
// 3 CTAs/SM (launch_bounds cap 168 regs).
// =====================================================================
#define TILE_B   18432          // 128 rows * 144 B
#define STAGE_B  (2 * TILE_B)   // 36864
#define GEMM_SMEM_BYTES (2 * STAGE_B)  // 73728

__device__ __forceinline__ void gemm_load_chunk(
    const __half* __restrict__ A, const __half* __restrict__ B,
    int bm, int bn, int K, int kc, uint32_t stbase, int tid) {
#pragma unroll
    for (int t = 0; t < 16; t++) {
        const int tile = t >> 3;                  // 0:A 1:B (compile-time)
        const int rem  = tid + (t & 7) * 128;     // 0..1023
        const int row  = rem >> 3;
        const int seg  = rem & 7;
        const __half* base = (tile == 0) ? A : B;
        const int grow = ((tile == 0) ? bm : bn) + row;
        const void* g = base + (size_t)grow * K + kc * 64 + seg * 8;
        uint32_t dst = stbase + (uint32_t)tile * TILE_B + (uint32_t)(row * 144 + seg * 16);
        asm volatile("cp.async.cg.shared.global [%0], [%1], 16;" :: "r"(dst), "l"(g) : "memory");
    }
    asm volatile("cp.async.commit_group;" ::: "memory");
}

template <bool ROPE_F16>
__global__ __launch_bounds__(128, 3)
void gemm_f16(const __half* __restrict__ A, const __half* __restrict__ B,
              void* __restrict__ Cout, int N, int K,
              const float* __restrict__ cosT, const float* __restrict__ sinT) {
    extern __shared__ char smem_raw[];
    const uint32_t sbase = smem_u32(smem_raw);

    const int tid  = threadIdx.x;
    const int wid  = tid >> 5;
    const int lane = tid & 31;
    const int warp_m = wid & 1;        // 2 warps along M (64 rows each)
    const int warp_n = wid >> 1;       // 2 warps along N (64 cols each)
    const int bm = blockIdx.y * 128;
    const int bn = blockIdx.x * 128;

    float acc[4][8][4];
#pragma unroll
    for (int i = 0; i < 4; i++)
#pragma unroll
        for (int j = 0; j < 8; j++)
#pragma unroll
            for (int v = 0; v < 4; v++) acc[i][j][v] = 0.0f;

    const uint32_t a_row = (uint32_t)(warp_m * 64 + (lane & 15));
    const uint32_t a_off = a_row * 144u + (uint32_t)((lane >> 4) * 16);
    const uint32_t b_row = (uint32_t)(warp_n * 64 + (lane & 7) + ((lane >> 4) & 1) * 8);
    const uint32_t b_off = b_row * 144u + (uint32_t)(((lane >> 3) & 1) * 16);

    const int NCHUNK = K >> 6;   // BK = 64

    gemm_load_chunk(A, B, bm, bn, K, 0, sbase, tid);

    for (int c = 0; c < NCHUNK; c++) {
        asm volatile("cp.async.wait_group 0;" ::: "memory");
        __syncthreads();
        if (c + 1 < NCHUNK)
            gemm_load_chunk(A, B, bm, bn, K, c + 1,
                            sbase + (uint32_t)((c + 1) & 1) * STAGE_B, tid);

        const uint32_t stage = (uint32_t)(c & 1) * STAGE_B;
#pragma unroll
        for (int ks = 0; ks < 4; ks++) {
            const uint32_t aa = sbase + stage + a_off + (uint32_t)ks * 32u;
            const uint32_t bb = sbase + stage + TILE_B + b_off + (uint32_t)ks * 32u;
            uint32_t af[4][4];
#pragma unroll
            for (int mt = 0; mt < 4; mt++)
                ldsm_x4(af[mt], aa + (uint32_t)mt * (16u * 144u));
#pragma unroll
            for (int nbh = 0; nbh < 2; nbh++) {
                uint32_t bf0[4], bf1[4];
                ldsm_x4(bf0, bb + (uint32_t)(nbh * 2 + 0) * (16u * 144u));
                ldsm_x4(bf1, bb + (uint32_t)(nbh * 2 + 1) * (16u * 144u));
#pragma unroll
                for (int mt = 0; mt < 4; mt++) {
                    mma16816(acc[mt][nbh * 4 + 0], af[mt], &bf0[0]);
                    mma16816(acc[mt][nbh * 4 + 1], af[mt], &bf0[2]);
                    mma16816(acc[mt][nbh * 4 + 2], af[mt], &bf1[0]);
                    mma16816(acc[mt][nbh * 4 + 3], af[mt], &bf1[2]);
                }
            }
        }
    }

    const int crow = lane >> 2;
    const int ccol = (lane & 3) * 2;
#pragma unroll
    for (int mt = 0; mt < 4; mt++) {
#pragma unroll
        for (int nt = 0; nt < 8; nt++) {
            const int row = bm + warp_m * 64 + mt * 16 + crow;
            const int col = bn + warp_n * 64 + nt * 8 + ccol;
            if (ROPE_F16) {
                float2 v0 = make_float2(acc[mt][nt][0], acc[mt][nt][1]);
                float2 v1 = make_float2(acc[mt][nt][2], acc[mt][nt][3]);
                if (col < QKEND) {
                    const int j  = (col & (HD - 1)) >> 1;
                    const int s0 = row & (S_LEN - 1);
                    const int s1 = (row + 8) & (S_LEN - 1);
                    float c0 = cosT[s0 * 64 + j], n0 = sinT[s0 * 64 + j];
                    float c1 = cosT[s1 * 64 + j], n1 = sinT[s1 * 64 + j];
                    v0 = make_float2(v0.x * c0 - v0.y * n0, v0.x * n0 + v0.y * c0);
                    v1 = make_float2(v1.x * c1 - v1.y * n1, v1.x * n1 + v1.y * c1);
                }
                __half* Ch = (__half*)Cout;
                *(uint32_t*)&Ch[(size_t)row * N + col]       = packh2(v0.x, v0.y);
                *(uint32_t*)&Ch[(size_t)(row + 8) * N + col] = packh2(v1.x, v1.y);
            } else {
                float* Cf = (float*)Cout;
                *(float2*)&Cf[(size_t)row * N + col]       = make_float2(acc[mt][nt][0], acc[mt][nt][1]);
                *(float2*)&Cf[(size_t)(row + 8) * N + col] = make_float2(acc[mt][nt][2], acc[mt][nt][3]);
            }
        }
    }
}

// =====================================================================
// Tensor-core flash attention (causal, GQA).
// BM=128, BN=64, D=128, 256 threads (8 warps, each owns 16 q-rows).
// Q/K/V fp16 in smem stride 136 halves; K/V double-buffered cp.async.
// Fully-masked warp-tiles on the diagonal are skipped.
// =====================================================================
#define FLA_KV_B    (64 * 136 * 2)                 // 17408 B
#define FLA_Q_B     (128 * 136 * 2)                // 34816 B
#define FLASH_SMEM_BYTES (FLA_Q_B + 4 * FLA_KV_B)  // 104448

__device__ __forceinline__ void fla_load_kv(const __half* src, uint32_t dst, int tid) {
#pragma unroll
    for (int i = 0; i < 4; i++) {
        int s = tid + i * 256;
        int row = s >> 4, seg = s & 15;
        const void* g = src + (size_t)row * QKVN + seg * 8;
        asm volatile("cp.async.cg.shared.global [%0], [%1], 16;"
            :: "r"(dst + (uint32_t)(row * 272 + seg * 16)), "l"(g) : "memory");
    }
}

__global__ __launch_bounds__(256)
void flash_mma(const __half* __restrict__ QKVh, __half* __restrict__ Oh) {
    const int qt = blockIdx.x;          // 0..7 (128-row q tiles)
    const int h  = blockIdx.y;
    const int b  = blockIdx.z;
    const int g  = h >> 2;

    extern __shared__ char smraw[];
    const uint32_t sQ = smem_u32(smraw);
    const uint32_t sK = sQ + FLA_Q_B;
    const uint32_t sV = sK + 2 * FLA_KV_B;

    const int tid  = threadIdx.x;
    const int wid  = tid >> 5;
    const int lane = tid & 31;

    {
        const __half* qsrc = QKVh + (size_t)(b * S_LEN + qt * 128) * QKVN + h * HD;
#pragma unroll
        for (int i = 0; i < 8; i++) {
            int s = tid + i * 256;
            int row = s >> 4, seg = s & 15;
            const void* gp = qsrc + (size_t)row * QKVN + seg * 8;
            asm volatile("cp.async.cg.shared.global [%0], [%1], 16;"
                :: "r"(sQ + (uint32_t)(row * 272 + seg * 16)), "l"(gp) : "memory");
        }
        const __half* ksrc = QKVh + (size_t)(b * S_LEN) * QKVN + DIM + g * HD;
        fla_load_kv(ksrc, sK, tid);
        fla_load_kv(ksrc + KVD, sV, tid);
        asm volatile("cp.async.commit_group;" ::: "memory");
    }

    const uint32_t a_base = sQ + (uint32_t)((wid * 16 + (lane & 15)) * 272 + (lane >> 4) * 16);
    const uint32_t kb_off = (uint32_t)(((lane & 7) + ((lane >> 4) & 1) * 8) * 272 + ((lane >> 3) & 1) * 16);
    const uint32_t vb_off = (uint32_t)(((lane & 7) + ((lane >> 3) & 1) * 8) * 272 + ((lane >> 4) & 1) * 16);

    float o[16][4];
#pragma unroll
    for (int j = 0; j < 16; j++)
#pragma unroll
        for (int v = 0; v < 4; v++) o[j][v] = 0.0f;
    float m0 = -INFINITY, m1 = -INFINITY, l0 = 0.0f, l1 = 0.0f;

    asm volatile("cp.async.wait_group 0;" ::: "memory");
    __syncthreads();

    uint32_t qa[8][4];
#pragma unroll
    for (int ks = 0; ks < 8; ks++) ldsm_x4(qa[ks], a_base + (uint32_t)ks * 32u);

    const float scale = 0.08838834764831845f;  // 1/sqrt(128)
    const int rb0 = wid * 16 + (lane >> 2);
    const int rb1 = rb0 + 8;
    const int cb  = (lane & 3) * 2;
    const int qrow0 = qt * 128 + rb0;
    const int qrow1 = qrow0 + 8;
    const int warp_row_max = qt * 128 + wid * 16 + 15;

    const int njt = 2 * qt + 2;
    for (int jt = 0; jt < njt; jt++) {
        const uint32_t buf = (uint32_t)(jt & 1) * FLA_KV_B;
        if (jt > 0) {
            asm volatile("cp.async.wait_group 0;" ::: "memory");
            __syncthreads();
        }
        if (jt + 1 < njt) {
            const __half* ksrc = QKVh + (size_t)(b * S_LEN + (jt + 1) * 64) * QKVN + DIM + g * HD;
            const uint32_t nbuf = (uint32_t)((jt + 1) & 1) * FLA_KV_B;
            fla_load_kv(ksrc, sK + nbuf, tid);
            fla_load_kv(ksrc + KVD, sV + nbuf, tid);
            asm volatile("cp.async.commit_group;" ::: "memory");
        }

        if (jt * 64 > warp_row_max) continue;

        // ---- S = Q K^T ----
        float s[8][4];
#pragma unroll
        for (int j = 0; j < 8; j++)
#pragma unroll
            for (int v = 0; v < 4; v++) s[j][v] = 0.0f;

#pragma unroll
        for (int ks = 0; ks < 8; ks++) {
            const uint32_t bb = sK + buf + kb_off + (uint32_t)ks * 32u;
#pragma unroll
            for (int nb = 0; nb < 4; nb++) {
                uint32_t bf[4];
                ldsm_x4(bf, bb + (uint32_t)nb * (16u * 272u));
                mma16816(s[nb * 2 + 0], qa[ks], &bf[0]);
                mma16816(s[nb * 2 + 1], qa[ks], &bf[2]);
            }
        }

#pragma unroll
        for (int j = 0; j < 8; j++) {
            s[j][0] *= scale; s[j][1] *= scale; s[j][2] *= scale; s[j][3] *= scale;
        }
        if (jt >= 2 * qt) {
#pragma unroll
            for (int j = 0; j < 8; j++) {
                const int c0 = jt * 64 + j * 8 + cb;
                if (c0 > qrow0)     s[j][0] = -1e30f;
                if (c0 + 1 > qrow0) s[j][1] = -1e30f;
                if (c0 > qrow1)     s[j][2] = -1e30f;
                if (c0 + 1 > qrow1) s[j][3] = -1e30f;
            }
        }

        // ---- online softmax ----
        float mx0 = -INFINITY, mx1 = -INFINITY;
#pragma unroll
        for (int j = 0; j < 8; j++) {
            mx0 = fmaxf(mx0, fmaxf(s[j][0], s[j][1]));
            mx1 = fmaxf(mx1, fmaxf(s[j][2], s[j][3]));
        }
        mx0 = fmaxf(mx0, __shfl_xor_sync(0xffffffffu, mx0, 1));
        mx0 = fmaxf(mx0, __shfl_xor_sync(0xffffffffu, mx0, 2));
        mx1 = fmaxf(mx1, __shfl_xor_sync(0xffffffffu, mx1, 1));
        mx1 = fmaxf(mx1, __shfl_xor_sync(0xffffffffu, mx1, 2));
        const float mn0 = fmaxf(m0, mx0);
        const float mn1 = fmaxf(m1, mx1);
        const float al0 = __expf(m0 - mn0);
        const float al1 = __expf(m1 - mn1);
        m0 = mn0; m1 = mn1;

        float sum0 = 0.0f, sum1 = 0.0f;
#pragma unroll
        for (int j = 0; j < 8; j++) {
            s[j][0] = __expf(s[j][0] - mn0);
            s[j][1] = __expf(s[j][1] - mn0);
            s[j][2] = __expf(s[j][2] - mn1);
            s[j][3] = __expf(s[j][3] - mn1);
            sum0 += s[j][0] + s[j][1];
            sum1 += s[j][2] + s[j][3];
        }
        sum0 += __shfl_xor_sync(0xffffffffu, sum0, 1);
        sum0 += __shfl_xor_sync(0xffffffffu, sum0, 2);
        sum1 += __shfl_xor_sync(0xffffffffu, sum1, 1);
        sum1 += __shfl_xor_sync(0xffffffffu, sum1, 2);
        l0 = l0 * al0 + sum0;
        l1 = l1 * al1 + sum1;

#pragma unroll
        for (int j = 0; j < 16; j++) {
            o[j][0] *= al0; o[j][1] *= al0; o[j][2] *= al1; o[j][3] *= al1;
        }

        // ---- O += P V ----
#pragma unroll
        for (int ksp = 0; ksp < 4; ksp++) {
            uint32_t pa[4];
            pa[0] = packh2(s[2 * ksp][0],     s[2 * ksp][1]);
            pa[1] = packh2(s[2 * ksp][2],     s[2 * ksp][3]);
            pa[2] = packh2(s[2 * ksp + 1][0], s[2 * ksp + 1][1]);
            pa[3] = packh2(s[2 * ksp + 1][2], s[2 * ksp + 1][3]);
            const uint32_t vb = sV + buf + vb_off + (uint32_t)ksp * (16u * 272u);
#pragma unroll
            for (int nb = 0; nb < 8; nb++) {
                uint32_t bf[4];
                ldsm_x4_trans(bf, vb + (uint32_t)nb * 32u);
                mma16816(o[nb * 2 + 0], pa, &bf[0]);
                mma16816(o[nb * 2 + 1], pa, &bf[2]);
            }
        }
    }

    const float inv0 = 1.0f / l0;
    const float inv1 = 1.0f / l1;
    const size_t row0 = (size_t)(b * S_LEN + qt * 128 + rb0);
    const size_t row1 = row0 + 8;
#pragma unroll
    for (int j = 0; j < 16; j++) {
        const int col = h * HD + j * 8 + cb;
        uint32_t p0 = packh2(o[j][0] * inv0, o[j][1] * inv0);
        uint32_t p1 = packh2(o[j][2] * inv1, o[j][3] * inv1);
        *(uint32_t*)&Oh[row0 * DIM + col] = p0;
        *(uint32_t*)&Oh[row1 * DIM + col] = p1;
    }
}

// =====================================================================
// launch
// =====================================================================
extern "C" void kernel_launch(void* const* d_in, const int* in_sizes, int n_in,
                              void* d_out, int out_size) {
    (void)in_sizes; (void)n_in; (void)out_size;
    const float* x    = (const float*)d_in[0];
    const float* cosT = (const float*)d_in[1];
    const float* sinT = (const float*)d_in[2];
    const float* wq   = (const float*)d_in[3];
    const float* wk   = (const float*)d_in[4];
    const float* wv   = (const float*)d_in[5];
    const float* wo   = (const float*)d_in[6];
    float* out = (float*)d_out;

    __half *pqkvh, *xh, *oh, *wf, *wo2;
    cudaGetSymbolAddress((void**)&pqkvh, g_qkvh);
    cudaGetSymbolAddress((void**)&xh, g_xh);
    cudaGetSymbolAddress((void**)&oh, g_oh);
    cudaGetSymbolAddress((void**)&wf, g_wf);
    cudaGetSymbolAddress((void**)&wo2, g_wo2);

    cudaFuncSetAttribute(flash_mma, cudaFuncAttributeMaxDynamicSharedMemorySize, FLASH_SMEM_BYTES);
    cudaFuncSetAttribute(gemm_f16<true>,  cudaFuncAttributeMaxDynamicSharedMemorySize, GEMM_SMEM_BYTES);
    cudaFuncSetAttribute(gemm_f16<false>, cudaFuncAttributeMaxDynamicSharedMemorySize, GEMM_SMEM_BYTES);

    // one fused convert launch
    convert_all<<<(CVT_TOTAL4 + 255) / 256, 256>>>(wq, wk, wv, wo, x, wf, wo2, xh);

    // fused QKV projection with RoPE epilogue, fp16 out
    gemm_f16<true><<<dim3(QKVN / 128, MTOT / 128), 128, GEMM_SMEM_BYTES>>>(
        xh, wf, pqkvh, QKVN, DIM, cosT, sinT);

    // tensor-core flash attention (writes fp16 O directly)
    flash_mma<<<dim3(S_LEN / 128, NH, B_SZ), 256, FLASH_SMEM_BYTES>>>(pqkvh, oh);

    // output projection (fp32 out)
    gemm_f16<false><<<dim3(DIM / 128, MTOT / 128), 128, GEMM_SMEM_BYTES>>>(
        oh, wo2, out, DIM, DIM, nullptr, nullptr);
}